// round 1
// baseline (speedup 1.0000x reference)
#include <cuda_runtime.h>
#include <math.h>

#define BB 64
#define NN 4096
#define DD 256
#define KS 11
#define HH 512
#define NITER 5
#define EPSF 1e-8f
#define LNEPS 1e-5f
#define SCALEF 0.0625f
#define SPLIT 16
#define CH (NN/SPLIT)

// ---------------- scratch (device globals; no allocation allowed) ----------------
__device__ float g_mean[BB*NN];
__device__ float g_rstd[BB*NN];
__device__ float g_weff[DD*DD];
__device__ float g_gv[DD];
__device__ float g_sln[BB*KS*DD];
__device__ float g_cb[BB*KS];
__device__ float g_qe[BB*KS*DD];
__device__ float g_uh[BB*KS*DD];
__device__ float g_rs[BB*KS];
__device__ float g_updpre[BB*KS*DD];
__device__ float g_upd[BB*KS*DD];
__device__ float g_gi[BB*KS*3*DD];
__device__ float g_gh[BB*KS*3*DD];
__device__ float g_p[BB*KS*DD];
__device__ float g_h1[BB*KS*HH];

// ---------------- per-row mean/rstd of inputs (once) ----------------
__global__ void k_stats(const float* __restrict__ X, float* __restrict__ mean,
                        float* __restrict__ rstd) {
    int row = blockIdx.x * 8 + (threadIdx.x >> 5);
    int lane = threadIdx.x & 31;
    const float* p = X + (size_t)row * DD;
    float s = 0.f, s2 = 0.f;
#pragma unroll
    for (int c = 0; c < 8; c++) {
        float v = p[lane + 32 * c];
        s += v; s2 += v * v;
    }
#pragma unroll
    for (int o = 16; o; o >>= 1) {
        s  += __shfl_xor_sync(0xffffffffu, s,  o);
        s2 += __shfl_xor_sync(0xffffffffu, s2, o);
    }
    if (lane == 0) {
        float m = s * (1.0f / DD);
        float var = s2 * (1.0f / DD) - m * m;
        mean[row] = m;
        rstd[row] = rsqrtf(var + LNEPS);
    }
}

// ---------------- Weff[e'][t] = ln_f_w[e'] * sum_s Wk[s,e'] * Wq[s,t] (once) ----------------
__global__ void k_weff(const float* __restrict__ Wk, const float* __restrict__ Wq,
                       const float* __restrict__ wf, float* __restrict__ weff) {
    __shared__ float col[DD];
    int d = blockIdx.x;   // e' (output row)
    int e = threadIdx.x;  // t (output col); also reused as s for the load
    col[e] = Wk[e * DD + d];
    __syncthreads();
    float acc = 0.f;
    for (int t = 0; t < DD; t++) acc = fmaf(col[t], Wq[t * DD + e], acc);
    weff[d * DD + e] = acc * wf[d];
}

// ---------------- g[e] = sum_t Wq[t,e] * (sum_d Wk[t,d]*ln_f_b[d]) (once) ----------------
__global__ void k_prep(const float* __restrict__ Wk, const float* __restrict__ Wq,
                       const float* __restrict__ bf, float* __restrict__ g) {
    __shared__ float wkb[DD];
    int t = threadIdx.x;
    float a = 0.f;
    for (int d = 0; d < DD; d++) a = fmaf(Wk[t * DD + d], bf[d], a);
    wkb[t] = a;
    __syncthreads();
    float acc = 0.f;
    for (int tt = 0; tt < DD; tt++) acc = fmaf(Wq[tt * DD + t], wkb[tt], acc);
    g[t] = acc;
}

// ---------------- LayerNorm on 704x256 rows; optional cb[row] = out . gvec ----------------
__global__ void k_ln_small(const float* __restrict__ in, const float* __restrict__ w,
                           const float* __restrict__ b, float* __restrict__ out,
                           const float* __restrict__ gvec, float* __restrict__ cb) {
    int row = blockIdx.x, tid = threadIdx.x, lane = tid & 31, warp = tid >> 5;
    float v = in[(size_t)row * DD + tid];
    float s = v, s2 = v * v;
#pragma unroll
    for (int o = 16; o; o >>= 1) {
        s  += __shfl_xor_sync(0xffffffffu, s,  o);
        s2 += __shfl_xor_sync(0xffffffffu, s2, o);
    }
    __shared__ float sa[8], sb[8], sc[8];
    if (lane == 0) { sa[warp] = s; sb[warp] = s2; }
    __syncthreads();
    float ts = 0.f, ts2 = 0.f;
#pragma unroll
    for (int i = 0; i < 8; i++) { ts += sa[i]; ts2 += sb[i]; }
    float m = ts * (1.0f / DD);
    float var = ts2 * (1.0f / DD) - m * m;
    float r = rsqrtf(var + LNEPS);
    float o_ = (v - m) * r * w[tid] + b[tid];
    out[(size_t)row * DD + tid] = o_;
    if (gvec) {
        float c = o_ * gvec[tid];
#pragma unroll
        for (int o2 = 16; o2; o2 >>= 1) c += __shfl_xor_sync(0xffffffffu, c, o2);
        if (lane == 0) sc[warp] = c;
        __syncthreads();
        if (tid == 0) {
            float t = 0.f;
#pragma unroll
            for (int i = 0; i < 8; i++) t += sc[i];
            cb[row] = t;
        }
    }
}

// ---------------- zero accumulators ----------------
__global__ void k_zero(float* __restrict__ uh, float* __restrict__ rs) {
    int i = blockIdx.x * 256 + threadIdx.x;
    if (i < BB * KS * DD) uh[i] = 0.f;
    if (i < BB * KS) rs[i] = 0.f;
}

// ---------------- fused attention: dots + softmax(+eps) + accumulate u_raw, rowsum ----------------
__global__ void __launch_bounds__(256, 1) k_attn(
    const float* __restrict__ X, const float* __restrict__ mean,
    const float* __restrict__ rstd, const float* __restrict__ qe,
    const float* __restrict__ cb, float* __restrict__ uh, float* __restrict__ rs) {
    int b = blockIdx.x, sp = blockIdx.y;
    int tid = threadIdx.x, lane = tid & 31, warp = tid >> 5;

    __shared__ float qs[KS * DD];
    __shared__ float uhs[KS * DD];
    __shared__ float cbs[KS];
    __shared__ float rss[KS];

    for (int i = tid; i < KS * DD; i += 256) {
        qs[i] = qe[(size_t)b * KS * DD + i];
        uhs[i] = 0.f;
    }
    if (tid < KS) { cbs[tid] = cb[b * KS + tid]; rss[tid] = 0.f; }
    __syncthreads();

    const int nw = CH / 8;               // n-values per warp
    int nbase = sp * CH + warp * nw;
    const float* Xb = X + (size_t)b * NN * DD;
    const float* mb = mean + (size_t)b * NN;
    const float* rb = rstd + (size_t)b * NN;

    float acc[KS][8];
    float rsl[KS];
#pragma unroll
    for (int i = 0; i < KS; i++) {
        rsl[i] = 0.f;
#pragma unroll
        for (int c = 0; c < 8; c++) acc[i][c] = 0.f;
    }

    float x[8], mc, rc;
    {
        const float* p = Xb + (size_t)nbase * DD;
#pragma unroll
        for (int c = 0; c < 8; c++) x[c] = p[lane + 32 * c];
        mc = mb[nbase]; rc = rb[nbase];
    }

    for (int t = 0; t < nw; t++) {
        // prefetch next row (clamped on last iter)
        int n2 = nbase + ((t + 1 < nw) ? (t + 1) : t);
        const float* p2 = Xb + (size_t)n2 * DD;
        float xn[8];
#pragma unroll
        for (int c = 0; c < 8; c++) xn[c] = p2[lane + 32 * c];
        float mn2 = mb[n2], rn2 = rb[n2];

        // normalize current row (LN affine folded into qs / cb / finalize)
        float xh[8];
#pragma unroll
        for (int c = 0; c < 8; c++) xh[c] = (x[c] - mc) * rc;

        // dots: per-lane partials over the lane's d-slice
        float dt[KS];
#pragma unroll
        for (int i = 0; i < KS; i++) {
            float s = 0.f;
#pragma unroll
            for (int c = 0; c < 8; c++) s = fmaf(xh[c], qs[i * DD + lane + 32 * c], s);
            dt[i] = s;
        }
        // warp all-reduce (all lanes need all 11 logits)
#pragma unroll
        for (int i = 0; i < KS; i++) {
#pragma unroll
            for (int o = 16; o; o >>= 1) dt[i] += __shfl_xor_sync(0xffffffffu, dt[i], o);
        }
        // softmax over slots
        float mx = -1e30f;
#pragma unroll
        for (int i = 0; i < KS; i++) {
            dt[i] = (dt[i] + cbs[i]) * SCALEF;
            mx = fmaxf(mx, dt[i]);
        }
        float se = 0.f;
#pragma unroll
        for (int i = 0; i < KS; i++) {
            float e = __expf(dt[i] - mx);
            dt[i] = e; se += e;
        }
        float inv = __fdividef(1.0f, se);
#pragma unroll
        for (int i = 0; i < KS; i++) {
            float a = fmaf(dt[i], inv, EPSF);   // softmax + EPS
            rsl[i] += a;
#pragma unroll
            for (int c = 0; c < 8; c++) acc[i][c] = fmaf(a, xh[c], acc[i][c]);
        }
#pragma unroll
        for (int c = 0; c < 8; c++) x[c] = xn[c];
        mc = mn2; rc = rn2;
    }

    // reduce into shared, then global
#pragma unroll
    for (int i = 0; i < KS; i++) {
#pragma unroll
        for (int c = 0; c < 8; c++) atomicAdd(&uhs[i * DD + lane + 32 * c], acc[i][c]);
    }
    if (lane == 0) {
#pragma unroll
        for (int i = 0; i < KS; i++) atomicAdd(&rss[i], rsl[i]);
    }
    __syncthreads();
    for (int i = tid; i < KS * DD; i += 256) atomicAdd(&uh[(size_t)b * KS * DD + i], uhs[i]);
    if (tid < KS) atomicAdd(&rs[b * KS + tid], rss[tid]);
}

// ---------------- finalize: updates_pre = ln_f_w[d]*uh/rs + ln_f_b[d] ----------------
__global__ void k_fin(const float* __restrict__ uh, const float* __restrict__ rs,
                      const float* __restrict__ wf, const float* __restrict__ bf,
                      float* __restrict__ out) {
    int i = blockIdx.x * 256 + threadIdx.x;
    if (i >= BB * KS * DD) return;
    int m = i >> 8, d = i & 255;
    float r = rs[m];
    out[i] = __fdividef(wf[d] * uh[i], r) + bf[d];
}

// ---------------- GRU gate elementwise ----------------
__global__ void k_gru(const float* __restrict__ gi, const float* __restrict__ gh,
                      float* __restrict__ slots) {
    int i = blockIdx.x * 256 + threadIdx.x;
    if (i >= BB * KS * DD) return;
    int m = i >> 8, d = i & 255;
    const float* gim = gi + (size_t)m * 3 * DD;
    const float* ghm = gh + (size_t)m * 3 * DD;
    float ir = gim[d], iz = gim[DD + d], inn = gim[2 * DD + d];
    float hr = ghm[d], hz = ghm[DD + d], hn = ghm[2 * DD + d];
    float r = 1.0f / (1.0f + __expf(-(ir + hr)));
    float z = 1.0f / (1.0f + __expf(-(iz + hz)));
    float nn = tanhf(inn + r * hn);
    slots[i] = (1.0f - z) * nn + z * slots[i];
}

// ---------------- generic SGEMM: C[m,n] = sum_k A[m,k]*W[n,k] (+bias, relu, +=C) ----------------
// M,N multiples of 64; K multiple of 16. 64x64 tile, 256 threads, 4x4 microtile.
__global__ void k_gemm(const float* __restrict__ A, const float* __restrict__ W,
                       const float* __restrict__ bias, float* __restrict__ C,
                       int M, int N, int K, int relu, int accflag) {
    __shared__ __align__(16) float As[16][68];
    __shared__ __align__(16) float Ws[16][68];
    int tid = threadIdx.x;
    int m0 = blockIdx.y * 64, n0 = blockIdx.x * 64;
    int tx = tid & 15, ty = tid >> 4;
    float acc[4][4];
#pragma unroll
    for (int i = 0; i < 4; i++)
#pragma unroll
        for (int j = 0; j < 4; j++) acc[i][j] = 0.f;

    for (int k0 = 0; k0 < K; k0 += 16) {
#pragma unroll
        for (int l = 0; l < 4; l++) {
            int idx = tid + l * 256;
            int r = idx >> 4, c = idx & 15;
            As[c][r] = A[(size_t)(m0 + r) * K + k0 + c];
            Ws[c][r] = W[(size_t)(n0 + r) * K + k0 + c];
        }
        __syncthreads();
#pragma unroll
        for (int kk = 0; kk < 16; kk++) {
            float4 a4 = *(const float4*)&As[kk][ty * 4];
            float4 b4 = *(const float4*)&Ws[kk][tx * 4];
            float av[4] = {a4.x, a4.y, a4.z, a4.w};
            float bv[4] = {b4.x, b4.y, b4.z, b4.w};
#pragma unroll
            for (int i = 0; i < 4; i++)
#pragma unroll
                for (int j = 0; j < 4; j++) acc[i][j] = fmaf(av[i], bv[j], acc[i][j]);
        }
        __syncthreads();
    }
#pragma unroll
    for (int i = 0; i < 4; i++) {
#pragma unroll
        for (int j = 0; j < 4; j++) {
            int m = m0 + ty * 4 + i, n = n0 + tx * 4 + j;
            float v = acc[i][j];
            if (bias) v += bias[n];
            if (relu) v = fmaxf(v, 0.f);
            size_t o = (size_t)m * N + n;
            if (accflag) v += C[o];
            C[o] = v;
        }
    }
}

static void gemm(const float* A, const float* W, const float* bias, float* C,
                 int M, int N, int K, int relu, int accflag) {
    dim3 g(N / 64, M / 64);
    k_gemm<<<g, 256>>>(A, W, bias, C, M, N, K, relu, accflag);
}

extern "C" void kernel_launch(void* const* d_in, const int* in_sizes, int n_in,
                              void* d_out, int out_size) {
    const float* inputs     = (const float*)d_in[0];
    const float* slots_init = (const float*)d_in[1];
    const float* ln_f_w = (const float*)d_in[2];
    const float* ln_f_b = (const float*)d_in[3];
    const float* ln_s_w = (const float*)d_in[4];
    const float* ln_s_b = (const float*)d_in[5];
    const float* ln_p_w = (const float*)d_in[6];
    const float* ln_p_b = (const float*)d_in[7];
    const float* Wq  = (const float*)d_in[8];
    const float* Wk  = (const float*)d_in[9];
    const float* Wv  = (const float*)d_in[10];
    const float* W_ih = (const float*)d_in[11];
    const float* b_ih = (const float*)d_in[12];
    const float* W_hh = (const float*)d_in[13];
    const float* b_hh = (const float*)d_in[14];
    const float* W1 = (const float*)d_in[15];
    const float* b1 = (const float*)d_in[16];
    const float* W2 = (const float*)d_in[17];
    const float* b2 = (const float*)d_in[18];
    float* slots = (float*)d_out;

    float *p_mean, *p_rstd, *p_weff, *p_gv, *p_sln, *p_cb, *p_qe, *p_uh, *p_rs;
    float *p_updpre, *p_upd, *p_gi, *p_gh, *p_p, *p_h1;
    cudaGetSymbolAddress((void**)&p_mean, g_mean);
    cudaGetSymbolAddress((void**)&p_rstd, g_rstd);
    cudaGetSymbolAddress((void**)&p_weff, g_weff);
    cudaGetSymbolAddress((void**)&p_gv, g_gv);
    cudaGetSymbolAddress((void**)&p_sln, g_sln);
    cudaGetSymbolAddress((void**)&p_cb, g_cb);
    cudaGetSymbolAddress((void**)&p_qe, g_qe);
    cudaGetSymbolAddress((void**)&p_uh, g_uh);
    cudaGetSymbolAddress((void**)&p_rs, g_rs);
    cudaGetSymbolAddress((void**)&p_updpre, g_updpre);
    cudaGetSymbolAddress((void**)&p_upd, g_upd);
    cudaGetSymbolAddress((void**)&p_gi, g_gi);
    cudaGetSymbolAddress((void**)&p_gh, g_gh);
    cudaGetSymbolAddress((void**)&p_p, g_p);
    cudaGetSymbolAddress((void**)&p_h1, g_h1);

    // slots = slots_init
    cudaMemcpyAsync(slots, slots_init, (size_t)BB * KS * DD * sizeof(float),
                    cudaMemcpyDeviceToDevice);

    // once: input-row LN stats; effective query weight; bias fold vector
    k_stats<<<BB * NN / 8, 256>>>(inputs, p_mean, p_rstd);
    k_weff<<<DD, DD>>>(Wk, Wq, ln_f_w, p_weff);
    k_prep<<<1, DD>>>(Wk, Wq, ln_f_b, p_gv);

    for (int it = 0; it < NITER; it++) {
        // q-side: sln = LN_s(slots), cb = sln . g
        k_ln_small<<<BB * KS, DD>>>(slots, ln_s_w, ln_s_b, p_sln, p_gv, p_cb);
        // qe = sln @ Weff^T  (704x256, K=256)
        gemm(p_sln, p_weff, nullptr, p_qe, BB * KS, DD, DD, 0, 0);
        // zero accumulators
        k_zero<<<704, 256>>>(p_uh, p_rs);
        // fused attention pass over inputs
        k_attn<<<dim3(BB, SPLIT), 256>>>(inputs, p_mean, p_rstd, p_qe, p_cb, p_uh, p_rs);
        // finalize normalization + LN affine fold
        k_fin<<<704, 256>>>(p_uh, p_rs, ln_f_w, ln_f_b, p_updpre);
        // updates = updates_pre @ Wv^T
        gemm(p_updpre, Wv, nullptr, p_upd, BB * KS, DD, DD, 0, 0);
        // GRU gates
        gemm(p_upd, W_ih, b_ih, p_gi, BB * KS, 3 * DD, DD, 0, 0);
        gemm(slots, W_hh, b_hh, p_gh, BB * KS, 3 * DD, DD, 0, 0);
        k_gru<<<704, 256>>>(p_gi, p_gh, slots);
        // residual MLP
        k_ln_small<<<BB * KS, DD>>>(slots, ln_p_w, ln_p_b, p_p, nullptr, nullptr);
        gemm(p_p, W1, b1, p_h1, BB * KS, HH, DD, 1, 0);
        gemm(p_h1, W2, b2, slots, BB * KS, DD, HH, 0, 1);
    }
}

// round 2
// speedup vs baseline: 1.0055x; 1.0055x over previous
#include <cuda_runtime.h>
#include <math.h>

#define BB 64
#define NN 4096
#define DD 256
#define KS 11
#define HH 512
#define NITER 5
#define EPSF 1e-8f
#define LNEPS 1e-5f
#define SCALEF 0.0625f
#define SPLIT 16
#define CH (NN/SPLIT)

// ---------------- scratch (device globals; no allocation allowed) ----------------
__device__ float g_mean[BB*NN];
__device__ float g_rstd[BB*NN];
__device__ float g_weff[DD*DD];
__device__ float g_gv[DD];
__device__ float g_sln[BB*KS*DD];
__device__ float g_cb[BB*KS];
__device__ float g_qe[BB*KS*DD];
__device__ float g_uh[BB*KS*DD];
__device__ float g_rs[BB*KS];
__device__ float g_updpre[BB*KS*DD];
__device__ float g_upd[BB*KS*DD];
__device__ float g_gi[BB*KS*3*DD];
__device__ float g_gh[BB*KS*3*DD];
__device__ float g_p[BB*KS*DD];
__device__ float g_h1[BB*KS*HH];

// ---------------- per-row mean/rstd of inputs (once) ----------------
__global__ void k_stats(const float* __restrict__ X, float* __restrict__ mean,
                        float* __restrict__ rstd) {
    int row = blockIdx.x * 8 + (threadIdx.x >> 5);
    int lane = threadIdx.x & 31;
    const float* p = X + (size_t)row * DD;
    float s = 0.f, s2 = 0.f;
#pragma unroll
    for (int c = 0; c < 8; c++) {
        float v = p[lane + 32 * c];
        s += v; s2 += v * v;
    }
#pragma unroll
    for (int o = 16; o; o >>= 1) {
        s  += __shfl_xor_sync(0xffffffffu, s,  o);
        s2 += __shfl_xor_sync(0xffffffffu, s2, o);
    }
    if (lane == 0) {
        float m = s * (1.0f / DD);
        float var = s2 * (1.0f / DD) - m * m;
        mean[row] = m;
        rstd[row] = rsqrtf(var + LNEPS);
    }
}

// ---------------- Weff[e'][t] = ln_f_w[e'] * sum_s Wk[s,e'] * Wq[s,t] (once) ----------------
__global__ void k_weff(const float* __restrict__ Wk, const float* __restrict__ Wq,
                       const float* __restrict__ wf, float* __restrict__ weff) {
    __shared__ float col[DD];
    int d = blockIdx.x;   // e' (output row)
    int e = threadIdx.x;  // t (output col); also reused as s for the load
    col[e] = Wk[e * DD + d];
    __syncthreads();
    float acc = 0.f;
    for (int t = 0; t < DD; t++) acc = fmaf(col[t], Wq[t * DD + e], acc);
    weff[d * DD + e] = acc * wf[d];
}

// ---------------- g[e] = sum_t Wq[t,e] * (sum_d Wk[t,d]*ln_f_b[d]) (once) ----------------
__global__ void k_prep(const float* __restrict__ Wk, const float* __restrict__ Wq,
                       const float* __restrict__ bf, float* __restrict__ g) {
    __shared__ float wkb[DD];
    int t = threadIdx.x;
    float a = 0.f;
    for (int d = 0; d < DD; d++) a = fmaf(Wk[t * DD + d], bf[d], a);
    wkb[t] = a;
    __syncthreads();
    float acc = 0.f;
    for (int tt = 0; tt < DD; tt++) acc = fmaf(Wq[tt * DD + t], wkb[tt], acc);
    g[t] = acc;
}

// ---------------- LayerNorm on 704x256 rows; optional cb[row] = out . gvec ----------------
__global__ void k_ln_small(const float* __restrict__ in, const float* __restrict__ w,
                           const float* __restrict__ b, float* __restrict__ out,
                           const float* __restrict__ gvec, float* __restrict__ cb) {
    int row = blockIdx.x, tid = threadIdx.x, lane = tid & 31, warp = tid >> 5;
    float v = in[(size_t)row * DD + tid];
    float s = v, s2 = v * v;
#pragma unroll
    for (int o = 16; o; o >>= 1) {
        s  += __shfl_xor_sync(0xffffffffu, s,  o);
        s2 += __shfl_xor_sync(0xffffffffu, s2, o);
    }
    __shared__ float sa[8], sb[8], sc[8];
    if (lane == 0) { sa[warp] = s; sb[warp] = s2; }
    __syncthreads();
    float ts = 0.f, ts2 = 0.f;
#pragma unroll
    for (int i = 0; i < 8; i++) { ts += sa[i]; ts2 += sb[i]; }
    float m = ts * (1.0f / DD);
    float var = ts2 * (1.0f / DD) - m * m;
    float r = rsqrtf(var + LNEPS);
    float o_ = (v - m) * r * w[tid] + b[tid];
    out[(size_t)row * DD + tid] = o_;
    if (gvec) {
        float c = o_ * gvec[tid];
#pragma unroll
        for (int o2 = 16; o2; o2 >>= 1) c += __shfl_xor_sync(0xffffffffu, c, o2);
        if (lane == 0) sc[warp] = c;
        __syncthreads();
        if (tid == 0) {
            float t = 0.f;
#pragma unroll
            for (int i = 0; i < 8; i++) t += sc[i];
            cb[row] = t;
        }
    }
}

// ---------------- zero accumulators ----------------
__global__ void k_zero(float* __restrict__ uh, float* __restrict__ rs) {
    int i = blockIdx.x * 256 + threadIdx.x;
    if (i < BB * KS * DD) uh[i] = 0.f;
    if (i < BB * KS) rs[i] = 0.f;
}

// ---------------- fused attention: dots + softmax(+eps) + accumulate u_raw, rowsum ----------------
__global__ void __launch_bounds__(256, 1) k_attn(
    const float* __restrict__ X, const float* __restrict__ mean,
    const float* __restrict__ rstd, const float* __restrict__ qe,
    const float* __restrict__ cb, float* __restrict__ uh, float* __restrict__ rs) {
    int b = blockIdx.x, sp = blockIdx.y;
    int tid = threadIdx.x, lane = tid & 31, warp = tid >> 5;

    __shared__ float qs[KS * DD];
    __shared__ float uhs[KS * DD];
    __shared__ float cbs[KS];
    __shared__ float rss[KS];

    for (int i = tid; i < KS * DD; i += 256) {
        qs[i] = qe[(size_t)b * KS * DD + i];
        uhs[i] = 0.f;
    }
    if (tid < KS) { cbs[tid] = cb[b * KS + tid]; rss[tid] = 0.f; }
    __syncthreads();

    const int nw = CH / 8;               // n-values per warp
    int nbase = sp * CH + warp * nw;
    const float* Xb = X + (size_t)b * NN * DD;
    const float* mb = mean + (size_t)b * NN;
    const float* rb = rstd + (size_t)b * NN;

    float acc[KS][8];
    float rsl[KS];
#pragma unroll
    for (int i = 0; i < KS; i++) {
        rsl[i] = 0.f;
#pragma unroll
        for (int c = 0; c < 8; c++) acc[i][c] = 0.f;
    }

    float x[8], mc, rc;
    {
        const float* p = Xb + (size_t)nbase * DD;
#pragma unroll
        for (int c = 0; c < 8; c++) x[c] = p[lane + 32 * c];
        mc = mb[nbase]; rc = rb[nbase];
    }

    for (int t = 0; t < nw; t++) {
        // prefetch next row (clamped on last iter)
        int n2 = nbase + ((t + 1 < nw) ? (t + 1) : t);
        const float* p2 = Xb + (size_t)n2 * DD;
        float xn[8];
#pragma unroll
        for (int c = 0; c < 8; c++) xn[c] = p2[lane + 32 * c];
        float mn2 = mb[n2], rn2 = rb[n2];

        // normalize current row (LN affine folded into qs / cb / finalize)
        float xh[8];
#pragma unroll
        for (int c = 0; c < 8; c++) xh[c] = (x[c] - mc) * rc;

        // dots: per-lane partials over the lane's d-slice
        float dt[KS];
#pragma unroll
        for (int i = 0; i < KS; i++) {
            float s = 0.f;
#pragma unroll
            for (int c = 0; c < 8; c++) s = fmaf(xh[c], qs[i * DD + lane + 32 * c], s);
            dt[i] = s;
        }
        // warp all-reduce (all lanes need all 11 logits)
#pragma unroll
        for (int i = 0; i < KS; i++) {
#pragma unroll
            for (int o = 16; o; o >>= 1) dt[i] += __shfl_xor_sync(0xffffffffu, dt[i], o);
        }
        // softmax over slots
        float mx = -1e30f;
#pragma unroll
        for (int i = 0; i < KS; i++) {
            dt[i] = (dt[i] + cbs[i]) * SCALEF;
            mx = fmaxf(mx, dt[i]);
        }
        float se = 0.f;
#pragma unroll
        for (int i = 0; i < KS; i++) {
            float e = __expf(dt[i] - mx);
            dt[i] = e; se += e;
        }
        float inv = __fdividef(1.0f, se);
#pragma unroll
        for (int i = 0; i < KS; i++) {
            float a = fmaf(dt[i], inv, EPSF);   // softmax + EPS
            rsl[i] += a;
#pragma unroll
            for (int c = 0; c < 8; c++) acc[i][c] = fmaf(a, xh[c], acc[i][c]);
        }
#pragma unroll
        for (int c = 0; c < 8; c++) x[c] = xn[c];
        mc = mn2; rc = rn2;
    }

    // reduce into shared, then global
#pragma unroll
    for (int i = 0; i < KS; i++) {
#pragma unroll
        for (int c = 0; c < 8; c++) atomicAdd(&uhs[i * DD + lane + 32 * c], acc[i][c]);
    }
    if (lane == 0) {
#pragma unroll
        for (int i = 0; i < KS; i++) atomicAdd(&rss[i], rsl[i]);
    }
    __syncthreads();
    for (int i = tid; i < KS * DD; i += 256) atomicAdd(&uh[(size_t)b * KS * DD + i], uhs[i]);
    if (tid < KS) atomicAdd(&rs[b * KS + tid], rss[tid]);
}

// ---------------- finalize: updates_pre = ln_f_w[d]*uh/rs + ln_f_b[d] ----------------
__global__ void k_fin(const float* __restrict__ uh, const float* __restrict__ rs,
                      const float* __restrict__ wf, const float* __restrict__ bf,
                      float* __restrict__ out) {
    int i = blockIdx.x * 256 + threadIdx.x;
    if (i >= BB * KS * DD) return;
    int m = i >> 8, d = i & 255;
    float r = rs[m];
    out[i] = __fdividef(wf[d] * uh[i], r) + bf[d];
}

// ---------------- GRU gate elementwise ----------------
__global__ void k_gru(const float* __restrict__ gi, const float* __restrict__ gh,
                      float* __restrict__ slots) {
    int i = blockIdx.x * 256 + threadIdx.x;
    if (i >= BB * KS * DD) return;
    int m = i >> 8, d = i & 255;
    const float* gim = gi + (size_t)m * 3 * DD;
    const float* ghm = gh + (size_t)m * 3 * DD;
    float ir = gim[d], iz = gim[DD + d], inn = gim[2 * DD + d];
    float hr = ghm[d], hz = ghm[DD + d], hn = ghm[2 * DD + d];
    float r = 1.0f / (1.0f + __expf(-(ir + hr)));
    float z = 1.0f / (1.0f + __expf(-(iz + hz)));
    float nn = tanhf(inn + r * hn);
    slots[i] = (1.0f - z) * nn + z * slots[i];
}

// ---------------- generic SGEMM: C[m,n] = sum_k A[m,k]*W[n,k] (+bias, relu, +=C) ----------------
// M,N multiples of 64; K multiple of 16. 64x64 tile, 256 threads, 4x4 microtile.
__global__ void k_gemm(const float* __restrict__ A, const float* __restrict__ W,
                       const float* __restrict__ bias, float* __restrict__ C,
                       int M, int N, int K, int relu, int accflag) {
    __shared__ __align__(16) float As[16][68];
    __shared__ __align__(16) float Ws[16][68];
    int tid = threadIdx.x;
    int m0 = blockIdx.y * 64, n0 = blockIdx.x * 64;
    int tx = tid & 15, ty = tid >> 4;
    float acc[4][4];
#pragma unroll
    for (int i = 0; i < 4; i++)
#pragma unroll
        for (int j = 0; j < 4; j++) acc[i][j] = 0.f;

    for (int k0 = 0; k0 < K; k0 += 16) {
#pragma unroll
        for (int l = 0; l < 4; l++) {
            int idx = tid + l * 256;
            int r = idx >> 4, c = idx & 15;
            As[c][r] = A[(size_t)(m0 + r) * K + k0 + c];
            Ws[c][r] = W[(size_t)(n0 + r) * K + k0 + c];
        }
        __syncthreads();
#pragma unroll
        for (int kk = 0; kk < 16; kk++) {
            float4 a4 = *(const float4*)&As[kk][ty * 4];
            float4 b4 = *(const float4*)&Ws[kk][tx * 4];
            float av[4] = {a4.x, a4.y, a4.z, a4.w};
            float bv[4] = {b4.x, b4.y, b4.z, b4.w};
#pragma unroll
            for (int i = 0; i < 4; i++)
#pragma unroll
                for (int j = 0; j < 4; j++) acc[i][j] = fmaf(av[i], bv[j], acc[i][j]);
        }
        __syncthreads();
    }
#pragma unroll
    for (int i = 0; i < 4; i++) {
#pragma unroll
        for (int j = 0; j < 4; j++) {
            int m = m0 + ty * 4 + i, n = n0 + tx * 4 + j;
            float v = acc[i][j];
            if (bias) v += bias[n];
            if (relu) v = fmaxf(v, 0.f);
            size_t o = (size_t)m * N + n;
            if (accflag) v += C[o];
            C[o] = v;
        }
    }
}

static void gemm(const float* A, const float* W, const float* bias, float* C,
                 int M, int N, int K, int relu, int accflag) {
    dim3 g(N / 64, M / 64);
    k_gemm<<<g, 256>>>(A, W, bias, C, M, N, K, relu, accflag);
}

extern "C" void kernel_launch(void* const* d_in, const int* in_sizes, int n_in,
                              void* d_out, int out_size) {
    const float* inputs     = (const float*)d_in[0];
    const float* slots_init = (const float*)d_in[1];
    const float* ln_f_w = (const float*)d_in[2];
    const float* ln_f_b = (const float*)d_in[3];
    const float* ln_s_w = (const float*)d_in[4];
    const float* ln_s_b = (const float*)d_in[5];
    const float* ln_p_w = (const float*)d_in[6];
    const float* ln_p_b = (const float*)d_in[7];
    const float* Wq  = (const float*)d_in[8];
    const float* Wk  = (const float*)d_in[9];
    const float* Wv  = (const float*)d_in[10];
    const float* W_ih = (const float*)d_in[11];
    const float* b_ih = (const float*)d_in[12];
    const float* W_hh = (const float*)d_in[13];
    const float* b_hh = (const float*)d_in[14];
    const float* W1 = (const float*)d_in[15];
    const float* b1 = (const float*)d_in[16];
    const float* W2 = (const float*)d_in[17];
    const float* b2 = (const float*)d_in[18];
    float* slots = (float*)d_out;

    float *p_mean, *p_rstd, *p_weff, *p_gv, *p_sln, *p_cb, *p_qe, *p_uh, *p_rs;
    float *p_updpre, *p_upd, *p_gi, *p_gh, *p_p, *p_h1;
    cudaGetSymbolAddress((void**)&p_mean, g_mean);
    cudaGetSymbolAddress((void**)&p_rstd, g_rstd);
    cudaGetSymbolAddress((void**)&p_weff, g_weff);
    cudaGetSymbolAddress((void**)&p_gv, g_gv);
    cudaGetSymbolAddress((void**)&p_sln, g_sln);
    cudaGetSymbolAddress((void**)&p_cb, g_cb);
    cudaGetSymbolAddress((void**)&p_qe, g_qe);
    cudaGetSymbolAddress((void**)&p_uh, g_uh);
    cudaGetSymbolAddress((void**)&p_rs, g_rs);
    cudaGetSymbolAddress((void**)&p_updpre, g_updpre);
    cudaGetSymbolAddress((void**)&p_upd, g_upd);
    cudaGetSymbolAddress((void**)&p_gi, g_gi);
    cudaGetSymbolAddress((void**)&p_gh, g_gh);
    cudaGetSymbolAddress((void**)&p_p, g_p);
    cudaGetSymbolAddress((void**)&p_h1, g_h1);

    // slots = slots_init
    cudaMemcpyAsync(slots, slots_init, (size_t)BB * KS * DD * sizeof(float),
                    cudaMemcpyDeviceToDevice);

    // once: input-row LN stats; effective query weight; bias fold vector
    k_stats<<<BB * NN / 8, 256>>>(inputs, p_mean, p_rstd);
    k_weff<<<DD, DD>>>(Wk, Wq, ln_f_w, p_weff);
    k_prep<<<1, DD>>>(Wk, Wq, ln_f_b, p_gv);

    for (int it = 0; it < NITER; it++) {
        // q-side: sln = LN_s(slots), cb = sln . g
        k_ln_small<<<BB * KS, DD>>>(slots, ln_s_w, ln_s_b, p_sln, p_gv, p_cb);
        // qe = sln @ Weff^T  (704x256, K=256)
        gemm(p_sln, p_weff, nullptr, p_qe, BB * KS, DD, DD, 0, 0);
        // zero accumulators
        k_zero<<<704, 256>>>(p_uh, p_rs);
        // fused attention pass over inputs
        k_attn<<<dim3(BB, SPLIT), 256>>>(inputs, p_mean, p_rstd, p_qe, p_cb, p_uh, p_rs);
        // finalize normalization + LN affine fold
        k_fin<<<704, 256>>>(p_uh, p_rs, ln_f_w, ln_f_b, p_updpre);
        // updates = updates_pre @ Wv^T
        gemm(p_updpre, Wv, nullptr, p_upd, BB * KS, DD, DD, 0, 0);
        // GRU gates
        gemm(p_upd, W_ih, b_ih, p_gi, BB * KS, 3 * DD, DD, 0, 0);
        gemm(slots, W_hh, b_hh, p_gh, BB * KS, 3 * DD, DD, 0, 0);
        k_gru<<<704, 256>>>(p_gi, p_gh, slots);
        // residual MLP
        k_ln_small<<<BB * KS, DD>>>(slots, ln_p_w, ln_p_b, p_p, nullptr, nullptr);
        gemm(p_p, W1, b1, p_h1, BB * KS, HH, DD, 1, 0);
        gemm(p_h1, W2, b2, slots, BB * KS, DD, HH, 0, 1);
    }
}

// round 3
// speedup vs baseline: 1.2799x; 1.2729x over previous
#include <cuda_runtime.h>
#include <cuda_bf16.h>
#include <math.h>

#define BB 64
#define NN 4096
#define DD 256
#define KS 11
#define HH 512
#define NITER 5
#define EPSF 1e-8f
#define LNEPS 1e-5f
#define SCALEF 0.0625f
#define TILE 128
#define NT (NN/TILE)

typedef unsigned long long ull;

// ---------------- f32x2 packed helpers ----------------
__device__ __forceinline__ ull fma2(ull a, ull b, ull c) {
    ull d; asm("fma.rn.f32x2 %0, %1, %2, %3;" : "=l"(d) : "l"(a), "l"(b), "l"(c)); return d;
}
__device__ __forceinline__ ull bf2f2(unsigned int u) {
    unsigned int lo = u << 16, hi = u & 0xffff0000u;
    ull d; asm("mov.b64 %0, {%1, %2};" : "=l"(d) : "r"(lo), "r"(hi)); return d;
}
__device__ __forceinline__ ull dup2(float a) {
    unsigned int u = __float_as_uint(a);
    ull d; asm("mov.b64 %0, {%1, %1};" : "=l"(d) : "r"(u)); return d;
}
__device__ __forceinline__ void unpack2(ull v, float& x, float& y) {
    unsigned int a, b;
    asm("mov.b64 {%0, %1}, %2;" : "=r"(a), "=r"(b) : "l"(v));
    x = __uint_as_float(a); y = __uint_as_float(b);
}

// ---------------- scratch (device globals; no allocation allowed) ----------------
__device__ __align__(16) unsigned short g_xln[BB*NN*DD];   // bf16 normalized inputs
__device__ float g_weff[DD*DD];
__device__ float g_gv[DD];
__device__ float g_sln[BB*KS*DD];
__device__ float g_cb[BB*KS];
__device__ float g_qe[BB*KS*DD];
__device__ float g_uhpart[BB*NT*KS*DD];
__device__ float g_rspart[BB*NT*KS];
__device__ float g_updpre[BB*KS*DD];
__device__ float g_upd[BB*KS*DD];
__device__ float g_gi[BB*KS*3*DD];
__device__ float g_gh[BB*KS*3*DD];
__device__ float g_p[BB*KS*DD];
__device__ float g_h1[BB*KS*HH];

// ---------------- xln = (x-mean)*rstd in bf16 (once) ----------------
__global__ void k_xln(const float* __restrict__ X, unsigned short* __restrict__ out) {
    int row = blockIdx.x * 8 + (threadIdx.x >> 5);
    int lane = threadIdx.x & 31;
    const float4* p = (const float4*)(X + (size_t)row * DD);
    float4 v0 = p[lane * 2], v1 = p[lane * 2 + 1];
    float s  = v0.x + v0.y + v0.z + v0.w + v1.x + v1.y + v1.z + v1.w;
    float s2 = v0.x*v0.x + v0.y*v0.y + v0.z*v0.z + v0.w*v0.w
             + v1.x*v1.x + v1.y*v1.y + v1.z*v1.z + v1.w*v1.w;
#pragma unroll
    for (int o = 16; o; o >>= 1) {
        s  += __shfl_xor_sync(0xffffffffu, s,  o);
        s2 += __shfl_xor_sync(0xffffffffu, s2, o);
    }
    float m = s * (1.0f / DD);
    float var = s2 * (1.0f / DD) - m * m;
    float r = rsqrtf(var + LNEPS);
    __nv_bfloat162 h0 = __float22bfloat162_rn(make_float2((v0.x-m)*r, (v0.y-m)*r));
    __nv_bfloat162 h1 = __float22bfloat162_rn(make_float2((v0.z-m)*r, (v0.w-m)*r));
    __nv_bfloat162 h2 = __float22bfloat162_rn(make_float2((v1.x-m)*r, (v1.y-m)*r));
    __nv_bfloat162 h3 = __float22bfloat162_rn(make_float2((v1.z-m)*r, (v1.w-m)*r));
    uint4 o;
    o.x = *(unsigned int*)&h0; o.y = *(unsigned int*)&h1;
    o.z = *(unsigned int*)&h2; o.w = *(unsigned int*)&h3;
    ((uint4*)(out + (size_t)row * DD))[lane] = o;
}

// ---------------- Weff[d][e] = ln_f_w[d] * sum_s Wk[s,d]*Wq[s,e] (once) ----------------
__global__ void k_weff(const float* __restrict__ Wk, const float* __restrict__ Wq,
                       const float* __restrict__ wf, float* __restrict__ weff) {
    __shared__ float col[DD];
    int d = blockIdx.x, e = threadIdx.x;
    col[e] = Wk[e * DD + d];
    __syncthreads();
    float acc = 0.f;
    for (int t = 0; t < DD; t++) acc = fmaf(col[t], Wq[t * DD + e], acc);
    weff[d * DD + e] = acc * wf[d];
}

// ---------------- g[e] = sum_t Wq[t,e] * (sum_d Wk[t,d]*ln_f_b[d]) (once) ----------------
__global__ void k_prep(const float* __restrict__ Wk, const float* __restrict__ Wq,
                       const float* __restrict__ bf, float* __restrict__ g) {
    __shared__ float wkb[DD];
    int t = threadIdx.x;
    float a = 0.f;
    for (int d = 0; d < DD; d++) a = fmaf(Wk[t * DD + d], bf[d], a);
    wkb[t] = a;
    __syncthreads();
    float acc = 0.f;
    for (int tt = 0; tt < DD; tt++) acc = fmaf(Wq[tt * DD + t], wkb[tt], acc);
    g[t] = acc;
}

// ---------------- LayerNorm, warp per row (704 rows); optional cb = out . gvec ----------------
__global__ void k_ln8(const float* __restrict__ in, const float* __restrict__ w,
                      const float* __restrict__ b, float* __restrict__ out,
                      const float* __restrict__ gvec, float* __restrict__ cb) {
    int row = blockIdx.x * 8 + (threadIdx.x >> 5);
    int lane = threadIdx.x & 31;
    const float4* p = (const float4*)(in + (size_t)row * DD);
    float4 v0 = p[lane * 2], v1 = p[lane * 2 + 1];
    float s  = v0.x + v0.y + v0.z + v0.w + v1.x + v1.y + v1.z + v1.w;
    float s2 = v0.x*v0.x + v0.y*v0.y + v0.z*v0.z + v0.w*v0.w
             + v1.x*v1.x + v1.y*v1.y + v1.z*v1.z + v1.w*v1.w;
#pragma unroll
    for (int o = 16; o; o >>= 1) {
        s  += __shfl_xor_sync(0xffffffffu, s,  o);
        s2 += __shfl_xor_sync(0xffffffffu, s2, o);
    }
    float m = s * (1.0f / DD);
    float var = s2 * (1.0f / DD) - m * m;
    float r = rsqrtf(var + LNEPS);
    float4 w0 = *(const float4*)(w + lane * 8), w1 = *(const float4*)(w + lane * 8 + 4);
    float4 b0 = *(const float4*)(b + lane * 8), b1 = *(const float4*)(b + lane * 8 + 4);
    float4 o0, o1;
    o0.x = (v0.x-m)*r*w0.x + b0.x; o0.y = (v0.y-m)*r*w0.y + b0.y;
    o0.z = (v0.z-m)*r*w0.z + b0.z; o0.w = (v0.w-m)*r*w0.w + b0.w;
    o1.x = (v1.x-m)*r*w1.x + b1.x; o1.y = (v1.y-m)*r*w1.y + b1.y;
    o1.z = (v1.z-m)*r*w1.z + b1.z; o1.w = (v1.w-m)*r*w1.w + b1.w;
    float4* q = (float4*)(out + (size_t)row * DD);
    q[lane * 2] = o0; q[lane * 2 + 1] = o1;
    if (gvec) {
        float4 g0 = *(const float4*)(gvec + lane * 8);
        float4 g1 = *(const float4*)(gvec + lane * 8 + 4);
        float c = o0.x*g0.x + o0.y*g0.y + o0.z*g0.z + o0.w*g0.w
                + o1.x*g1.x + o1.y*g1.y + o1.z*g1.z + o1.w*g1.w;
#pragma unroll
        for (int o2 = 16; o2; o2 >>= 1) c += __shfl_xor_sync(0xffffffffu, c, o2);
        if (lane == 0) cb[row] = c;
    }
}

// ---------------- fused attention (tile-resident, f32x2, no atomics) ----------------
// smem: Xs [0,67584) 128 x 264 bf16 (row stride 528B)
//       Qs [67584,78848) 11x256 f32 ; As [78848,84992) 128x12 f32
//       Us [84992,96256) 11x256 f32 ; rsw [96256,+176) ; cbs [96432,+44)
#define ATTN_SMEM 96512

__global__ void __launch_bounds__(256, 2) k_attn(
    const uint4* __restrict__ xln, const float* __restrict__ qe,
    const float* __restrict__ cb, float* __restrict__ uhpart,
    float* __restrict__ rspart) {
    extern __shared__ char sm[];
    char*  XsB = sm;
    float* Qs  = (float*)(sm + 67584);
    float* As  = (float*)(sm + 78848);
    float* Us  = (float*)(sm + 84992);
    float* rsw = (float*)(sm + 96256);
    float* cbs = (float*)(sm + 96432);

    int tile = blockIdx.x, b = blockIdx.y;
    int tid = threadIdx.x, lane = tid & 31, warp = tid >> 5;
    int row0 = tile * TILE;

    for (int i = tid; i < KS * DD; i += 256) Qs[i] = qe[(size_t)b * KS * DD + i];
    if (tid < KS) cbs[tid] = cb[b * KS + tid];
    {
        uint4* Xs4 = (uint4*)XsB;
        const uint4* src = xln + ((size_t)b * NN + row0) * (DD / 8);
        for (int idx = tid; idx < TILE * 32; idx += 256) {
            int r = idx >> 5, c = idx & 31;
            Xs4[r * 33 + c] = src[r * 32 + c];
        }
    }
    __syncthreads();

    // ---- dots + softmax: thread t < 128 owns row t ----
    if (tid < TILE) {
        int row = tid;
        ull dt2[KS];
#pragma unroll
        for (int i = 0; i < KS; i++) dt2[i] = 0ull;
        const uint4* xr = (const uint4*)(XsB + row * 528);
#pragma unroll 2
        for (int kc = 0; kc < 32; kc++) {
            uint4 xw = xr[kc];
            ull x0 = bf2f2(xw.x), x1 = bf2f2(xw.y), x2 = bf2f2(xw.z), x3 = bf2f2(xw.w);
            const float* qb = Qs + kc * 8;
#pragma unroll
            for (int i = 0; i < KS; i++) {
                ulonglong2 qa = *(const ulonglong2*)(qb + i * DD);
                ulonglong2 qc = *(const ulonglong2*)(qb + i * DD + 4);
                dt2[i] = fma2(x0, qa.x, dt2[i]);
                dt2[i] = fma2(x1, qa.y, dt2[i]);
                dt2[i] = fma2(x2, qc.x, dt2[i]);
                dt2[i] = fma2(x3, qc.y, dt2[i]);
            }
        }
        float l[KS];
#pragma unroll
        for (int i = 0; i < KS; i++) {
            float lo, hi; unpack2(dt2[i], lo, hi);
            l[i] = (lo + hi + cbs[i]) * SCALEF;
        }
        float mx = l[0];
#pragma unroll
        for (int i = 1; i < KS; i++) mx = fmaxf(mx, l[i]);
        float se = 0.f;
#pragma unroll
        for (int i = 0; i < KS; i++) { float e = __expf(l[i] - mx); l[i] = e; se += e; }
        float inv = __fdividef(1.0f, se);
#pragma unroll
        for (int i = 0; i < KS; i++) {
            float a = fmaf(l[i], inv, EPSF);
            As[row * 12 + i] = a;
            l[i] = a;
        }
#pragma unroll
        for (int i = 0; i < KS; i++) {
#pragma unroll
            for (int o = 16; o; o >>= 1) l[i] += __shfl_xor_sync(0xffffffffu, l[i], o);
        }
        if (lane == 0) {
#pragma unroll
            for (int i = 0; i < KS; i++) rsw[warp * KS + i] = l[i];
        }
    }
    __syncthreads();

    // ---- accumulation: warp -> d-half (warp&1), row-quarter (warp>>1) ----
    {
        int s = warp & 1, rq = warp >> 1;
        int d0 = s * 128;
        ull u0[KS], u1[KS];
#pragma unroll
        for (int i = 0; i < KS; i++) { u0[i] = 0ull; u1[i] = 0ull; }
        const char* xb = XsB + (size_t)(d0 + lane * 4) * 2;
#pragma unroll 2
        for (int r = 0; r < 32; r++) {
            int row = rq * 32 + r;
            const float4* a4 = (const float4*)(As + row * 12);
            float4 A0 = a4[0], A1 = a4[1], A2 = a4[2];
            uint2 xw = *(const uint2*)(xb + row * 528);
            ull x0 = bf2f2(xw.x), x1 = bf2f2(xw.y);
            float av[12] = {A0.x, A0.y, A0.z, A0.w, A1.x, A1.y, A1.z, A1.w,
                            A2.x, A2.y, A2.z, A2.w};
#pragma unroll
            for (int i = 0; i < KS; i++) {
                ull ad = dup2(av[i]);
                u0[i] = fma2(ad, x0, u0[i]);
                u1[i] = fma2(ad, x1, u1[i]);
            }
        }
        // combine 4 row-quarters (exclusive d-slices per step; no atomics)
        for (int g = 0; g < 4; g++) {
            if (rq == g) {
#pragma unroll
                for (int i = 0; i < KS; i++) {
                    float a, bq, c, d;
                    unpack2(u0[i], a, bq); unpack2(u1[i], c, d);
                    float4* up = (float4*)(Us + i * DD + d0) + lane;
                    if (g == 0) {
                        *up = make_float4(a, bq, c, d);
                    } else {
                        float4 t = *up;
                        t.x += a; t.y += bq; t.z += c; t.w += d;
                        *up = t;
                    }
                }
            }
            __syncthreads();
        }
    }

    // ---- write per-tile partials ----
    for (int i = tid; i < KS * DD; i += 256)
        uhpart[((size_t)(b * NT + tile)) * KS * DD + i] = Us[i];
    if (tid < KS) {
        float r = rsw[tid] + rsw[KS + tid] + rsw[2 * KS + tid] + rsw[3 * KS + tid];
        rspart[(size_t)(b * NT + tile) * KS + tid] = r;
    }
}

// ---------------- finalize: reduce partials, updates_pre = wf*uh/rs + bf ----------------
__global__ void k_fin(const float* __restrict__ uhpart, const float* __restrict__ rspart,
                      const float* __restrict__ wf, const float* __restrict__ bf,
                      float* __restrict__ out) {
    int m = blockIdx.x, d = threadIdx.x;
    int b = m / KS, i = m % KS;
    const float* up = uhpart + (size_t)b * NT * KS * DD + i * DD + d;
    const float* rp = rspart + b * NT * KS + i;
    float s = 0.f, r = 0.f;
#pragma unroll 4
    for (int t = 0; t < NT; t++) { s += up[(size_t)t * KS * DD]; r += rp[t * KS]; }
    out[(size_t)m * DD + d] = __fdividef(wf[d] * s, r) + bf[d];
}

// ---------------- GRU gate elementwise ----------------
__global__ void k_gru(const float* __restrict__ gi, const float* __restrict__ gh,
                      float* __restrict__ slots) {
    int i = blockIdx.x * 256 + threadIdx.x;
    if (i >= BB * KS * DD) return;
    int m = i >> 8, d = i & 255;
    const float* gim = gi + (size_t)m * 3 * DD;
    const float* ghm = gh + (size_t)m * 3 * DD;
    float ir = gim[d], iz = gim[DD + d], inn = gim[2 * DD + d];
    float hr = ghm[d], hz = ghm[DD + d], hn = ghm[2 * DD + d];
    float r = 1.0f / (1.0f + __expf(-(ir + hr)));
    float z = 1.0f / (1.0f + __expf(-(iz + hz)));
    float nn = tanhf(inn + r * hn);
    slots[i] = (1.0f - z) * nn + z * slots[i];
}

// ---------------- SGEMM body: C[m,n] = sum_k A[m,k]*W[n,k] (+bias, relu, +=C) ----------------
// 64x64 tile, 256 threads, 8(M as 4 f32x2 pairs) x 2(N) microtile.
__device__ __forceinline__ void gemm_body(
    const float* __restrict__ A, const float* __restrict__ W,
    const float* __restrict__ bias, float* __restrict__ C,
    int M, int N, int K, int relu, int accflag,
    float (*As)[68], float (*Ws)[68]) {
    int tid = threadIdx.x;
    int m0 = blockIdx.y * 64, n0 = blockIdx.x * 64;
    int ml = (tid >> 5) * 8;
    int nl = (tid & 31) * 2;
    ull acc[4][2];
#pragma unroll
    for (int i = 0; i < 4; i++) { acc[i][0] = 0ull; acc[i][1] = 0ull; }

    for (int k0 = 0; k0 < K; k0 += 16) {
#pragma unroll
        for (int l = 0; l < 4; l++) {
            int idx = tid + l * 256;
            int r = idx >> 4, c = idx & 15;
            As[c][r] = A[(size_t)(m0 + r) * K + k0 + c];
            Ws[c][r] = W[(size_t)(n0 + r) * K + k0 + c];
        }
        __syncthreads();
#pragma unroll
        for (int kk = 0; kk < 16; kk++) {
            ulonglong2 a01 = *(const ulonglong2*)&As[kk][ml];
            ulonglong2 a23 = *(const ulonglong2*)&As[kk][ml + 4];
            float2 bv = *(const float2*)&Ws[kk][nl];
            ull b0 = dup2(bv.x), b1 = dup2(bv.y);
            acc[0][0] = fma2(a01.x, b0, acc[0][0]); acc[0][1] = fma2(a01.x, b1, acc[0][1]);
            acc[1][0] = fma2(a01.y, b0, acc[1][0]); acc[1][1] = fma2(a01.y, b1, acc[1][1]);
            acc[2][0] = fma2(a23.x, b0, acc[2][0]); acc[2][1] = fma2(a23.x, b1, acc[2][1]);
            acc[3][0] = fma2(a23.y, b0, acc[3][0]); acc[3][1] = fma2(a23.y, b1, acc[3][1]);
        }
        __syncthreads();
    }
    float bb0 = bias ? bias[n0 + nl] : 0.f;
    float bb1 = bias ? bias[n0 + nl + 1] : 0.f;
#pragma unroll
    for (int mi = 0; mi < 4; mi++) {
        float r0c0, r1c0, r0c1, r1c1;
        unpack2(acc[mi][0], r0c0, r1c0);
        unpack2(acc[mi][1], r0c1, r1c1);
        int m = m0 + ml + mi * 2;
        float2 v0 = make_float2(r0c0 + bb0, r0c1 + bb1);
        float2 v1 = make_float2(r1c0 + bb0, r1c1 + bb1);
        if (relu) {
            v0.x = fmaxf(v0.x, 0.f); v0.y = fmaxf(v0.y, 0.f);
            v1.x = fmaxf(v1.x, 0.f); v1.y = fmaxf(v1.y, 0.f);
        }
        float2* p0 = (float2*)&C[(size_t)m * N + n0 + nl];
        float2* p1 = (float2*)&C[(size_t)(m + 1) * N + n0 + nl];
        if (accflag) {
            float2 t0 = *p0, t1 = *p1;
            v0.x += t0.x; v0.y += t0.y; v1.x += t1.x; v1.y += t1.y;
        }
        *p0 = v0; *p1 = v1;
    }
}

__global__ void __launch_bounds__(256) k_gemm(
    const float* __restrict__ A, const float* __restrict__ W,
    const float* __restrict__ bias, float* __restrict__ C,
    int M, int N, int K, int relu, int accflag) {
    __shared__ __align__(16) float As[16][68];
    __shared__ __align__(16) float Ws[16][68];
    gemm_body(A, W, bias, C, M, N, K, relu, accflag, As, Ws);
}

__global__ void __launch_bounds__(256) k_gemmd(
    const float* __restrict__ A0, const float* __restrict__ A1,
    const float* __restrict__ W0, const float* __restrict__ W1,
    const float* __restrict__ b0, const float* __restrict__ b1,
    float* __restrict__ C0, float* __restrict__ C1, int M, int N, int K) {
    __shared__ __align__(16) float As[16][68];
    __shared__ __align__(16) float Ws[16][68];
    if (blockIdx.z == 0) gemm_body(A0, W0, b0, C0, M, N, K, 0, 0, As, Ws);
    else                 gemm_body(A1, W1, b1, C1, M, N, K, 0, 0, As, Ws);
}

extern "C" void kernel_launch(void* const* d_in, const int* in_sizes, int n_in,
                              void* d_out, int out_size) {
    const float* inputs     = (const float*)d_in[0];
    const float* slots_init = (const float*)d_in[1];
    const float* ln_f_w = (const float*)d_in[2];
    const float* ln_f_b = (const float*)d_in[3];
    const float* ln_s_w = (const float*)d_in[4];
    const float* ln_s_b = (const float*)d_in[5];
    const float* ln_p_w = (const float*)d_in[6];
    const float* ln_p_b = (const float*)d_in[7];
    const float* Wq  = (const float*)d_in[8];
    const float* Wk  = (const float*)d_in[9];
    const float* Wv  = (const float*)d_in[10];
    const float* W_ih = (const float*)d_in[11];
    const float* b_ih = (const float*)d_in[12];
    const float* W_hh = (const float*)d_in[13];
    const float* b_hh = (const float*)d_in[14];
    const float* W1 = (const float*)d_in[15];
    const float* b1 = (const float*)d_in[16];
    const float* W2 = (const float*)d_in[17];
    const float* b2 = (const float*)d_in[18];
    float* slots = (float*)d_out;

    unsigned short* p_xln;
    float *p_weff, *p_gv, *p_sln, *p_cb, *p_qe, *p_uhp, *p_rsp;
    float *p_updpre, *p_upd, *p_gi, *p_gh, *p_p, *p_h1;
    cudaGetSymbolAddress((void**)&p_xln, g_xln);
    cudaGetSymbolAddress((void**)&p_weff, g_weff);
    cudaGetSymbolAddress((void**)&p_gv, g_gv);
    cudaGetSymbolAddress((void**)&p_sln, g_sln);
    cudaGetSymbolAddress((void**)&p_cb, g_cb);
    cudaGetSymbolAddress((void**)&p_qe, g_qe);
    cudaGetSymbolAddress((void**)&p_uhp, g_uhpart);
    cudaGetSymbolAddress((void**)&p_rsp, g_rspart);
    cudaGetSymbolAddress((void**)&p_updpre, g_updpre);
    cudaGetSymbolAddress((void**)&p_upd, g_upd);
    cudaGetSymbolAddress((void**)&p_gi, g_gi);
    cudaGetSymbolAddress((void**)&p_gh, g_gh);
    cudaGetSymbolAddress((void**)&p_p, g_p);
    cudaGetSymbolAddress((void**)&p_h1, g_h1);

    cudaFuncSetAttribute(k_attn, cudaFuncAttributeMaxDynamicSharedMemorySize, ATTN_SMEM);

    cudaMemcpyAsync(slots, slots_init, (size_t)BB * KS * DD * sizeof(float),
                    cudaMemcpyDeviceToDevice);

    k_xln<<<BB * NN / 8, 256>>>(inputs, p_xln);
    k_weff<<<DD, DD>>>(Wk, Wq, ln_f_w, p_weff);
    k_prep<<<1, DD>>>(Wk, Wq, ln_f_b, p_gv);

    for (int it = 0; it < NITER; it++) {
        k_ln8<<<88, 256>>>(slots, ln_s_w, ln_s_b, p_sln, p_gv, p_cb);
        k_gemm<<<dim3(4, 11), 256>>>(p_sln, p_weff, nullptr, p_qe, 704, 256, 256, 0, 0);
        k_attn<<<dim3(NT, BB), 256, ATTN_SMEM>>>((const uint4*)p_xln, p_qe, p_cb,
                                                 p_uhp, p_rsp);
        k_fin<<<704, 256>>>(p_uhp, p_rsp, ln_f_w, ln_f_b, p_updpre);
        k_gemm<<<dim3(4, 11), 256>>>(p_updpre, Wv, nullptr, p_upd, 704, 256, 256, 0, 0);
        k_gemmd<<<dim3(12, 11, 2), 256>>>(p_upd, slots, W_ih, W_hh, b_ih, b_hh,
                                          p_gi, p_gh, 704, 768, 256);
        k_gru<<<704, 256>>>(p_gi, p_gh, slots);
        k_ln8<<<88, 256>>>(slots, ln_p_w, ln_p_b, p_p, nullptr, nullptr);
        k_gemm<<<dim3(8, 11), 256>>>(p_p, W1, b1, p_h1, 704, 512, 256, 1, 0);
        k_gemm<<<dim3(4, 11), 256>>>(p_h1, W2, b2, slots, 704, 256, 512, 0, 1);
    }
}

// round 4
// speedup vs baseline: 1.6032x; 1.2526x over previous
#include <cuda_runtime.h>
#include <cuda_bf16.h>
#include <math.h>

#define BB 64
#define NN 4096
#define DD 256
#define KS 11
#define HH 512
#define NITER 5
#define EPSF 1e-8f
#define LNEPS 1e-5f
#define SCALEF 0.0625f
#define TILE 128
#define NT (NN/TILE)
#define TPB 8
#define NTP (NT/TPB)   // 4 partials per batch

typedef unsigned long long ull;

// ---------------- f32x2 packed helpers ----------------
__device__ __forceinline__ ull fma2(ull a, ull b, ull c) {
    ull d; asm("fma.rn.f32x2 %0, %1, %2, %3;" : "=l"(d) : "l"(a), "l"(b), "l"(c)); return d;
}
__device__ __forceinline__ ull bf2f2(unsigned int u) {
    unsigned int lo = u << 16, hi = u & 0xffff0000u;
    ull d; asm("mov.b64 %0, {%1, %2};" : "=l"(d) : "r"(lo), "r"(hi)); return d;
}
__device__ __forceinline__ ull dup2(float a) {
    unsigned int u = __float_as_uint(a);
    ull d; asm("mov.b64 %0, {%1, %1};" : "=l"(d) : "r"(u)); return d;
}
__device__ __forceinline__ void unpack2(ull v, float& x, float& y) {
    unsigned int a, b;
    asm("mov.b64 {%0, %1}, %2;" : "=r"(a), "=r"(b) : "l"(v));
    x = __uint_as_float(a); y = __uint_as_float(b);
}

// ---------------- scratch ----------------
__device__ __align__(16) unsigned short g_xln[BB*NN*DD];
__device__ float g_weff[DD*DD];
__device__ float g_wgv[DD + 2];      // wgv[0..255], [256]=C1, [257]=C0
__device__ float g_wihv[3*DD*DD];    // W_ih @ Wv (768x256)
__device__ float g_cb[BB*KS];
__device__ float g_qe[BB*KS*DD];
__device__ float g_uhpart[BB*NTP*KS*DD];
__device__ float g_rspart[BB*NTP*KS];
__device__ float g_updpre[BB*KS*DD];
__device__ float g_gi[BB*KS*3*DD];
__device__ float g_gh[BB*KS*3*DD];
__device__ float g_p[BB*KS*DD];
__device__ float g_h1[BB*KS*HH];

// ---------------- xln = (x-mean)*rstd in bf16 (once) ----------------
__global__ void k_xln(const float* __restrict__ X, unsigned short* __restrict__ out) {
    int row = blockIdx.x * 8 + (threadIdx.x >> 5);
    int lane = threadIdx.x & 31;
    const float4* p = (const float4*)(X + (size_t)row * DD);
    float4 v0 = p[lane * 2], v1 = p[lane * 2 + 1];
    float s  = v0.x + v0.y + v0.z + v0.w + v1.x + v1.y + v1.z + v1.w;
    float s2 = v0.x*v0.x + v0.y*v0.y + v0.z*v0.z + v0.w*v0.w
             + v1.x*v1.x + v1.y*v1.y + v1.z*v1.z + v1.w*v1.w;
#pragma unroll
    for (int o = 16; o; o >>= 1) {
        s  += __shfl_xor_sync(0xffffffffu, s,  o);
        s2 += __shfl_xor_sync(0xffffffffu, s2, o);
    }
    float m = s * (1.0f / DD);
    float var = s2 * (1.0f / DD) - m * m;
    float r = rsqrtf(var + LNEPS);
    __nv_bfloat162 h0 = __float22bfloat162_rn(make_float2((v0.x-m)*r, (v0.y-m)*r));
    __nv_bfloat162 h1 = __float22bfloat162_rn(make_float2((v0.z-m)*r, (v0.w-m)*r));
    __nv_bfloat162 h2 = __float22bfloat162_rn(make_float2((v1.x-m)*r, (v1.y-m)*r));
    __nv_bfloat162 h3 = __float22bfloat162_rn(make_float2((v1.z-m)*r, (v1.w-m)*r));
    uint4 o;
    o.x = *(unsigned int*)&h0; o.y = *(unsigned int*)&h1;
    o.z = *(unsigned int*)&h2; o.w = *(unsigned int*)&h3;
    ((uint4*)(out + (size_t)row * DD))[lane] = o;
}

// ---------------- wprep: weff rows (blocks 0..255), gv/wgv/consts (block 256) ----------------
__global__ void k_wprep(const float* __restrict__ Wk, const float* __restrict__ Wq,
                        const float* __restrict__ wf, const float* __restrict__ bf,
                        const float* __restrict__ ws, const float* __restrict__ bs,
                        float* __restrict__ weff, float* __restrict__ wgv) {
    __shared__ float col[DD];
    __shared__ float red[8];
    int t = threadIdx.x;
    if (blockIdx.x < DD) {
        int d = blockIdx.x;
        col[t] = Wk[t * DD + d];
        __syncthreads();
        float acc = 0.f;
        for (int s = 0; s < DD; s++) acc = fmaf(col[s], Wq[s * DD + t], acc);
        weff[d * DD + t] = acc * wf[d];
    } else {
        // gv[t] = sum_s Wq[s,t] * (sum_e Wk[s,e]*bf[e])
        float a = 0.f;
        for (int e = 0; e < DD; e++) a = fmaf(Wk[t * DD + e], bf[e], a);
        col[t] = a;
        __syncthreads();
        float gv = 0.f;
        for (int s = 0; s < DD; s++) gv = fmaf(Wq[s * DD + t], col[s], gv);
        float w = ws[t] * gv;
        wgv[t] = w;
        // C1 = sum ws*gv, C0 = sum bs*gv
        float c1 = w, c0 = bs[t] * gv;
        int lane = t & 31, warp = t >> 5;
#pragma unroll
        for (int o = 16; o; o >>= 1) {
            c1 += __shfl_xor_sync(0xffffffffu, c1, o);
            c0 += __shfl_xor_sync(0xffffffffu, c0, o);
        }
        __syncthreads();
        if (lane == 0) { red[warp] = c1; }
        __syncthreads();
        if (t == 0) {
            float s1 = 0.f;
            for (int i = 0; i < 8; i++) s1 += red[i];
            wgv[DD] = s1;
        }
        __syncthreads();
        if (lane == 0) { red[warp] = c0; }
        __syncthreads();
        if (t == 1) {
            float s0 = 0.f;
            for (int i = 0; i < 8; i++) s0 += red[i];
            wgv[DD + 1] = s0;
        }
    }
}

// ---------------- wihv[m][e] = sum_j W_ih[m,j] * Wv[j,e] (once) ----------------
__global__ void k_wihv(const float* __restrict__ Wih, const float* __restrict__ Wv,
                       float* __restrict__ out) {
    __shared__ float row[DD];
    int m = blockIdx.x, t = threadIdx.x;
    row[t] = Wih[m * DD + t];
    __syncthreads();
    float acc = 0.f;
#pragma unroll 4
    for (int j = 0; j < DD; j++) acc = fmaf(row[j], Wv[j * DD + t], acc);
    out[m * DD + t] = acc;
}

// ---------------- fused LN_s + cb + qe GEMM ----------------
// qe[m][n] = sum_e LNs(slots)[m,e] * weff[n][e];  cb[m] = r*dot3 - r*mean*C1 + C0
__global__ void __launch_bounds__(256) k_qeln(
    const float* __restrict__ slots, const float* __restrict__ weff,
    const float* __restrict__ wgv, const float* __restrict__ lsw,
    const float* __restrict__ lsb, float* __restrict__ qe, float* __restrict__ cb) {
    __shared__ __align__(16) float As[16][68];
    __shared__ __align__(16) float Ws[16][68];
    __shared__ float ws[DD], bs[DD], rowm[64], rowr[64];
    int tid = threadIdx.x, lane = tid & 31, warp = tid >> 5;
    int m0 = blockIdx.y * 64, n0 = blockIdx.x * 64;
    ws[tid] = lsw[tid]; bs[tid] = lsb[tid];
    float C1 = wgv[DD], C0 = wgv[DD + 1];
    float4 wg0 = *(const float4*)(wgv + lane * 8);
    float4 wg1 = *(const float4*)(wgv + lane * 8 + 4);
    // stats: warp handles 8 rows
#pragma unroll
    for (int rr = 0; rr < 8; rr++) {
        int rl = warp * 8 + rr, row = m0 + rl;
        const float4* p = (const float4*)(slots + (size_t)row * DD);
        float4 v0 = p[lane * 2], v1 = p[lane * 2 + 1];
        float s  = v0.x + v0.y + v0.z + v0.w + v1.x + v1.y + v1.z + v1.w;
        float s2 = v0.x*v0.x + v0.y*v0.y + v0.z*v0.z + v0.w*v0.w
                 + v1.x*v1.x + v1.y*v1.y + v1.z*v1.z + v1.w*v1.w;
        float s3 = v0.x*wg0.x + v0.y*wg0.y + v0.z*wg0.z + v0.w*wg0.w
                 + v1.x*wg1.x + v1.y*wg1.y + v1.z*wg1.z + v1.w*wg1.w;
#pragma unroll
        for (int o = 16; o; o >>= 1) {
            s  += __shfl_xor_sync(0xffffffffu, s,  o);
            s2 += __shfl_xor_sync(0xffffffffu, s2, o);
            s3 += __shfl_xor_sync(0xffffffffu, s3, o);
        }
        if (lane == 0) {
            float m = s * (1.0f / DD);
            float var = s2 * (1.0f / DD) - m * m;
            float r = rsqrtf(var + LNEPS);
            rowm[rl] = m; rowr[rl] = r;
            if (blockIdx.x == 0) cb[row] = r * s3 - r * m * C1 + C0;
        }
    }
    __syncthreads();
    // GEMM with LN applied at A-staging
    int ml = (tid >> 5) * 8, nl = (tid & 31) * 2;
    ull acc[4][2];
#pragma unroll
    for (int i = 0; i < 4; i++) { acc[i][0] = 0ull; acc[i][1] = 0ull; }
    for (int k0 = 0; k0 < DD; k0 += 16) {
#pragma unroll
        for (int l = 0; l < 4; l++) {
            int idx = tid + l * 256;
            int r = idx >> 4, c = idx & 15;
            float v = slots[(size_t)(m0 + r) * DD + k0 + c];
            As[c][r] = (v - rowm[r]) * rowr[r] * ws[k0 + c] + bs[k0 + c];
            Ws[c][r] = weff[(size_t)(n0 + r) * DD + k0 + c];
        }
        __syncthreads();
#pragma unroll
        for (int kk = 0; kk < 16; kk++) {
            ulonglong2 a01 = *(const ulonglong2*)&As[kk][ml];
            ulonglong2 a23 = *(const ulonglong2*)&As[kk][ml + 4];
            float2 bv = *(const float2*)&Ws[kk][nl];
            ull b0 = dup2(bv.x), b1 = dup2(bv.y);
            acc[0][0] = fma2(a01.x, b0, acc[0][0]); acc[0][1] = fma2(a01.x, b1, acc[0][1]);
            acc[1][0] = fma2(a01.y, b0, acc[1][0]); acc[1][1] = fma2(a01.y, b1, acc[1][1]);
            acc[2][0] = fma2(a23.x, b0, acc[2][0]); acc[2][1] = fma2(a23.x, b1, acc[2][1]);
            acc[3][0] = fma2(a23.y, b0, acc[3][0]); acc[3][1] = fma2(a23.y, b1, acc[3][1]);
        }
        __syncthreads();
    }
#pragma unroll
    for (int mi = 0; mi < 4; mi++) {
        float r0c0, r1c0, r0c1, r1c1;
        unpack2(acc[mi][0], r0c0, r1c0);
        unpack2(acc[mi][1], r0c1, r1c1);
        int m = m0 + ml + mi * 2;
        *(float2*)&qe[(size_t)m * DD + n0 + nl] = make_float2(r0c0, r0c1);
        *(float2*)&qe[(size_t)(m + 1) * DD + n0 + nl] = make_float2(r1c0, r1c1);
    }
}

// ---------------- fused attention: 8 tiles per block, persistent accumulators ----------------
// smem: Xs[0,67584) 128x264 bf16 (stride 528B); Qs[67584,78848); As[78848,84992) 128x12;
//       Us[84992,96256); rsw[96256,+176); cbs[96432,+44)
#define ATTN_SMEM 96512

__global__ void __launch_bounds__(256, 2) k_attn(
    const uint4* __restrict__ xln, const float* __restrict__ qe,
    const float* __restrict__ cb, float* __restrict__ uhpart,
    float* __restrict__ rspart) {
    extern __shared__ char sm[];
    char*  XsB = sm;
    float* Qs  = (float*)(sm + 67584);
    float* As  = (float*)(sm + 78848);
    float* Us  = (float*)(sm + 84992);
    float* rsw = (float*)(sm + 96256);
    float* cbs = (float*)(sm + 96432);

    int bx = blockIdx.x, b = blockIdx.y;
    int tid = threadIdx.x, lane = tid & 31, warp = tid >> 5;

    for (int i = tid; i < KS * DD; i += 256) Qs[i] = qe[(size_t)b * KS * DD + i];
    if (tid < KS) cbs[tid] = cb[b * KS + tid];

    int dq = warp & 3, rh = warp >> 2;     // accum: d-quarter, row-half
    int d0 = dq * 64;
    ull u[KS];
    float rsl[KS];
#pragma unroll
    for (int i = 0; i < KS; i++) { u[i] = 0ull; rsl[i] = 0.f; }

    for (int t = 0; t < TPB; t++) {
        int row0 = (bx * TPB + t) * TILE;
        // stage X tile
        {
            uint4* Xs4 = (uint4*)XsB;
            const uint4* src = xln + ((size_t)b * NN + row0) * (DD / 8);
            for (int idx = tid; idx < TILE * 32; idx += 256) {
                int r = idx >> 5, c = idx & 31;
                Xs4[r * 33 + c] = src[r * 32 + c];
            }
        }
        __syncthreads();

        // dots + softmax: thread t<128 owns one row
        if (tid < TILE) {
            int row = tid;
            ull dt2[KS];
#pragma unroll
            for (int i = 0; i < KS; i++) dt2[i] = 0ull;
            const uint4* xr = (const uint4*)(XsB + row * 528);
#pragma unroll 2
            for (int kc = 0; kc < 32; kc++) {
                uint4 xw = xr[kc];
                ull x0 = bf2f2(xw.x), x1 = bf2f2(xw.y), x2 = bf2f2(xw.z), x3 = bf2f2(xw.w);
                const float* qb = Qs + kc * 8;
#pragma unroll
                for (int i = 0; i < KS; i++) {
                    ulonglong2 qa = *(const ulonglong2*)(qb + i * DD);
                    ulonglong2 qc = *(const ulonglong2*)(qb + i * DD + 4);
                    dt2[i] = fma2(x0, qa.x, dt2[i]);
                    dt2[i] = fma2(x1, qa.y, dt2[i]);
                    dt2[i] = fma2(x2, qc.x, dt2[i]);
                    dt2[i] = fma2(x3, qc.y, dt2[i]);
                }
            }
            float l[KS];
#pragma unroll
            for (int i = 0; i < KS; i++) {
                float lo, hi; unpack2(dt2[i], lo, hi);
                l[i] = (lo + hi + cbs[i]) * SCALEF;
            }
            float mx = l[0];
#pragma unroll
            for (int i = 1; i < KS; i++) mx = fmaxf(mx, l[i]);
            float se = 0.f;
#pragma unroll
            for (int i = 0; i < KS; i++) { float e = __expf(l[i] - mx); l[i] = e; se += e; }
            float inv = __fdividef(1.0f, se);
#pragma unroll
            for (int i = 0; i < KS; i++) {
                float a = fmaf(l[i], inv, EPSF);
                As[row * 12 + i] = a;
                rsl[i] += a;
            }
        }
        __syncthreads();

        // accumulation: warp -> d-quarter dq, rows [rh*64, rh*64+64)
        {
            const char* xb = XsB + (size_t)(d0 + lane * 2) * 2;
#pragma unroll 2
            for (int r = 0; r < 64; r++) {
                int row = rh * 64 + r;
                const float4* a4 = (const float4*)(As + row * 12);
                float4 A0 = a4[0], A1 = a4[1], A2 = a4[2];
                unsigned int xw = *(const unsigned int*)(xb + row * 528);
                ull x0 = bf2f2(xw);
                float av[12] = {A0.x, A0.y, A0.z, A0.w, A1.x, A1.y, A1.z, A1.w,
                                A2.x, A2.y, A2.z, A2.w};
#pragma unroll
                for (int i = 0; i < KS; i++) u[i] = fma2(dup2(av[i]), x0, u[i]);
            }
        }
        __syncthreads();
    }

    // row-sum reduce (dot-phase warps 0-3 hold rsl)
    if (tid < TILE) {
#pragma unroll
        for (int i = 0; i < KS; i++) {
#pragma unroll
            for (int o = 16; o; o >>= 1) rsl[i] += __shfl_xor_sync(0xffffffffu, rsl[i], o);
        }
        if (lane == 0) {
#pragma unroll
            for (int i = 0; i < KS; i++) rsw[warp * KS + i] = rsl[i];
        }
    }
    // combine row-halves into Us (exclusive d-quarter slices per step)
    for (int g = 0; g < 2; g++) {
        if (rh == g) {
#pragma unroll
            for (int i = 0; i < KS; i++) {
                float x0, x1; unpack2(u[i], x0, x1);
                float2* up = (float2*)(Us + i * DD + d0) + lane;
                if (g == 0) *up = make_float2(x0, x1);
                else { float2 tt = *up; tt.x += x0; tt.y += x1; *up = tt; }
            }
        }
        __syncthreads();
    }

    // write partials
    for (int i = tid; i < KS * DD; i += 256)
        uhpart[((size_t)(b * NTP + bx)) * KS * DD + i] = Us[i];
    if (tid < KS) {
        float r = rsw[tid] + rsw[KS + tid] + rsw[2 * KS + tid] + rsw[3 * KS + tid];
        rspart[(size_t)(b * NTP + bx) * KS + tid] = r;
    }
}

// ---------------- finalize ----------------
__global__ void k_fin(const float* __restrict__ uhpart, const float* __restrict__ rspart,
                      const float* __restrict__ wf, const float* __restrict__ bf,
                      float* __restrict__ out) {
    int m = blockIdx.x, d = threadIdx.x;
    int b = m / KS, i = m % KS;
    const float* up = uhpart + ((size_t)b * NTP) * KS * DD + i * DD + d;
    const float* rp = rspart + b * NTP * KS + i;
    float s = 0.f, r = 0.f;
#pragma unroll
    for (int t = 0; t < NTP; t++) { s += up[(size_t)t * KS * DD]; r += rp[t * KS]; }
    out[(size_t)m * DD + d] = __fdividef(wf[d] * s, r) + bf[d];
}

// ---------------- fused GRU + LN_p: warp per row ----------------
__global__ void k_gruln(const float* __restrict__ gi, const float* __restrict__ gh,
                        float* __restrict__ slots, const float* __restrict__ wp,
                        const float* __restrict__ bp, float* __restrict__ p) {
    int m = blockIdx.x * 8 + (threadIdx.x >> 5);
    int lane = threadIdx.x & 31;
    int d0 = lane * 8;
    const float* gim = gi + (size_t)m * 3 * DD;
    const float* ghm = gh + (size_t)m * 3 * DD;
    float ir[8], iz[8], in_[8], hr[8], hz[8], hn[8], sp[8], v[8];
    *(float4*)ir   = *(const float4*)(gim + d0);       *(float4*)(ir+4)  = *(const float4*)(gim + d0 + 4);
    *(float4*)iz   = *(const float4*)(gim + DD + d0);  *(float4*)(iz+4)  = *(const float4*)(gim + DD + d0 + 4);
    *(float4*)in_  = *(const float4*)(gim + 2*DD + d0);*(float4*)(in_+4) = *(const float4*)(gim + 2*DD + d0 + 4);
    *(float4*)hr   = *(const float4*)(ghm + d0);       *(float4*)(hr+4)  = *(const float4*)(ghm + d0 + 4);
    *(float4*)hz   = *(const float4*)(ghm + DD + d0);  *(float4*)(hz+4)  = *(const float4*)(ghm + DD + d0 + 4);
    *(float4*)hn   = *(const float4*)(ghm + 2*DD + d0);*(float4*)(hn+4)  = *(const float4*)(ghm + 2*DD + d0 + 4);
    *(float4*)sp   = *(const float4*)(slots + (size_t)m*DD + d0);
    *(float4*)(sp+4) = *(const float4*)(slots + (size_t)m*DD + d0 + 4);
    float s = 0.f, s2 = 0.f;
#pragma unroll
    for (int j = 0; j < 8; j++) {
        float r = 1.0f / (1.0f + __expf(-(ir[j] + hr[j])));
        float z = 1.0f / (1.0f + __expf(-(iz[j] + hz[j])));
        float n = tanhf(in_[j] + r * hn[j]);
        float vv = (1.0f - z) * n + z * sp[j];
        v[j] = vv; s += vv; s2 += vv * vv;
    }
#pragma unroll
    for (int o = 16; o; o >>= 1) {
        s  += __shfl_xor_sync(0xffffffffu, s,  o);
        s2 += __shfl_xor_sync(0xffffffffu, s2, o);
    }
    float mm = s * (1.0f / DD);
    float var = s2 * (1.0f / DD) - mm * mm;
    float rr = rsqrtf(var + LNEPS);
    *(float4*)(slots + (size_t)m*DD + d0)     = *(float4*)v;
    *(float4*)(slots + (size_t)m*DD + d0 + 4) = *(float4*)(v+4);
    float w_[8], b_[8], pv[8];
    *(float4*)w_ = *(const float4*)(wp + d0); *(float4*)(w_+4) = *(const float4*)(wp + d0 + 4);
    *(float4*)b_ = *(const float4*)(bp + d0); *(float4*)(b_+4) = *(const float4*)(bp + d0 + 4);
#pragma unroll
    for (int j = 0; j < 8; j++) pv[j] = (v[j] - mm) * rr * w_[j] + b_[j];
    *(float4*)(p + (size_t)m*DD + d0)     = *(float4*)pv;
    *(float4*)(p + (size_t)m*DD + d0 + 4) = *(float4*)(pv+4);
}

// ---------------- SGEMM body ----------------
__device__ __forceinline__ void gemm_body(
    const float* __restrict__ A, const float* __restrict__ W,
    const float* __restrict__ bias, float* __restrict__ C,
    int M, int N, int K, int relu, int accflag,
    float (*As)[68], float (*Ws)[68]) {
    int tid = threadIdx.x;
    int m0 = blockIdx.y * 64, n0 = blockIdx.x * 64;
    int ml = (tid >> 5) * 8;
    int nl = (tid & 31) * 2;
    ull acc[4][2];
#pragma unroll
    for (int i = 0; i < 4; i++) { acc[i][0] = 0ull; acc[i][1] = 0ull; }

    for (int k0 = 0; k0 < K; k0 += 16) {
#pragma unroll
        for (int l = 0; l < 4; l++) {
            int idx = tid + l * 256;
            int r = idx >> 4, c = idx & 15;
            As[c][r] = A[(size_t)(m0 + r) * K + k0 + c];
            Ws[c][r] = W[(size_t)(n0 + r) * K + k0 + c];
        }
        __syncthreads();
#pragma unroll
        for (int kk = 0; kk < 16; kk++) {
            ulonglong2 a01 = *(const ulonglong2*)&As[kk][ml];
            ulonglong2 a23 = *(const ulonglong2*)&As[kk][ml + 4];
            float2 bv = *(const float2*)&Ws[kk][nl];
            ull b0 = dup2(bv.x), b1 = dup2(bv.y);
            acc[0][0] = fma2(a01.x, b0, acc[0][0]); acc[0][1] = fma2(a01.x, b1, acc[0][1]);
            acc[1][0] = fma2(a01.y, b0, acc[1][0]); acc[1][1] = fma2(a01.y, b1, acc[1][1]);
            acc[2][0] = fma2(a23.x, b0, acc[2][0]); acc[2][1] = fma2(a23.x, b1, acc[2][1]);
            acc[3][0] = fma2(a23.y, b0, acc[3][0]); acc[3][1] = fma2(a23.y, b1, acc[3][1]);
        }
        __syncthreads();
    }
    float bb0 = bias ? bias[n0 + nl] : 0.f;
    float bb1 = bias ? bias[n0 + nl + 1] : 0.f;
#pragma unroll
    for (int mi = 0; mi < 4; mi++) {
        float r0c0, r1c0, r0c1, r1c1;
        unpack2(acc[mi][0], r0c0, r1c0);
        unpack2(acc[mi][1], r0c1, r1c1);
        int m = m0 + ml + mi * 2;
        float2 v0 = make_float2(r0c0 + bb0, r0c1 + bb1);
        float2 v1 = make_float2(r1c0 + bb0, r1c1 + bb1);
        if (relu) {
            v0.x = fmaxf(v0.x, 0.f); v0.y = fmaxf(v0.y, 0.f);
            v1.x = fmaxf(v1.x, 0.f); v1.y = fmaxf(v1.y, 0.f);
        }
        float2* p0 = (float2*)&C[(size_t)m * N + n0 + nl];
        float2* p1 = (float2*)&C[(size_t)(m + 1) * N + n0 + nl];
        if (accflag) {
            float2 t0 = *p0, t1 = *p1;
            v0.x += t0.x; v0.y += t0.y; v1.x += t1.x; v1.y += t1.y;
        }
        *p0 = v0; *p1 = v1;
    }
}

__global__ void __launch_bounds__(256) k_gemm(
    const float* __restrict__ A, const float* __restrict__ W,
    const float* __restrict__ bias, float* __restrict__ C,
    int M, int N, int K, int relu, int accflag) {
    __shared__ __align__(16) float As[16][68];
    __shared__ __align__(16) float Ws[16][68];
    gemm_body(A, W, bias, C, M, N, K, relu, accflag, As, Ws);
}

__global__ void __launch_bounds__(256) k_gemmd(
    const float* __restrict__ A0, const float* __restrict__ A1,
    const float* __restrict__ W0, const float* __restrict__ W1,
    const float* __restrict__ b0, const float* __restrict__ b1,
    float* __restrict__ C0, float* __restrict__ C1, int M, int N, int K) {
    __shared__ __align__(16) float As[16][68];
    __shared__ __align__(16) float Ws[16][68];
    if (blockIdx.z == 0) gemm_body(A0, W0, b0, C0, M, N, K, 0, 0, As, Ws);
    else                 gemm_body(A1, W1, b1, C1, M, N, K, 0, 0, As, Ws);
}

extern "C" void kernel_launch(void* const* d_in, const int* in_sizes, int n_in,
                              void* d_out, int out_size) {
    const float* inputs     = (const float*)d_in[0];
    const float* slots_init = (const float*)d_in[1];
    const float* ln_f_w = (const float*)d_in[2];
    const float* ln_f_b = (const float*)d_in[3];
    const float* ln_s_w = (const float*)d_in[4];
    const float* ln_s_b = (const float*)d_in[5];
    const float* ln_p_w = (const float*)d_in[6];
    const float* ln_p_b = (const float*)d_in[7];
    const float* Wq  = (const float*)d_in[8];
    const float* Wk  = (const float*)d_in[9];
    const float* Wv  = (const float*)d_in[10];
    const float* W_ih = (const float*)d_in[11];
    const float* b_ih = (const float*)d_in[12];
    const float* W_hh = (const float*)d_in[13];
    const float* b_hh = (const float*)d_in[14];
    const float* W1 = (const float*)d_in[15];
    const float* b1 = (const float*)d_in[16];
    const float* W2 = (const float*)d_in[17];
    const float* b2 = (const float*)d_in[18];
    float* slots = (float*)d_out;

    unsigned short* p_xln;
    float *p_weff, *p_wgv, *p_wihv, *p_cb, *p_qe, *p_uhp, *p_rsp;
    float *p_updpre, *p_gi, *p_gh, *p_p, *p_h1;
    cudaGetSymbolAddress((void**)&p_xln, g_xln);
    cudaGetSymbolAddress((void**)&p_weff, g_weff);
    cudaGetSymbolAddress((void**)&p_wgv, g_wgv);
    cudaGetSymbolAddress((void**)&p_wihv, g_wihv);
    cudaGetSymbolAddress((void**)&p_cb, g_cb);
    cudaGetSymbolAddress((void**)&p_qe, g_qe);
    cudaGetSymbolAddress((void**)&p_uhp, g_uhpart);
    cudaGetSymbolAddress((void**)&p_rsp, g_rspart);
    cudaGetSymbolAddress((void**)&p_updpre, g_updpre);
    cudaGetSymbolAddress((void**)&p_gi, g_gi);
    cudaGetSymbolAddress((void**)&p_gh, g_gh);
    cudaGetSymbolAddress((void**)&p_p, g_p);
    cudaGetSymbolAddress((void**)&p_h1, g_h1);

    cudaFuncSetAttribute(k_attn, cudaFuncAttributeMaxDynamicSharedMemorySize, ATTN_SMEM);

    // launch order keeps k_attn at absolute launch #5 for the ncu -s 5 window
    cudaMemcpyAsync(slots, slots_init, (size_t)BB * KS * DD * sizeof(float),
                    cudaMemcpyDeviceToDevice);
    k_xln<<<BB * NN / 8, 256>>>(inputs, p_xln);
    k_wprep<<<DD + 1, DD>>>(Wk, Wq, ln_f_w, ln_f_b, ln_s_w, ln_s_b, p_weff, p_wgv);

    for (int it = 0; it < NITER; it++) {
        k_qeln<<<dim3(4, 11), 256>>>(slots, p_weff, p_wgv, ln_s_w, ln_s_b, p_qe, p_cb);
        k_attn<<<dim3(NTP, BB), 256, ATTN_SMEM>>>((const uint4*)p_xln, p_qe, p_cb,
                                                  p_uhp, p_rsp);
        k_fin<<<704, 256>>>(p_uhp, p_rsp, ln_f_w, ln_f_b, p_updpre);
        if (it == 0) k_wihv<<<3 * DD, DD>>>(W_ih, Wv, p_wihv);
        k_gemmd<<<dim3(12, 11, 2), 256>>>(p_updpre, slots, p_wihv, W_hh, b_ih, b_hh,
                                          p_gi, p_gh, 704, 768, 256);
        k_gruln<<<88, 256>>>(p_gi, p_gh, slots, ln_p_w, ln_p_b, p_p);
        k_gemm<<<dim3(8, 11), 256>>>(p_p, W1, b1, p_h1, 704, 512, 256, 1, 0);
        k_gemm<<<dim3(4, 11), 256>>>(p_h1, W2, b2, slots, 704, 256, 512, 0, 1);
    }
}

// round 5
// speedup vs baseline: 2.1215x; 1.3233x over previous
#include <cuda_runtime.h>
#include <cuda_bf16.h>
#include <math.h>
#include <stdint.h>

#define BB 64
#define NN 4096
#define DD 256
#define KS 11
#define HH 512
#define NITER 5
#define EPSF 1e-8f
#define LNEPS 1e-5f
#define SCALEF 0.0625f
#define TILE 128
#define TPB 4
#define NTP (NN/TILE/TPB)   // 8 partials per batch

typedef unsigned long long ull;

// ---------------- f32x2 packed helpers ----------------
__device__ __forceinline__ ull fma2(ull a, ull b, ull c) {
    ull d; asm("fma.rn.f32x2 %0, %1, %2, %3;" : "=l"(d) : "l"(a), "l"(b), "l"(c)); return d;
}
__device__ __forceinline__ ull dup2(float a) {
    unsigned int u = __float_as_uint(a);
    ull d; asm("mov.b64 %0, {%1, %1};" : "=l"(d) : "r"(u)); return d;
}
__device__ __forceinline__ void unpack2(ull v, float& x, float& y) {
    unsigned int a, b;
    asm("mov.b64 {%0, %1}, %2;" : "=r"(a), "=r"(b) : "l"(v));
    x = __uint_as_float(a); y = __uint_as_float(b);
}

// ---------------- mma / ldmatrix helpers ----------------
__device__ __forceinline__ uint32_t s2u(const void* p) {
    uint32_t a;
    asm("{.reg .u64 t; cvta.to.shared.u64 t, %1; cvt.u32.u64 %0, t;}" : "=r"(a) : "l"(p));
    return a;
}
__device__ __forceinline__ void ldsm4(unsigned& r0, unsigned& r1, unsigned& r2,
                                      unsigned& r3, uint32_t addr) {
    asm volatile("ldmatrix.sync.aligned.m8n8.x4.shared.b16 {%0,%1,%2,%3}, [%4];"
                 : "=r"(r0), "=r"(r1), "=r"(r2), "=r"(r3) : "r"(addr));
}
__device__ __forceinline__ void ldsm4t(unsigned& r0, unsigned& r1, unsigned& r2,
                                       unsigned& r3, uint32_t addr) {
    asm volatile("ldmatrix.sync.aligned.m8n8.x4.trans.shared.b16 {%0,%1,%2,%3}, [%4];"
                 : "=r"(r0), "=r"(r1), "=r"(r2), "=r"(r3) : "r"(addr));
}
__device__ __forceinline__ void mma16816(float* d, unsigned a0, unsigned a1, unsigned a2,
                                         unsigned a3, unsigned b0, unsigned b1) {
    asm volatile("mma.sync.aligned.m16n8k16.row.col.f32.bf16.bf16.f32 "
                 "{%0,%1,%2,%3}, {%4,%5,%6,%7}, {%8,%9}, {%0,%1,%2,%3};"
                 : "+f"(d[0]), "+f"(d[1]), "+f"(d[2]), "+f"(d[3])
                 : "r"(a0), "r"(a1), "r"(a2), "r"(a3), "r"(b0), "r"(b1));
}

// ---------------- scratch ----------------
__device__ __align__(16) unsigned short g_xln[BB*NN*DD];
__device__ float g_weff[DD*DD];
__device__ float g_wgv[DD + 2];
__device__ float g_wihv[3*DD*DD];
__device__ float g_cb[BB*KS];
__device__ float g_qe[BB*KS*DD];
__device__ float g_uhpart[BB*NTP*KS*DD];
__device__ float g_rspart[BB*NTP*KS];
__device__ float g_updpre[BB*KS*DD];
__device__ float g_gi[BB*KS*3*DD];
__device__ float g_gh[BB*KS*3*DD];
__device__ float g_p[BB*KS*DD];
__device__ float g_h1[BB*KS*HH];

// ---------------- xln = (x-mean)*rstd in bf16 (once) ----------------
__global__ void k_xln(const float* __restrict__ X, unsigned short* __restrict__ out) {
    int row = blockIdx.x * 8 + (threadIdx.x >> 5);
    int lane = threadIdx.x & 31;
    const float4* p = (const float4*)(X + (size_t)row * DD);
    float4 v0 = p[lane * 2], v1 = p[lane * 2 + 1];
    float s  = v0.x + v0.y + v0.z + v0.w + v1.x + v1.y + v1.z + v1.w;
    float s2 = v0.x*v0.x + v0.y*v0.y + v0.z*v0.z + v0.w*v0.w
             + v1.x*v1.x + v1.y*v1.y + v1.z*v1.z + v1.w*v1.w;
#pragma unroll
    for (int o = 16; o; o >>= 1) {
        s  += __shfl_xor_sync(0xffffffffu, s,  o);
        s2 += __shfl_xor_sync(0xffffffffu, s2, o);
    }
    float m = s * (1.0f / DD);
    float var = s2 * (1.0f / DD) - m * m;
    float r = rsqrtf(var + LNEPS);
    __nv_bfloat162 h0 = __float22bfloat162_rn(make_float2((v0.x-m)*r, (v0.y-m)*r));
    __nv_bfloat162 h1 = __float22bfloat162_rn(make_float2((v0.z-m)*r, (v0.w-m)*r));
    __nv_bfloat162 h2 = __float22bfloat162_rn(make_float2((v1.x-m)*r, (v1.y-m)*r));
    __nv_bfloat162 h3 = __float22bfloat162_rn(make_float2((v1.z-m)*r, (v1.w-m)*r));
    uint4 o;
    o.x = *(unsigned int*)&h0; o.y = *(unsigned int*)&h1;
    o.z = *(unsigned int*)&h2; o.w = *(unsigned int*)&h3;
    ((uint4*)(out + (size_t)row * DD))[lane] = o;
}

// ---------------- wprep ----------------
__global__ void k_wprep(const float* __restrict__ Wk, const float* __restrict__ Wq,
                        const float* __restrict__ wf, const float* __restrict__ bf,
                        const float* __restrict__ ws, const float* __restrict__ bs,
                        float* __restrict__ weff, float* __restrict__ wgv) {
    __shared__ float col[DD];
    __shared__ float red[8];
    int t = threadIdx.x;
    if (blockIdx.x < DD) {
        int d = blockIdx.x;
        col[t] = Wk[t * DD + d];
        __syncthreads();
        float acc = 0.f;
        for (int s = 0; s < DD; s++) acc = fmaf(col[s], Wq[s * DD + t], acc);
        weff[d * DD + t] = acc * wf[d];
    } else {
        float a = 0.f;
        for (int e = 0; e < DD; e++) a = fmaf(Wk[t * DD + e], bf[e], a);
        col[t] = a;
        __syncthreads();
        float gv = 0.f;
        for (int s = 0; s < DD; s++) gv = fmaf(Wq[s * DD + t], col[s], gv);
        float w = ws[t] * gv;
        wgv[t] = w;
        float c1 = w, c0 = bs[t] * gv;
        int lane = t & 31, warp = t >> 5;
#pragma unroll
        for (int o = 16; o; o >>= 1) {
            c1 += __shfl_xor_sync(0xffffffffu, c1, o);
            c0 += __shfl_xor_sync(0xffffffffu, c0, o);
        }
        __syncthreads();
        if (lane == 0) red[warp] = c1;
        __syncthreads();
        if (t == 0) {
            float s1 = 0.f;
            for (int i = 0; i < 8; i++) s1 += red[i];
            wgv[DD] = s1;
        }
        __syncthreads();
        if (lane == 0) red[warp] = c0;
        __syncthreads();
        if (t == 1) {
            float s0 = 0.f;
            for (int i = 0; i < 8; i++) s0 += red[i];
            wgv[DD + 1] = s0;
        }
    }
}

// ---------------- wihv[m][e] = sum_j W_ih[m,j] * Wv[j,e] (once) ----------------
__global__ void k_wihv(const float* __restrict__ Wih, const float* __restrict__ Wv,
                       float* __restrict__ out) {
    __shared__ float row[DD];
    int m = blockIdx.x, t = threadIdx.x;
    row[t] = Wih[m * DD + t];
    __syncthreads();
    float acc = 0.f;
#pragma unroll 4
    for (int j = 0; j < DD; j++) acc = fmaf(row[j], Wv[j * DD + t], acc);
    out[m * DD + t] = acc;
}

// ---------------- fused LN_s + cb + qe GEMM ----------------
__global__ void __launch_bounds__(256) k_qeln(
    const float* __restrict__ slots, const float* __restrict__ weff,
    const float* __restrict__ wgv, const float* __restrict__ lsw,
    const float* __restrict__ lsb, float* __restrict__ qe, float* __restrict__ cb) {
    __shared__ __align__(16) float As[16][68];
    __shared__ __align__(16) float Ws[16][68];
    __shared__ float ws[DD], bs[DD], rowm[64], rowr[64];
    int tid = threadIdx.x, lane = tid & 31, warp = tid >> 5;
    int m0 = blockIdx.y * 64, n0 = blockIdx.x * 64;
    ws[tid] = lsw[tid]; bs[tid] = lsb[tid];
    float C1 = wgv[DD], C0 = wgv[DD + 1];
    float4 wg0 = *(const float4*)(wgv + lane * 8);
    float4 wg1 = *(const float4*)(wgv + lane * 8 + 4);
#pragma unroll
    for (int rr = 0; rr < 8; rr++) {
        int rl = warp * 8 + rr, row = m0 + rl;
        const float4* p = (const float4*)(slots + (size_t)row * DD);
        float4 v0 = p[lane * 2], v1 = p[lane * 2 + 1];
        float s  = v0.x + v0.y + v0.z + v0.w + v1.x + v1.y + v1.z + v1.w;
        float s2 = v0.x*v0.x + v0.y*v0.y + v0.z*v0.z + v0.w*v0.w
                 + v1.x*v1.x + v1.y*v1.y + v1.z*v1.z + v1.w*v1.w;
        float s3 = v0.x*wg0.x + v0.y*wg0.y + v0.z*wg0.z + v0.w*wg0.w
                 + v1.x*wg1.x + v1.y*wg1.y + v1.z*wg1.z + v1.w*wg1.w;
#pragma unroll
        for (int o = 16; o; o >>= 1) {
            s  += __shfl_xor_sync(0xffffffffu, s,  o);
            s2 += __shfl_xor_sync(0xffffffffu, s2, o);
            s3 += __shfl_xor_sync(0xffffffffu, s3, o);
        }
        if (lane == 0) {
            float m = s * (1.0f / DD);
            float var = s2 * (1.0f / DD) - m * m;
            float r = rsqrtf(var + LNEPS);
            rowm[rl] = m; rowr[rl] = r;
            if (blockIdx.x == 0) cb[row] = r * s3 - r * m * C1 + C0;
        }
    }
    __syncthreads();
    int ml = (tid >> 5) * 8, nl = (tid & 31) * 2;
    ull acc[4][2];
#pragma unroll
    for (int i = 0; i < 4; i++) { acc[i][0] = 0ull; acc[i][1] = 0ull; }
    for (int k0 = 0; k0 < DD; k0 += 16) {
#pragma unroll
        for (int l = 0; l < 4; l++) {
            int idx = tid + l * 256;
            int r = idx >> 4, c = idx & 15;
            float v = slots[(size_t)(m0 + r) * DD + k0 + c];
            As[c][r] = (v - rowm[r]) * rowr[r] * ws[k0 + c] + bs[k0 + c];
            Ws[c][r] = weff[(size_t)(n0 + r) * DD + k0 + c];
        }
        __syncthreads();
#pragma unroll
        for (int kk = 0; kk < 16; kk++) {
            ulonglong2 a01 = *(const ulonglong2*)&As[kk][ml];
            ulonglong2 a23 = *(const ulonglong2*)&As[kk][ml + 4];
            float2 bv = *(const float2*)&Ws[kk][nl];
            ull b0 = dup2(bv.x), b1 = dup2(bv.y);
            acc[0][0] = fma2(a01.x, b0, acc[0][0]); acc[0][1] = fma2(a01.x, b1, acc[0][1]);
            acc[1][0] = fma2(a01.y, b0, acc[1][0]); acc[1][1] = fma2(a01.y, b1, acc[1][1]);
            acc[2][0] = fma2(a23.x, b0, acc[2][0]); acc[2][1] = fma2(a23.x, b1, acc[2][1]);
            acc[3][0] = fma2(a23.y, b0, acc[3][0]); acc[3][1] = fma2(a23.y, b1, acc[3][1]);
        }
        __syncthreads();
    }
#pragma unroll
    for (int mi = 0; mi < 4; mi++) {
        float r0c0, r1c0, r0c1, r1c1;
        unpack2(acc[mi][0], r0c0, r1c0);
        unpack2(acc[mi][1], r0c1, r1c1);
        int m = m0 + ml + mi * 2;
        *(float2*)&qe[(size_t)m * DD + n0 + nl] = make_float2(r0c0, r0c1);
        *(float2*)&qe[(size_t)(m + 1) * DD + n0 + nl] = make_float2(r1c0, r1c1);
    }
}

// ---------------- fused attention: tensor-core dots + accum ----------------
// smem layout (bytes):
//   Xs  [0, 67584)          128 rows x 264 bf16 (stride 528B)
//   Qp  [67584, 76032)      16 x 264 bf16 (stride 528B), slots 11-15 zero
//   Ls  [76032, 85248)      128 x 18 f32 logits
//   As  [85248, 91392)      128 x 24 bf16 attn (stride 48B), slots 11-15 zero
//   Us  [91392, 107776)     16 x 256 f32 block output
//   rsw [107776, 108032)    4 x 16 f32
//   cbs [108032, 108096)    16 f32
#define OFF_X   0
#define OFF_QP  67584
#define OFF_LS  76032
#define OFF_AS  85248
#define OFF_US  91392
#define OFF_RSW 107776
#define OFF_CBS 108032
#define ATTN_SMEM 108096

__global__ void __launch_bounds__(256, 2) k_attn(
    const uint4* __restrict__ xln, const float* __restrict__ qe,
    const float* __restrict__ cb, float* __restrict__ uhpart,
    float* __restrict__ rspart) {
    extern __shared__ char sm[];
    uint32_t sb = s2u(sm);
    float* Ls  = (float*)(sm + OFF_LS);
    float* Us  = (float*)(sm + OFF_US);
    float* rsw = (float*)(sm + OFF_RSW);
    float* cbs = (float*)(sm + OFF_CBS);

    int bx = blockIdx.x, b = blockIdx.y;
    int tid = threadIdx.x, lane = tid & 31, warp = tid >> 5;

    // stage Qp (bf16, padded slots zero) + cbs
    for (int i = tid; i < 16 * 128; i += 256) {
        int slot = i >> 7, dp = i & 127;
        unsigned v = 0;
        if (slot < KS) {
            float2 f = *(const float2*)(qe + ((size_t)b * KS + slot) * DD + dp * 2);
            __nv_bfloat162 h = __float22bfloat162_rn(f);
            v = *(unsigned*)&h;
        }
        *(unsigned*)(sm + OFF_QP + slot * 528 + dp * 4) = v;
    }
    if (tid < 16) cbs[tid] = (tid < KS) ? cb[b * KS + tid] : 0.f;

    float rsl[KS];
    float uacc[4][4];
#pragma unroll
    for (int i = 0; i < KS; i++) rsl[i] = 0.f;
#pragma unroll
    for (int i = 0; i < 4; i++)
#pragma unroll
        for (int j = 0; j < 4; j++) uacc[i][j] = 0.f;

    // per-lane ldmatrix base addresses
    int g8  = (lane & 8)  ? 1 : 0;
    int g16 = (lane & 16) ? 1 : 0;
    // dots A (X, non-trans): row = r0 + (lane&7) + g8*8, col16B = g16
    uint32_t dA = sb + OFF_X + ((warp * 16) + (lane & 7) + g8 * 8) * 528 + g16 * 16;
    // dots B (Qp, non-trans): n = (lane&7) + g16*8, koff16B = g8
    uint32_t dB = sb + OFF_QP + ((lane & 7) + g16 * 8) * 528 + g8 * 16;
    // accum A (As, trans): krow = (lane&7) + g16*8, col16B = g8
    uint32_t aA = sb + OFF_AS + ((lane & 7) + g16 * 8) * 48 + g8 * 16;
    // accum B (X, trans): krow = (lane&7) + g8*8, col16B = g16 (+ d-chunk)
    int d0w = warp * 32;
    uint32_t aB = sb + OFF_X + ((lane & 7) + g8 * 8) * 528 + d0w * 2 + g16 * 16;

    for (int t = 0; t < TPB; t++) {
        int row0 = (bx * TPB + t) * TILE;
        // stage X tile
        {
            uint4* Xs4 = (uint4*)sm;
            const uint4* src = xln + ((size_t)b * NN + row0) * (DD / 8);
            for (int idx = tid; idx < TILE * 32; idx += 256) {
                int r = idx >> 5, c = idx & 31;
                Xs4[r * 33 + c] = src[r * 32 + c];
            }
        }
        __syncthreads();

        // ---- dots via mma: warp covers rows [warp*16, +16), 16 slots ----
        {
            float D0[4] = {0.f, 0.f, 0.f, 0.f}, D1[4] = {0.f, 0.f, 0.f, 0.f};
#pragma unroll
            for (int kc = 0; kc < 16; kc++) {
                unsigned a0, a1, a2, a3, b0, b1, b2, b3;
                ldsm4(a0, a1, a2, a3, dA + kc * 32);
                ldsm4(b0, b1, b2, b3, dB + kc * 32);
                mma16816(D0, a0, a1, a2, a3, b0, b1);
                mma16816(D1, a0, a1, a2, a3, b2, b3);
            }
            int lr = warp * 16 + (lane >> 2), lc = (lane & 3) * 2;
            *(float2*)(Ls + lr * 18 + lc)           = make_float2(D0[0], D0[1]);
            *(float2*)(Ls + (lr + 8) * 18 + lc)     = make_float2(D0[2], D0[3]);
            *(float2*)(Ls + lr * 18 + 8 + lc)       = make_float2(D1[0], D1[1]);
            *(float2*)(Ls + (lr + 8) * 18 + 8 + lc) = make_float2(D1[2], D1[3]);
        }
        __syncthreads();

        // ---- softmax: thread-per-row (threads 0-127) ----
        if (tid < TILE) {
            const float* lr = Ls + tid * 18;
            float l[KS];
#pragma unroll
            for (int i = 0; i < KS; i++) l[i] = (lr[i] + cbs[i]) * SCALEF;
            float mx = l[0];
#pragma unroll
            for (int i = 1; i < KS; i++) mx = fmaxf(mx, l[i]);
            float se = 0.f;
#pragma unroll
            for (int i = 0; i < KS; i++) { float e = __expf(l[i] - mx); l[i] = e; se += e; }
            float inv = __fdividef(1.0f, se);
            float a16[16];
#pragma unroll
            for (int i = 0; i < 16; i++) a16[i] = 0.f;
#pragma unroll
            for (int i = 0; i < KS; i++) {
                float a = fmaf(l[i], inv, EPSF);
                a16[i] = a; rsl[i] += a;
            }
            unsigned* dst = (unsigned*)(sm + OFF_AS + tid * 48);
#pragma unroll
            for (int p = 0; p < 8; p++) {
                __nv_bfloat162 h = __float22bfloat162_rn(make_float2(a16[2*p], a16[2*p+1]));
                dst[p] = *(unsigned*)&h;
            }
        }
        __syncthreads();

        // ---- accum via mma: U[16 slots x 32 d per warp] += As^T @ X ----
        {
#pragma unroll
            for (int kr = 0; kr < 8; kr++) {
                unsigned p0, p1, p2, p3, x0, x1, x2, x3, y0, y1, y2, y3;
                ldsm4t(p0, p1, p2, p3, aA + kr * (16 * 48));
                ldsm4t(x0, x1, x2, x3, aB + kr * (16 * 528));
                ldsm4t(y0, y1, y2, y3, aB + kr * (16 * 528) + 32);
                mma16816(uacc[0], p0, p1, p2, p3, x0, x1);
                mma16816(uacc[1], p0, p1, p2, p3, x2, x3);
                mma16816(uacc[2], p0, p1, p2, p3, y0, y1);
                mma16816(uacc[3], p0, p1, p2, p3, y2, y3);
            }
        }
        __syncthreads();
    }

    // ---- write U fragments to Us ----
    {
        int slot = lane >> 2, dp = (lane & 3) * 2;
#pragma unroll
        for (int nt = 0; nt < 4; nt++) {
            int d = d0w + nt * 8 + dp;
            *(float2*)(Us + slot * 256 + d)       = make_float2(uacc[nt][0], uacc[nt][1]);
            *(float2*)(Us + (slot + 8) * 256 + d) = make_float2(uacc[nt][2], uacc[nt][3]);
        }
    }
    // ---- row-sum reduce ----
    if (tid < TILE) {
#pragma unroll
        for (int i = 0; i < KS; i++) {
#pragma unroll
            for (int o = 16; o; o >>= 1) rsl[i] += __shfl_xor_sync(0xffffffffu, rsl[i], o);
        }
        if (lane == 0) {
#pragma unroll
            for (int i = 0; i < KS; i++) rsw[warp * 16 + i] = rsl[i];
        }
    }
    __syncthreads();

    // ---- write partials ----
    for (int i = tid; i < KS * DD; i += 256)
        uhpart[((size_t)(b * NTP + bx)) * KS * DD + i] = Us[i];
    if (tid < KS)
        rspart[(size_t)(b * NTP + bx) * KS + tid] =
            rsw[tid] + rsw[16 + tid] + rsw[32 + tid] + rsw[48 + tid];
}

// ---------------- finalize ----------------
__global__ void k_fin(const float* __restrict__ uhpart, const float* __restrict__ rspart,
                      const float* __restrict__ wf, const float* __restrict__ bf,
                      float* __restrict__ out) {
    int m = blockIdx.x, d = threadIdx.x;
    int b = m / KS, i = m % KS;
    const float* up = uhpart + ((size_t)b * NTP) * KS * DD + i * DD + d;
    const float* rp = rspart + b * NTP * KS + i;
    float s = 0.f, r = 0.f;
#pragma unroll
    for (int t = 0; t < NTP; t++) { s += up[(size_t)t * KS * DD]; r += rp[t * KS]; }
    out[(size_t)m * DD + d] = __fdividef(wf[d] * s, r) + bf[d];
}

// ---------------- fused GRU + LN_p: warp per row ----------------
__global__ void k_gruln(const float* __restrict__ gi, const float* __restrict__ gh,
                        float* __restrict__ slots, const float* __restrict__ wp,
                        const float* __restrict__ bp, float* __restrict__ p) {
    int m = blockIdx.x * 8 + (threadIdx.x >> 5);
    int lane = threadIdx.x & 31;
    int d0 = lane * 8;
    const float* gim = gi + (size_t)m * 3 * DD;
    const float* ghm = gh + (size_t)m * 3 * DD;
    float ir[8], iz[8], in_[8], hr[8], hz[8], hn[8], sp[8], v[8];
    *(float4*)ir   = *(const float4*)(gim + d0);       *(float4*)(ir+4)  = *(const float4*)(gim + d0 + 4);
    *(float4*)iz   = *(const float4*)(gim + DD + d0);  *(float4*)(iz+4)  = *(const float4*)(gim + DD + d0 + 4);
    *(float4*)in_  = *(const float4*)(gim + 2*DD + d0);*(float4*)(in_+4) = *(const float4*)(gim + 2*DD + d0 + 4);
    *(float4*)hr   = *(const float4*)(ghm + d0);       *(float4*)(hr+4)  = *(const float4*)(ghm + d0 + 4);
    *(float4*)hz   = *(const float4*)(ghm + DD + d0);  *(float4*)(hz+4)  = *(const float4*)(ghm + DD + d0 + 4);
    *(float4*)hn   = *(const float4*)(ghm + 2*DD + d0);*(float4*)(hn+4)  = *(const float4*)(ghm + 2*DD + d0 + 4);
    *(float4*)sp   = *(const float4*)(slots + (size_t)m*DD + d0);
    *(float4*)(sp+4) = *(const float4*)(slots + (size_t)m*DD + d0 + 4);
    float s = 0.f, s2 = 0.f;
#pragma unroll
    for (int j = 0; j < 8; j++) {
        float r = 1.0f / (1.0f + __expf(-(ir[j] + hr[j])));
        float z = 1.0f / (1.0f + __expf(-(iz[j] + hz[j])));
        float n = tanhf(in_[j] + r * hn[j]);
        float vv = (1.0f - z) * n + z * sp[j];
        v[j] = vv; s += vv; s2 += vv * vv;
    }
#pragma unroll
    for (int o = 16; o; o >>= 1) {
        s  += __shfl_xor_sync(0xffffffffu, s,  o);
        s2 += __shfl_xor_sync(0xffffffffu, s2, o);
    }
    float mm = s * (1.0f / DD);
    float var = s2 * (1.0f / DD) - mm * mm;
    float rr = rsqrtf(var + LNEPS);
    *(float4*)(slots + (size_t)m*DD + d0)     = *(float4*)v;
    *(float4*)(slots + (size_t)m*DD + d0 + 4) = *(float4*)(v+4);
    float w_[8], b_[8], pv[8];
    *(float4*)w_ = *(const float4*)(wp + d0); *(float4*)(w_+4) = *(const float4*)(wp + d0 + 4);
    *(float4*)b_ = *(const float4*)(bp + d0); *(float4*)(b_+4) = *(const float4*)(bp + d0 + 4);
#pragma unroll
    for (int j = 0; j < 8; j++) pv[j] = (v[j] - mm) * rr * w_[j] + b_[j];
    *(float4*)(p + (size_t)m*DD + d0)     = *(float4*)pv;
    *(float4*)(p + (size_t)m*DD + d0 + 4) = *(float4*)(pv+4);
}

// ---------------- SGEMM body ----------------
__device__ __forceinline__ void gemm_body(
    const float* __restrict__ A, const float* __restrict__ W,
    const float* __restrict__ bias, float* __restrict__ C,
    int M, int N, int K, int relu, int accflag,
    float (*As)[68], float (*Ws)[68]) {
    int tid = threadIdx.x;
    int m0 = blockIdx.y * 64, n0 = blockIdx.x * 64;
    int ml = (tid >> 5) * 8;
    int nl = (tid & 31) * 2;
    ull acc[4][2];
#pragma unroll
    for (int i = 0; i < 4; i++) { acc[i][0] = 0ull; acc[i][1] = 0ull; }

    for (int k0 = 0; k0 < K; k0 += 16) {
#pragma unroll
        for (int l = 0; l < 4; l++) {
            int idx = tid + l * 256;
            int r = idx >> 4, c = idx & 15;
            As[c][r] = A[(size_t)(m0 + r) * K + k0 + c];
            Ws[c][r] = W[(size_t)(n0 + r) * K + k0 + c];
        }
        __syncthreads();
#pragma unroll
        for (int kk = 0; kk < 16; kk++) {
            ulonglong2 a01 = *(const ulonglong2*)&As[kk][ml];
            ulonglong2 a23 = *(const ulonglong2*)&As[kk][ml + 4];
            float2 bv = *(const float2*)&Ws[kk][nl];
            ull b0 = dup2(bv.x), b1 = dup2(bv.y);
            acc[0][0] = fma2(a01.x, b0, acc[0][0]); acc[0][1] = fma2(a01.x, b1, acc[0][1]);
            acc[1][0] = fma2(a01.y, b0, acc[1][0]); acc[1][1] = fma2(a01.y, b1, acc[1][1]);
            acc[2][0] = fma2(a23.x, b0, acc[2][0]); acc[2][1] = fma2(a23.x, b1, acc[2][1]);
            acc[3][0] = fma2(a23.y, b0, acc[3][0]); acc[3][1] = fma2(a23.y, b1, acc[3][1]);
        }
        __syncthreads();
    }
    float bb0 = bias ? bias[n0 + nl] : 0.f;
    float bb1 = bias ? bias[n0 + nl + 1] : 0.f;
#pragma unroll
    for (int mi = 0; mi < 4; mi++) {
        float r0c0, r1c0, r0c1, r1c1;
        unpack2(acc[mi][0], r0c0, r1c0);
        unpack2(acc[mi][1], r0c1, r1c1);
        int m = m0 + ml + mi * 2;
        float2 v0 = make_float2(r0c0 + bb0, r0c1 + bb1);
        float2 v1 = make_float2(r1c0 + bb0, r1c1 + bb1);
        if (relu) {
            v0.x = fmaxf(v0.x, 0.f); v0.y = fmaxf(v0.y, 0.f);
            v1.x = fmaxf(v1.x, 0.f); v1.y = fmaxf(v1.y, 0.f);
        }
        float2* p0 = (float2*)&C[(size_t)m * N + n0 + nl];
        float2* p1 = (float2*)&C[(size_t)(m + 1) * N + n0 + nl];
        if (accflag) {
            float2 t0 = *p0, t1 = *p1;
            v0.x += t0.x; v0.y += t0.y; v1.x += t1.x; v1.y += t1.y;
        }
        *p0 = v0; *p1 = v1;
    }
}

__global__ void __launch_bounds__(256) k_gemm(
    const float* __restrict__ A, const float* __restrict__ W,
    const float* __restrict__ bias, float* __restrict__ C,
    int M, int N, int K, int relu, int accflag) {
    __shared__ __align__(16) float As[16][68];
    __shared__ __align__(16) float Ws[16][68];
    gemm_body(A, W, bias, C, M, N, K, relu, accflag, As, Ws);
}

__global__ void __launch_bounds__(256) k_gemmd(
    const float* __restrict__ A0, const float* __restrict__ A1,
    const float* __restrict__ W0, const float* __restrict__ W1,
    const float* __restrict__ b0, const float* __restrict__ b1,
    float* __restrict__ C0, float* __restrict__ C1, int M, int N, int K) {
    __shared__ __align__(16) float As[16][68];
    __shared__ __align__(16) float Ws[16][68];
    if (blockIdx.z == 0) gemm_body(A0, W0, b0, C0, M, N, K, 0, 0, As, Ws);
    else                 gemm_body(A1, W1, b1, C1, M, N, K, 0, 0, As, Ws);
}

extern "C" void kernel_launch(void* const* d_in, const int* in_sizes, int n_in,
                              void* d_out, int out_size) {
    const float* inputs     = (const float*)d_in[0];
    const float* slots_init = (const float*)d_in[1];
    const float* ln_f_w = (const float*)d_in[2];
    const float* ln_f_b = (const float*)d_in[3];
    const float* ln_s_w = (const float*)d_in[4];
    const float* ln_s_b = (const float*)d_in[5];
    const float* ln_p_w = (const float*)d_in[6];
    const float* ln_p_b = (const float*)d_in[7];
    const float* Wq  = (const float*)d_in[8];
    const float* Wk  = (const float*)d_in[9];
    const float* Wv  = (const float*)d_in[10];
    const float* W_ih = (const float*)d_in[11];
    const float* b_ih = (const float*)d_in[12];
    const float* W_hh = (const float*)d_in[13];
    const float* b_hh = (const float*)d_in[14];
    const float* W1 = (const float*)d_in[15];
    const float* b1 = (const float*)d_in[16];
    const float* W2 = (const float*)d_in[17];
    const float* b2 = (const float*)d_in[18];
    float* slots = (float*)d_out;

    unsigned short* p_xln;
    float *p_weff, *p_wgv, *p_wihv, *p_cb, *p_qe, *p_uhp, *p_rsp;
    float *p_updpre, *p_gi, *p_gh, *p_p, *p_h1;
    cudaGetSymbolAddress((void**)&p_xln, g_xln);
    cudaGetSymbolAddress((void**)&p_weff, g_weff);
    cudaGetSymbolAddress((void**)&p_wgv, g_wgv);
    cudaGetSymbolAddress((void**)&p_wihv, g_wihv);
    cudaGetSymbolAddress((void**)&p_cb, g_cb);
    cudaGetSymbolAddress((void**)&p_qe, g_qe);
    cudaGetSymbolAddress((void**)&p_uhp, g_uhpart);
    cudaGetSymbolAddress((void**)&p_rsp, g_rspart);
    cudaGetSymbolAddress((void**)&p_updpre, g_updpre);
    cudaGetSymbolAddress((void**)&p_gi, g_gi);
    cudaGetSymbolAddress((void**)&p_gh, g_gh);
    cudaGetSymbolAddress((void**)&p_p, g_p);
    cudaGetSymbolAddress((void**)&p_h1, g_h1);

    cudaFuncSetAttribute(k_attn, cudaFuncAttributeMaxDynamicSharedMemorySize, ATTN_SMEM);

    // launch order keeps k_attn at absolute launch #5 for the ncu -s 5 window
    cudaMemcpyAsync(slots, slots_init, (size_t)BB * KS * DD * sizeof(float),
                    cudaMemcpyDeviceToDevice);
    k_xln<<<BB * NN / 8, 256>>>(inputs, p_xln);
    k_wprep<<<DD + 1, DD>>>(Wk, Wq, ln_f_w, ln_f_b, ln_s_w, ln_s_b, p_weff, p_wgv);

    for (int it = 0; it < NITER; it++) {
        k_qeln<<<dim3(4, 11), 256>>>(slots, p_weff, p_wgv, ln_s_w, ln_s_b, p_qe, p_cb);
        k_attn<<<dim3(NTP, BB), 256, ATTN_SMEM>>>((const uint4*)p_xln, p_qe, p_cb,
                                                  p_uhp, p_rsp);
        k_fin<<<704, 256>>>(p_uhp, p_rsp, ln_f_w, ln_f_b, p_updpre);
        if (it == 0) k_wihv<<<3 * DD, DD>>>(W_ih, Wv, p_wihv);
        k_gemmd<<<dim3(12, 11, 2), 256>>>(p_updpre, slots, p_wihv, W_hh, b_ih, b_hh,
                                          p_gi, p_gh, 704, 768, 256);
        k_gruln<<<88, 256>>>(p_gi, p_gh, slots, ln_p_w, ln_p_b, p_p);
        k_gemm<<<dim3(8, 11), 256>>>(p_p, W1, b1, p_h1, 704, 512, 256, 1, 0);
        k_gemm<<<dim3(4, 11), 256>>>(p_h1, W2, b2, slots, 704, 256, 512, 0, 1);
    }
}

// round 6
// speedup vs baseline: 2.3018x; 1.0850x over previous
#include <cuda_runtime.h>
#include <cuda_bf16.h>
#include <math.h>
#include <stdint.h>

#define BB 64
#define NN 4096
#define DD 256
#define KS 11
#define HH 512
#define NITER 5
#define EPSF 1e-8f
#define LNEPS 1e-5f
#define SCALEF 0.0625f
#define TILE 128
#define TPB 8
#define NTP (NN/TILE/TPB)   // 4 partials per batch

typedef unsigned long long ull;

// ---------------- f32x2 packed helpers ----------------
__device__ __forceinline__ ull fma2(ull a, ull b, ull c) {
    ull d; asm("fma.rn.f32x2 %0, %1, %2, %3;" : "=l"(d) : "l"(a), "l"(b), "l"(c)); return d;
}
__device__ __forceinline__ ull dup2(float a) {
    unsigned int u = __float_as_uint(a);
    ull d; asm("mov.b64 %0, {%1, %1};" : "=l"(d) : "r"(u)); return d;
}
__device__ __forceinline__ void unpack2(ull v, float& x, float& y) {
    unsigned int a, b;
    asm("mov.b64 {%0, %1}, %2;" : "=r"(a), "=r"(b) : "l"(v));
    x = __uint_as_float(a); y = __uint_as_float(b);
}

// ---------------- mma / ldmatrix / cp.async helpers ----------------
__device__ __forceinline__ uint32_t s2u(const void* p) {
    uint32_t a;
    asm("{.reg .u64 t; cvta.to.shared.u64 t, %1; cvt.u32.u64 %0, t;}" : "=r"(a) : "l"(p));
    return a;
}
__device__ __forceinline__ void ldsm4(unsigned& r0, unsigned& r1, unsigned& r2,
                                      unsigned& r3, uint32_t addr) {
    asm volatile("ldmatrix.sync.aligned.m8n8.x4.shared.b16 {%0,%1,%2,%3}, [%4];"
                 : "=r"(r0), "=r"(r1), "=r"(r2), "=r"(r3) : "r"(addr));
}
__device__ __forceinline__ void ldsm4t(unsigned& r0, unsigned& r1, unsigned& r2,
                                       unsigned& r3, uint32_t addr) {
    asm volatile("ldmatrix.sync.aligned.m8n8.x4.trans.shared.b16 {%0,%1,%2,%3}, [%4];"
                 : "=r"(r0), "=r"(r1), "=r"(r2), "=r"(r3) : "r"(addr));
}
__device__ __forceinline__ void mma16816(float* d, unsigned a0, unsigned a1, unsigned a2,
                                         unsigned a3, unsigned b0, unsigned b1) {
    asm volatile("mma.sync.aligned.m16n8k16.row.col.f32.bf16.bf16.f32 "
                 "{%0,%1,%2,%3}, {%4,%5,%6,%7}, {%8,%9}, {%0,%1,%2,%3};"
                 : "+f"(d[0]), "+f"(d[1]), "+f"(d[2]), "+f"(d[3])
                 : "r"(a0), "r"(a1), "r"(a2), "r"(a3), "r"(b0), "r"(b1));
}
__device__ __forceinline__ void cpasync16(uint32_t saddr, const void* gaddr) {
    asm volatile("cp.async.cg.shared.global [%0], [%1], 16;" :: "r"(saddr), "l"(gaddr));
}
__device__ __forceinline__ void cpcommit() {
    asm volatile("cp.async.commit_group;");
}
template <int N>
__device__ __forceinline__ void cpwait() {
    asm volatile("cp.async.wait_group %0;" :: "n"(N));
}

// ---------------- scratch ----------------
__device__ __align__(16) unsigned short g_xln[BB*NN*DD];
__device__ float g_weff[DD*DD];
__device__ float g_wgv[DD + 2];
__device__ float g_wihv[3*DD*DD];
__device__ float g_cb[BB*KS];
__device__ float g_qe[BB*KS*DD];
__device__ float g_uhpart[BB*NTP*KS*DD];
__device__ float g_rspart[BB*NTP*KS];
__device__ float g_updpre[BB*KS*DD];
__device__ float g_gi[BB*KS*3*DD];
__device__ float g_gh[BB*KS*3*DD];
__device__ float g_p[BB*KS*DD];
__device__ float g_h1[BB*KS*HH];

// ---------------- xln = (x-mean)*rstd in bf16 (once) ----------------
__global__ void k_xln(const float* __restrict__ X, unsigned short* __restrict__ out) {
    int row = blockIdx.x * 8 + (threadIdx.x >> 5);
    int lane = threadIdx.x & 31;
    const float4* p = (const float4*)(X + (size_t)row * DD);
    float4 v0 = p[lane * 2], v1 = p[lane * 2 + 1];
    float s  = v0.x + v0.y + v0.z + v0.w + v1.x + v1.y + v1.z + v1.w;
    float s2 = v0.x*v0.x + v0.y*v0.y + v0.z*v0.z + v0.w*v0.w
             + v1.x*v1.x + v1.y*v1.y + v1.z*v1.z + v1.w*v1.w;
#pragma unroll
    for (int o = 16; o; o >>= 1) {
        s  += __shfl_xor_sync(0xffffffffu, s,  o);
        s2 += __shfl_xor_sync(0xffffffffu, s2, o);
    }
    float m = s * (1.0f / DD);
    float var = s2 * (1.0f / DD) - m * m;
    float r = rsqrtf(var + LNEPS);
    __nv_bfloat162 h0 = __float22bfloat162_rn(make_float2((v0.x-m)*r, (v0.y-m)*r));
    __nv_bfloat162 h1 = __float22bfloat162_rn(make_float2((v0.z-m)*r, (v0.w-m)*r));
    __nv_bfloat162 h2 = __float22bfloat162_rn(make_float2((v1.x-m)*r, (v1.y-m)*r));
    __nv_bfloat162 h3 = __float22bfloat162_rn(make_float2((v1.z-m)*r, (v1.w-m)*r));
    uint4 o;
    o.x = *(unsigned int*)&h0; o.y = *(unsigned int*)&h1;
    o.z = *(unsigned int*)&h2; o.w = *(unsigned int*)&h3;
    ((uint4*)(out + (size_t)row * DD))[lane] = o;
}

// ---------------- wprep ----------------
__global__ void k_wprep(const float* __restrict__ Wk, const float* __restrict__ Wq,
                        const float* __restrict__ wf, const float* __restrict__ bf,
                        const float* __restrict__ ws, const float* __restrict__ bs,
                        float* __restrict__ weff, float* __restrict__ wgv) {
    __shared__ float col[DD];
    __shared__ float red[8];
    int t = threadIdx.x;
    if (blockIdx.x < DD) {
        int d = blockIdx.x;
        col[t] = Wk[t * DD + d];
        __syncthreads();
        float acc = 0.f;
        for (int s = 0; s < DD; s++) acc = fmaf(col[s], Wq[s * DD + t], acc);
        weff[d * DD + t] = acc * wf[d];
    } else {
        float a = 0.f;
        for (int e = 0; e < DD; e++) a = fmaf(Wk[t * DD + e], bf[e], a);
        col[t] = a;
        __syncthreads();
        float gv = 0.f;
        for (int s = 0; s < DD; s++) gv = fmaf(Wq[s * DD + t], col[s], gv);
        float w = ws[t] * gv;
        wgv[t] = w;
        float c1 = w, c0 = bs[t] * gv;
        int lane = t & 31, warp = t >> 5;
#pragma unroll
        for (int o = 16; o; o >>= 1) {
            c1 += __shfl_xor_sync(0xffffffffu, c1, o);
            c0 += __shfl_xor_sync(0xffffffffu, c0, o);
        }
        __syncthreads();
        if (lane == 0) red[warp] = c1;
        __syncthreads();
        if (t == 0) {
            float s1 = 0.f;
            for (int i = 0; i < 8; i++) s1 += red[i];
            wgv[DD] = s1;
        }
        __syncthreads();
        if (lane == 0) red[warp] = c0;
        __syncthreads();
        if (t == 1) {
            float s0 = 0.f;
            for (int i = 0; i < 8; i++) s0 += red[i];
            wgv[DD + 1] = s0;
        }
    }
}

// ---------------- wihv[m][e] = sum_j W_ih[m,j] * Wv[j,e] (once) ----------------
__global__ void k_wihv(const float* __restrict__ Wih, const float* __restrict__ Wv,
                       float* __restrict__ out) {
    __shared__ float row[DD];
    int m = blockIdx.x, t = threadIdx.x;
    row[t] = Wih[m * DD + t];
    __syncthreads();
    float acc = 0.f;
#pragma unroll 4
    for (int j = 0; j < DD; j++) acc = fmaf(row[j], Wv[j * DD + t], acc);
    out[m * DD + t] = acc;
}

// ---------------- fused LN_s + cb + qe GEMM ----------------
__global__ void __launch_bounds__(256) k_qeln(
    const float* __restrict__ slots, const float* __restrict__ weff,
    const float* __restrict__ wgv, const float* __restrict__ lsw,
    const float* __restrict__ lsb, float* __restrict__ qe, float* __restrict__ cb) {
    __shared__ __align__(16) float As[16][68];
    __shared__ __align__(16) float Ws[16][68];
    __shared__ float ws[DD], bs[DD], rowm[64], rowr[64];
    int tid = threadIdx.x, lane = tid & 31, warp = tid >> 5;
    int m0 = blockIdx.y * 64, n0 = blockIdx.x * 64;
    ws[tid] = lsw[tid]; bs[tid] = lsb[tid];
    float C1 = wgv[DD], C0 = wgv[DD + 1];
    float4 wg0 = *(const float4*)(wgv + lane * 8);
    float4 wg1 = *(const float4*)(wgv + lane * 8 + 4);
#pragma unroll
    for (int rr = 0; rr < 8; rr++) {
        int rl = warp * 8 + rr, row = m0 + rl;
        const float4* p = (const float4*)(slots + (size_t)row * DD);
        float4 v0 = p[lane * 2], v1 = p[lane * 2 + 1];
        float s  = v0.x + v0.y + v0.z + v0.w + v1.x + v1.y + v1.z + v1.w;
        float s2 = v0.x*v0.x + v0.y*v0.y + v0.z*v0.z + v0.w*v0.w
                 + v1.x*v1.x + v1.y*v1.y + v1.z*v1.z + v1.w*v1.w;
        float s3 = v0.x*wg0.x + v0.y*wg0.y + v0.z*wg0.z + v0.w*wg0.w
                 + v1.x*wg1.x + v1.y*wg1.y + v1.z*wg1.z + v1.w*wg1.w;
#pragma unroll
        for (int o = 16; o; o >>= 1) {
            s  += __shfl_xor_sync(0xffffffffu, s,  o);
            s2 += __shfl_xor_sync(0xffffffffu, s2, o);
            s3 += __shfl_xor_sync(0xffffffffu, s3, o);
        }
        if (lane == 0) {
            float m = s * (1.0f / DD);
            float var = s2 * (1.0f / DD) - m * m;
            float r = rsqrtf(var + LNEPS);
            rowm[rl] = m; rowr[rl] = r;
            if (blockIdx.x == 0) cb[row] = r * s3 - r * m * C1 + C0;
        }
    }
    __syncthreads();
    int ml = (tid >> 5) * 8, nl = (tid & 31) * 2;
    ull acc[4][2];
#pragma unroll
    for (int i = 0; i < 4; i++) { acc[i][0] = 0ull; acc[i][1] = 0ull; }
    for (int k0 = 0; k0 < DD; k0 += 16) {
#pragma unroll
        for (int l = 0; l < 4; l++) {
            int idx = tid + l * 256;
            int r = idx >> 4, c = idx & 15;
            float v = slots[(size_t)(m0 + r) * DD + k0 + c];
            As[c][r] = (v - rowm[r]) * rowr[r] * ws[k0 + c] + bs[k0 + c];
            Ws[c][r] = weff[(size_t)(n0 + r) * DD + k0 + c];
        }
        __syncthreads();
#pragma unroll
        for (int kk = 0; kk < 16; kk++) {
            ulonglong2 a01 = *(const ulonglong2*)&As[kk][ml];
            ulonglong2 a23 = *(const ulonglong2*)&As[kk][ml + 4];
            float2 bv = *(const float2*)&Ws[kk][nl];
            ull b0 = dup2(bv.x), b1 = dup2(bv.y);
            acc[0][0] = fma2(a01.x, b0, acc[0][0]); acc[0][1] = fma2(a01.x, b1, acc[0][1]);
            acc[1][0] = fma2(a01.y, b0, acc[1][0]); acc[1][1] = fma2(a01.y, b1, acc[1][1]);
            acc[2][0] = fma2(a23.x, b0, acc[2][0]); acc[2][1] = fma2(a23.x, b1, acc[2][1]);
            acc[3][0] = fma2(a23.y, b0, acc[3][0]); acc[3][1] = fma2(a23.y, b1, acc[3][1]);
        }
        __syncthreads();
    }
#pragma unroll
    for (int mi = 0; mi < 4; mi++) {
        float r0c0, r1c0, r0c1, r1c1;
        unpack2(acc[mi][0], r0c0, r1c0);
        unpack2(acc[mi][1], r0c1, r1c1);
        int m = m0 + ml + mi * 2;
        *(float2*)&qe[(size_t)m * DD + n0 + nl] = make_float2(r0c0, r0c1);
        *(float2*)&qe[(size_t)(m + 1) * DD + n0 + nl] = make_float2(r1c0, r1c1);
    }
}

// ---------------- fused attention: tensor-core + cp.async double buffer ----------------
// smem layout (bytes):
//   X0  [0, 67584)          128 x 264 bf16 (stride 528B), buffer 0
//   X1  [67584, 135168)     buffer 1
//   Qp  [135168, 143616)    16 x 264 bf16 (stride 528B), slots 11-15 zero
//   Ls  [143616, 152832)    128 x 18 f32 logits
//   As  [152832, 158976)    128 x 24 bf16 attn (stride 48B)
//   rsw [158976, 159232)    4 x 16 f32
//   cbs [159232, 159296)    16 f32
#define OFF_X0  0
#define OFF_X1  67584
#define OFF_QP  135168
#define OFF_LS  143616
#define OFF_AS  152832
#define OFF_RSW 158976
#define OFF_CBS 159232
#define ATTN_SMEM 159296

__global__ void __launch_bounds__(256, 1) k_attn(
    const uint4* __restrict__ xln, const float* __restrict__ qe,
    const float* __restrict__ cb, float* __restrict__ uhpart,
    float* __restrict__ rspart) {
    extern __shared__ char sm[];
    uint32_t sb = s2u(sm);
    float* Ls  = (float*)(sm + OFF_LS);
    float* rsw = (float*)(sm + OFF_RSW);
    float* cbs = (float*)(sm + OFF_CBS);

    int bx = blockIdx.x, b = blockIdx.y;
    int tid = threadIdx.x, lane = tid & 31, warp = tid >> 5;

    // stage Qp (bf16, padded slots zero) + cbs
    for (int i = tid; i < 16 * 128; i += 256) {
        int slot = i >> 7, dp = i & 127;
        unsigned v = 0;
        if (slot < KS) {
            float2 f = *(const float2*)(qe + ((size_t)b * KS + slot) * DD + dp * 2);
            __nv_bfloat162 h = __float22bfloat162_rn(f);
            v = *(unsigned*)&h;
        }
        *(unsigned*)(sm + OFF_QP + slot * 528 + dp * 4) = v;
    }
    if (tid < 16) cbs[tid] = (tid < KS) ? cb[b * KS + tid] : 0.f;

    // cp.async staging: thread covers row (tid>>4)*? -> 16 chunks each
    // per tile: 128 rows x 32 chunks(16B) = 4096 ops / 256 thr = 16 per thread
    int srow = tid >> 1;             // rows handled: srow, srow+... pattern below
    // simple mapping: idx = tid + k*256; row = idx>>5, chunk = idx&31
    const uint4* Xg = xln + (size_t)b * NN * (DD / 8);

    // prologue: prefetch tile 0 into buffer 0
    {
        int row0 = bx * TPB * TILE;
#pragma unroll
        for (int k = 0; k < 16; k++) {
            int idx = tid + k * 256;
            int r = idx >> 5, c = idx & 31;
            cpasync16(sb + OFF_X0 + r * 528 + c * 16,
                      (const void*)(Xg + (size_t)(row0 + r) * 32 + c));
        }
        cpcommit();
    }

    float rsl[KS];
    float uacc[4][4];
#pragma unroll
    for (int i = 0; i < KS; i++) rsl[i] = 0.f;
#pragma unroll
    for (int i = 0; i < 4; i++)
#pragma unroll
        for (int j = 0; j < 4; j++) uacc[i][j] = 0.f;

    int g8  = (lane & 8)  ? 1 : 0;
    int g16 = (lane & 16) ? 1 : 0;
    uint32_t dA_off = ((warp * 16) + (lane & 7) + g8 * 8) * 528 + g16 * 16;
    uint32_t dB = sb + OFF_QP + ((lane & 7) + g16 * 8) * 528 + g8 * 16;
    uint32_t aA = sb + OFF_AS + ((lane & 7) + g16 * 8) * 48 + g8 * 16;
    int d0w = warp * 32;
    uint32_t aB_off = ((lane & 7) + g8 * 8) * 528 + d0w * 2 + g16 * 16;

    for (int t = 0; t < TPB; t++) {
        uint32_t cur = (t & 1) ? OFF_X1 : OFF_X0;
        uint32_t nxt = (t & 1) ? OFF_X0 : OFF_X1;
        // prefetch next tile
        if (t + 1 < TPB) {
            int row0 = (bx * TPB + t + 1) * TILE;
#pragma unroll
            for (int k = 0; k < 16; k++) {
                int idx = tid + k * 256;
                int r = idx >> 5, c = idx & 31;
                cpasync16(sb + nxt + r * 528 + c * 16,
                          (const void*)(Xg + (size_t)(row0 + r) * 32 + c));
            }
            cpcommit();
            cpwait<1>();
        } else {
            cpwait<0>();
        }
        __syncthreads();

        // ---- dots via mma ----
        {
            uint32_t dA = sb + cur + dA_off;
            float D0[4] = {0.f, 0.f, 0.f, 0.f}, D1[4] = {0.f, 0.f, 0.f, 0.f};
#pragma unroll
            for (int kc = 0; kc < 16; kc++) {
                unsigned a0, a1, a2, a3, b0, b1, b2, b3;
                ldsm4(a0, a1, a2, a3, dA + kc * 32);
                ldsm4(b0, b1, b2, b3, dB + kc * 32);
                mma16816(D0, a0, a1, a2, a3, b0, b1);
                mma16816(D1, a0, a1, a2, a3, b2, b3);
            }
            int lr = warp * 16 + (lane >> 2), lc = (lane & 3) * 2;
            *(float2*)(Ls + lr * 18 + lc)           = make_float2(D0[0], D0[1]);
            *(float2*)(Ls + (lr + 8) * 18 + lc)     = make_float2(D0[2], D0[3]);
            *(float2*)(Ls + lr * 18 + 8 + lc)       = make_float2(D1[0], D1[1]);
            *(float2*)(Ls + (lr + 8) * 18 + 8 + lc) = make_float2(D1[2], D1[3]);
        }
        __syncthreads();

        // ---- softmax: thread-per-row ----
        if (tid < TILE) {
            const float* lr = Ls + tid * 18;
            float l[KS];
#pragma unroll
            for (int i = 0; i < KS; i++) l[i] = (lr[i] + cbs[i]) * SCALEF;
            float mx = l[0];
#pragma unroll
            for (int i = 1; i < KS; i++) mx = fmaxf(mx, l[i]);
            float se = 0.f;
#pragma unroll
            for (int i = 0; i < KS; i++) { float e = __expf(l[i] - mx); l[i] = e; se += e; }
            float inv = __fdividef(1.0f, se);
            float a16[16];
#pragma unroll
            for (int i = 0; i < 16; i++) a16[i] = 0.f;
#pragma unroll
            for (int i = 0; i < KS; i++) {
                float a = fmaf(l[i], inv, EPSF);
                a16[i] = a; rsl[i] += a;
            }
            unsigned* dst = (unsigned*)(sm + OFF_AS + tid * 48);
#pragma unroll
            for (int p = 0; p < 8; p++) {
                __nv_bfloat162 h = __float22bfloat162_rn(make_float2(a16[2*p], a16[2*p+1]));
                dst[p] = *(unsigned*)&h;
            }
        }
        __syncthreads();

        // ---- accum via mma ----
        {
            uint32_t aB = sb + cur + aB_off;
#pragma unroll
            for (int kr = 0; kr < 8; kr++) {
                unsigned p0, p1, p2, p3, x0, x1, x2, x3, y0, y1, y2, y3;
                ldsm4t(p0, p1, p2, p3, aA + kr * (16 * 48));
                ldsm4t(x0, x1, x2, x3, aB + kr * (16 * 528));
                ldsm4t(y0, y1, y2, y3, aB + kr * (16 * 528) + 32);
                mma16816(uacc[0], p0, p1, p2, p3, x0, x1);
                mma16816(uacc[1], p0, p1, p2, p3, x2, x3);
                mma16816(uacc[2], p0, p1, p2, p3, y0, y1);
                mma16816(uacc[3], p0, p1, p2, p3, y2, y3);
            }
        }
        __syncthreads();
    }

    // ---- write U fragments directly to global partials ----
    {
        float* up = uhpart + ((size_t)(b * NTP + bx)) * KS * DD;
        int slot = lane >> 2, dp = (lane & 3) * 2;
#pragma unroll
        for (int nt = 0; nt < 4; nt++) {
            int d = d0w + nt * 8 + dp;
            *(float2*)(up + slot * DD + d) = make_float2(uacc[nt][0], uacc[nt][1]);
            if (slot + 8 < KS)
                *(float2*)(up + (slot + 8) * DD + d) = make_float2(uacc[nt][2], uacc[nt][3]);
        }
    }
    // ---- row-sum reduce ----
    if (tid < TILE) {
#pragma unroll
        for (int i = 0; i < KS; i++) {
#pragma unroll
            for (int o = 16; o; o >>= 1) rsl[i] += __shfl_xor_sync(0xffffffffu, rsl[i], o);
        }
        if (lane == 0) {
#pragma unroll
            for (int i = 0; i < KS; i++) rsw[warp * 16 + i] = rsl[i];
        }
    }
    __syncthreads();
    if (tid < KS)
        rspart[(size_t)(b * NTP + bx) * KS + tid] =
            rsw[tid] + rsw[16 + tid] + rsw[32 + tid] + rsw[48 + tid];
}

// ---------------- finalize ----------------
__global__ void k_fin(const float* __restrict__ uhpart, const float* __restrict__ rspart,
                      const float* __restrict__ wf, const float* __restrict__ bf,
                      float* __restrict__ out) {
    int m = blockIdx.x, d = threadIdx.x;
    int b = m / KS, i = m % KS;
    const float* up = uhpart + ((size_t)b * NTP) * KS * DD + i * DD + d;
    const float* rp = rspart + b * NTP * KS + i;
    float s = 0.f, r = 0.f;
#pragma unroll
    for (int t = 0; t < NTP; t++) { s += up[(size_t)t * KS * DD]; r += rp[t * KS]; }
    out[(size_t)m * DD + d] = __fdividef(wf[d] * s, r) + bf[d];
}

// ---------------- fused GRU + LN_p: warp per row ----------------
__global__ void k_gruln(const float* __restrict__ gi, const float* __restrict__ gh,
                        float* __restrict__ slots, const float* __restrict__ wp,
                        const float* __restrict__ bp, float* __restrict__ p) {
    int m = blockIdx.x * 8 + (threadIdx.x >> 5);
    int lane = threadIdx.x & 31;
    int d0 = lane * 8;
    const float* gim = gi + (size_t)m * 3 * DD;
    const float* ghm = gh + (size_t)m * 3 * DD;
    float ir[8], iz[8], in_[8], hr[8], hz[8], hn[8], sp[8], v[8];
    *(float4*)ir   = *(const float4*)(gim + d0);       *(float4*)(ir+4)  = *(const float4*)(gim + d0 + 4);
    *(float4*)iz   = *(const float4*)(gim + DD + d0);  *(float4*)(iz+4)  = *(const float4*)(gim + DD + d0 + 4);
    *(float4*)in_  = *(const float4*)(gim + 2*DD + d0);*(float4*)(in_+4) = *(const float4*)(gim + 2*DD + d0 + 4);
    *(float4*)hr   = *(const float4*)(ghm + d0);       *(float4*)(hr+4)  = *(const float4*)(ghm + d0 + 4);
    *(float4*)hz   = *(const float4*)(ghm + DD + d0);  *(float4*)(hz+4)  = *(const float4*)(ghm + DD + d0 + 4);
    *(float4*)hn   = *(const float4*)(ghm + 2*DD + d0);*(float4*)(hn+4)  = *(const float4*)(ghm + 2*DD + d0 + 4);
    *(float4*)sp   = *(const float4*)(slots + (size_t)m*DD + d0);
    *(float4*)(sp+4) = *(const float4*)(slots + (size_t)m*DD + d0 + 4);
    float s = 0.f, s2 = 0.f;
#pragma unroll
    for (int j = 0; j < 8; j++) {
        float r = 1.0f / (1.0f + __expf(-(ir[j] + hr[j])));
        float z = 1.0f / (1.0f + __expf(-(iz[j] + hz[j])));
        float n = tanhf(in_[j] + r * hn[j]);
        float vv = (1.0f - z) * n + z * sp[j];
        v[j] = vv; s += vv; s2 += vv * vv;
    }
#pragma unroll
    for (int o = 16; o; o >>= 1) {
        s  += __shfl_xor_sync(0xffffffffu, s,  o);
        s2 += __shfl_xor_sync(0xffffffffu, s2, o);
    }
    float mm = s * (1.0f / DD);
    float var = s2 * (1.0f / DD) - mm * mm;
    float rr = rsqrtf(var + LNEPS);
    *(float4*)(slots + (size_t)m*DD + d0)     = *(float4*)v;
    *(float4*)(slots + (size_t)m*DD + d0 + 4) = *(float4*)(v+4);
    float w_[8], b_[8], pv[8];
    *(float4*)w_ = *(const float4*)(wp + d0); *(float4*)(w_+4) = *(const float4*)(wp + d0 + 4);
    *(float4*)b_ = *(const float4*)(bp + d0); *(float4*)(b_+4) = *(const float4*)(bp + d0 + 4);
#pragma unroll
    for (int j = 0; j < 8; j++) pv[j] = (v[j] - mm) * rr * w_[j] + b_[j];
    *(float4*)(p + (size_t)m*DD + d0)     = *(float4*)pv;
    *(float4*)(p + (size_t)m*DD + d0 + 4) = *(float4*)(pv+4);
}

// ---------------- SGEMM body ----------------
__device__ __forceinline__ void gemm_body(
    const float* __restrict__ A, const float* __restrict__ W,
    const float* __restrict__ bias, float* __restrict__ C,
    int M, int N, int K, int relu, int accflag,
    float (*As)[68], float (*Ws)[68]) {
    int tid = threadIdx.x;
    int m0 = blockIdx.y * 64, n0 = blockIdx.x * 64;
    int ml = (tid >> 5) * 8;
    int nl = (tid & 31) * 2;
    ull acc[4][2];
#pragma unroll
    for (int i = 0; i < 4; i++) { acc[i][0] = 0ull; acc[i][1] = 0ull; }

    for (int k0 = 0; k0 < K; k0 += 16) {
#pragma unroll
        for (int l = 0; l < 4; l++) {
            int idx = tid + l * 256;
            int r = idx >> 4, c = idx & 15;
            As[c][r] = A[(size_t)(m0 + r) * K + k0 + c];
            Ws[c][r] = W[(size_t)(n0 + r) * K + k0 + c];
        }
        __syncthreads();
#pragma unroll
        for (int kk = 0; kk < 16; kk++) {
            ulonglong2 a01 = *(const ulonglong2*)&As[kk][ml];
            ulonglong2 a23 = *(const ulonglong2*)&As[kk][ml + 4];
            float2 bv = *(const float2*)&Ws[kk][nl];
            ull b0 = dup2(bv.x), b1 = dup2(bv.y);
            acc[0][0] = fma2(a01.x, b0, acc[0][0]); acc[0][1] = fma2(a01.x, b1, acc[0][1]);
            acc[1][0] = fma2(a01.y, b0, acc[1][0]); acc[1][1] = fma2(a01.y, b1, acc[1][1]);
            acc[2][0] = fma2(a23.x, b0, acc[2][0]); acc[2][1] = fma2(a23.x, b1, acc[2][1]);
            acc[3][0] = fma2(a23.y, b0, acc[3][0]); acc[3][1] = fma2(a23.y, b1, acc[3][1]);
        }
        __syncthreads();
    }
    float bb0 = bias ? bias[n0 + nl] : 0.f;
    float bb1 = bias ? bias[n0 + nl + 1] : 0.f;
#pragma unroll
    for (int mi = 0; mi < 4; mi++) {
        float r0c0, r1c0, r0c1, r1c1;
        unpack2(acc[mi][0], r0c0, r1c0);
        unpack2(acc[mi][1], r0c1, r1c1);
        int m = m0 + ml + mi * 2;
        float2 v0 = make_float2(r0c0 + bb0, r0c1 + bb1);
        float2 v1 = make_float2(r1c0 + bb0, r1c1 + bb1);
        if (relu) {
            v0.x = fmaxf(v0.x, 0.f); v0.y = fmaxf(v0.y, 0.f);
            v1.x = fmaxf(v1.x, 0.f); v1.y = fmaxf(v1.y, 0.f);
        }
        float2* p0 = (float2*)&C[(size_t)m * N + n0 + nl];
        float2* p1 = (float2*)&C[(size_t)(m + 1) * N + n0 + nl];
        if (accflag) {
            float2 t0 = *p0, t1 = *p1;
            v0.x += t0.x; v0.y += t0.y; v1.x += t1.x; v1.y += t1.y;
        }
        *p0 = v0; *p1 = v1;
    }
}

__global__ void __launch_bounds__(256) k_gemm(
    const float* __restrict__ A, const float* __restrict__ W,
    const float* __restrict__ bias, float* __restrict__ C,
    int M, int N, int K, int relu, int accflag) {
    __shared__ __align__(16) float As[16][68];
    __shared__ __align__(16) float Ws[16][68];
    gemm_body(A, W, bias, C, M, N, K, relu, accflag, As, Ws);
}

__global__ void __launch_bounds__(256) k_gemmd(
    const float* __restrict__ A0, const float* __restrict__ A1,
    const float* __restrict__ W0, const float* __restrict__ W1,
    const float* __restrict__ b0, const float* __restrict__ b1,
    float* __restrict__ C0, float* __restrict__ C1, int M, int N, int K) {
    __shared__ __align__(16) float As[16][68];
    __shared__ __align__(16) float Ws[16][68];
    if (blockIdx.z == 0) gemm_body(A0, W0, b0, C0, M, N, K, 0, 0, As, Ws);
    else                 gemm_body(A1, W1, b1, C1, M, N, K, 0, 0, As, Ws);
}

extern "C" void kernel_launch(void* const* d_in, const int* in_sizes, int n_in,
                              void* d_out, int out_size) {
    const float* inputs     = (const float*)d_in[0];
    const float* slots_init = (const float*)d_in[1];
    const float* ln_f_w = (const float*)d_in[2];
    const float* ln_f_b = (const float*)d_in[3];
    const float* ln_s_w = (const float*)d_in[4];
    const float* ln_s_b = (const float*)d_in[5];
    const float* ln_p_w = (const float*)d_in[6];
    const float* ln_p_b = (const float*)d_in[7];
    const float* Wq  = (const float*)d_in[8];
    const float* Wk  = (const float*)d_in[9];
    const float* Wv  = (const float*)d_in[10];
    const float* W_ih = (const float*)d_in[11];
    const float* b_ih = (const float*)d_in[12];
    const float* W_hh = (const float*)d_in[13];
    const float* b_hh = (const float*)d_in[14];
    const float* W1 = (const float*)d_in[15];
    const float* b1 = (const float*)d_in[16];
    const float* W2 = (const float*)d_in[17];
    const float* b2 = (const float*)d_in[18];
    float* slots = (float*)d_out;

    unsigned short* p_xln;
    float *p_weff, *p_wgv, *p_wihv, *p_cb, *p_qe, *p_uhp, *p_rsp;
    float *p_updpre, *p_gi, *p_gh, *p_p, *p_h1;
    cudaGetSymbolAddress((void**)&p_xln, g_xln);
    cudaGetSymbolAddress((void**)&p_weff, g_weff);
    cudaGetSymbolAddress((void**)&p_wgv, g_wgv);
    cudaGetSymbolAddress((void**)&p_wihv, g_wihv);
    cudaGetSymbolAddress((void**)&p_cb, g_cb);
    cudaGetSymbolAddress((void**)&p_qe, g_qe);
    cudaGetSymbolAddress((void**)&p_uhp, g_uhpart);
    cudaGetSymbolAddress((void**)&p_rsp, g_rspart);
    cudaGetSymbolAddress((void**)&p_updpre, g_updpre);
    cudaGetSymbolAddress((void**)&p_gi, g_gi);
    cudaGetSymbolAddress((void**)&p_gh, g_gh);
    cudaGetSymbolAddress((void**)&p_p, g_p);
    cudaGetSymbolAddress((void**)&p_h1, g_h1);

    cudaFuncSetAttribute(k_attn, cudaFuncAttributeMaxDynamicSharedMemorySize, ATTN_SMEM);

    cudaMemcpyAsync(slots, slots_init, (size_t)BB * KS * DD * sizeof(float),
                    cudaMemcpyDeviceToDevice);
    k_xln<<<BB * NN / 8, 256>>>(inputs, p_xln);
    k_wprep<<<DD + 1, DD>>>(Wk, Wq, ln_f_w, ln_f_b, ln_s_w, ln_s_b, p_weff, p_wgv);

    for (int it = 0; it < NITER; it++) {
        k_qeln<<<dim3(4, 11), 256>>>(slots, p_weff, p_wgv, ln_s_w, ln_s_b, p_qe, p_cb);
        k_attn<<<dim3(NTP, BB), 256, ATTN_SMEM>>>((const uint4*)p_xln, p_qe, p_cb,
                                                  p_uhp, p_rsp);
        k_fin<<<704, 256>>>(p_uhp, p_rsp, ln_f_w, ln_f_b, p_updpre);
        if (it == 0) k_wihv<<<3 * DD, DD>>>(W_ih, Wv, p_wihv);
        k_gemmd<<<dim3(12, 11, 2), 256>>>(p_updpre, slots, p_wihv, W_hh, b_ih, b_hh,
                                          p_gi, p_gh, 704, 768, 256);
        k_gruln<<<88, 256>>>(p_gi, p_gh, slots, ln_p_w, ln_p_b, p_p);
        k_gemm<<<dim3(8, 11), 256>>>(p_p, W1, b1, p_h1, 704, 512, 256, 1, 0);
        k_gemm<<<dim3(4, 11), 256>>>(p_h1, W2, b2, slots, 704, 256, 512, 0, 1);
    }
}

// round 9
// speedup vs baseline: 2.5823x; 1.1219x over previous
#include <cuda_runtime.h>
#include <cuda_bf16.h>
#include <math.h>
#include <stdint.h>

#define BB 64
#define NN 4096
#define DD 256
#define KS 11
#define HH 512
#define NITER 5
#define EPSF 1e-8f
#define LNEPS 1e-5f
#define SCALEF 0.0625f
#define TILE 128
#define TPB 8
#define NTP (NN/TILE/TPB)   // 4 partials per batch

typedef unsigned long long ull;

// ---------------- f32x2 packed helpers (k_qeln) ----------------
__device__ __forceinline__ ull fma2(ull a, ull b, ull c) {
    ull d; asm("fma.rn.f32x2 %0, %1, %2, %3;" : "=l"(d) : "l"(a), "l"(b), "l"(c)); return d;
}
__device__ __forceinline__ ull dup2(float a) {
    unsigned int u = __float_as_uint(a);
    ull d; asm("mov.b64 %0, {%1, %1};" : "=l"(d) : "r"(u)); return d;
}
__device__ __forceinline__ void unpack2(ull v, float& x, float& y) {
    unsigned int a, b;
    asm("mov.b64 {%0, %1}, %2;" : "=r"(a), "=r"(b) : "l"(v));
    x = __uint_as_float(a); y = __uint_as_float(b);
}

// ---------------- mma / ldmatrix / cp.async helpers ----------------
__device__ __forceinline__ uint32_t s2u(const void* p) {
    uint32_t a;
    asm("{.reg .u64 t; cvta.to.shared.u64 t, %1; cvt.u32.u64 %0, t;}" : "=r"(a) : "l"(p));
    return a;
}
__device__ __forceinline__ void ldsm4(unsigned& r0, unsigned& r1, unsigned& r2,
                                      unsigned& r3, uint32_t addr) {
    asm volatile("ldmatrix.sync.aligned.m8n8.x4.shared.b16 {%0,%1,%2,%3}, [%4];"
                 : "=r"(r0), "=r"(r1), "=r"(r2), "=r"(r3) : "r"(addr));
}
__device__ __forceinline__ void ldsm4t(unsigned& r0, unsigned& r1, unsigned& r2,
                                       unsigned& r3, uint32_t addr) {
    asm volatile("ldmatrix.sync.aligned.m8n8.x4.trans.shared.b16 {%0,%1,%2,%3}, [%4];"
                 : "=r"(r0), "=r"(r1), "=r"(r2), "=r"(r3) : "r"(addr));
}
__device__ __forceinline__ void mma16816(float* d, unsigned a0, unsigned a1, unsigned a2,
                                         unsigned a3, unsigned b0, unsigned b1) {
    asm volatile("mma.sync.aligned.m16n8k16.row.col.f32.bf16.bf16.f32 "
                 "{%0,%1,%2,%3}, {%4,%5,%6,%7}, {%8,%9}, {%0,%1,%2,%3};"
                 : "+f"(d[0]), "+f"(d[1]), "+f"(d[2]), "+f"(d[3])
                 : "r"(a0), "r"(a1), "r"(a2), "r"(a3), "r"(b0), "r"(b1));
}
__device__ __forceinline__ void mma_tf32(float* d, unsigned a0, unsigned a1, unsigned a2,
                                         unsigned a3, unsigned b0, unsigned b1) {
    asm volatile("mma.sync.aligned.m16n8k8.row.col.f32.tf32.tf32.f32 "
                 "{%0,%1,%2,%3}, {%4,%5,%6,%7}, {%8,%9}, {%0,%1,%2,%3};"
                 : "+f"(d[0]), "+f"(d[1]), "+f"(d[2]), "+f"(d[3])
                 : "r"(a0), "r"(a1), "r"(a2), "r"(a3), "r"(b0), "r"(b1));
}
__device__ __forceinline__ void cvt_tf32_4(float4& v) {
    unsigned x;
    asm("cvt.rna.tf32.f32 %0, %1;" : "=r"(x) : "f"(v.x)); v.x = __uint_as_float(x);
    asm("cvt.rna.tf32.f32 %0, %1;" : "=r"(x) : "f"(v.y)); v.y = __uint_as_float(x);
    asm("cvt.rna.tf32.f32 %0, %1;" : "=r"(x) : "f"(v.z)); v.z = __uint_as_float(x);
    asm("cvt.rna.tf32.f32 %0, %1;" : "=r"(x) : "f"(v.w)); v.w = __uint_as_float(x);
}
__device__ __forceinline__ void cpasync16(uint32_t saddr, const void* gaddr) {
    asm volatile("cp.async.cg.shared.global [%0], [%1], 16;" :: "r"(saddr), "l"(gaddr));
}
__device__ __forceinline__ void cpcommit() {
    asm volatile("cp.async.commit_group;");
}
template <int N>
__device__ __forceinline__ void cpwait() {
    asm volatile("cp.async.wait_group %0;" :: "n"(N));
}

// ---------------- scratch ----------------
__device__ __align__(16) unsigned short g_xln[BB*NN*DD];
__device__ float g_weff[DD*DD];
__device__ float g_wgv[DD + 2];
__device__ float g_wihv[3*DD*DD];
__device__ float g_cb[BB*KS];
__device__ float g_qe[BB*KS*DD];
__device__ float g_uhpart[BB*NTP*KS*DD];
__device__ float g_rspart[BB*NTP*KS];
__device__ float g_gi[BB*KS*3*DD];
__device__ float g_gh[BB*KS*3*DD];
__device__ float g_p[BB*KS*DD];
__device__ float g_h1[BB*KS*HH];

// ---------------- xln = (x-mean)*rstd in bf16 (once) ----------------
__global__ void k_xln(const float* __restrict__ X, unsigned short* __restrict__ out) {
    int row = blockIdx.x * 8 + (threadIdx.x >> 5);
    int lane = threadIdx.x & 31;
    const float4* p = (const float4*)(X + (size_t)row * DD);
    float4 v0 = p[lane * 2], v1 = p[lane * 2 + 1];
    float s  = v0.x + v0.y + v0.z + v0.w + v1.x + v1.y + v1.z + v1.w;
    float s2 = v0.x*v0.x + v0.y*v0.y + v0.z*v0.z + v0.w*v0.w
             + v1.x*v1.x + v1.y*v1.y + v1.z*v1.z + v1.w*v1.w;
#pragma unroll
    for (int o = 16; o; o >>= 1) {
        s  += __shfl_xor_sync(0xffffffffu, s,  o);
        s2 += __shfl_xor_sync(0xffffffffu, s2, o);
    }
    float m = s * (1.0f / DD);
    float var = s2 * (1.0f / DD) - m * m;
    float r = rsqrtf(var + LNEPS);
    __nv_bfloat162 h0 = __float22bfloat162_rn(make_float2((v0.x-m)*r, (v0.y-m)*r));
    __nv_bfloat162 h1 = __float22bfloat162_rn(make_float2((v0.z-m)*r, (v0.w-m)*r));
    __nv_bfloat162 h2 = __float22bfloat162_rn(make_float2((v1.x-m)*r, (v1.y-m)*r));
    __nv_bfloat162 h3 = __float22bfloat162_rn(make_float2((v1.z-m)*r, (v1.w-m)*r));
    uint4 o;
    o.x = *(unsigned int*)&h0; o.y = *(unsigned int*)&h1;
    o.z = *(unsigned int*)&h2; o.w = *(unsigned int*)&h3;
    ((uint4*)(out + (size_t)row * DD))[lane] = o;
}

// ---------------- wprep ----------------
__global__ void k_wprep(const float* __restrict__ Wk, const float* __restrict__ Wq,
                        const float* __restrict__ wf, const float* __restrict__ bf,
                        const float* __restrict__ ws, const float* __restrict__ bs,
                        float* __restrict__ weff, float* __restrict__ wgv) {
    __shared__ float col[DD];
    __shared__ float red[8];
    int t = threadIdx.x;
    if (blockIdx.x < DD) {
        int d = blockIdx.x;
        col[t] = Wk[t * DD + d];
        __syncthreads();
        float acc = 0.f;
        for (int s = 0; s < DD; s++) acc = fmaf(col[s], Wq[s * DD + t], acc);
        weff[d * DD + t] = acc * wf[d];
    } else {
        float a = 0.f;
        for (int e = 0; e < DD; e++) a = fmaf(Wk[t * DD + e], bf[e], a);
        col[t] = a;
        __syncthreads();
        float gv = 0.f;
        for (int s = 0; s < DD; s++) gv = fmaf(Wq[s * DD + t], col[s], gv);
        float w = ws[t] * gv;
        wgv[t] = w;
        float c1 = w, c0 = bs[t] * gv;
        int lane = t & 31, warp = t >> 5;
#pragma unroll
        for (int o = 16; o; o >>= 1) {
            c1 += __shfl_xor_sync(0xffffffffu, c1, o);
            c0 += __shfl_xor_sync(0xffffffffu, c0, o);
        }
        __syncthreads();
        if (lane == 0) red[warp] = c1;
        __syncthreads();
        if (t == 0) {
            float s1 = 0.f;
            for (int i = 0; i < 8; i++) s1 += red[i];
            wgv[DD] = s1;
        }
        __syncthreads();
        if (lane == 0) red[warp] = c0;
        __syncthreads();
        if (t == 1) {
            float s0 = 0.f;
            for (int i = 0; i < 8; i++) s0 += red[i];
            wgv[DD + 1] = s0;
        }
    }
}

// ---------------- wihv[m][e] = sum_j W_ih[m,j] * Wv[j,e] (once) ----------------
__global__ void k_wihv(const float* __restrict__ Wih, const float* __restrict__ Wv,
                       float* __restrict__ out) {
    __shared__ float row[DD];
    int m = blockIdx.x, t = threadIdx.x;
    row[t] = Wih[m * DD + t];
    __syncthreads();
    float acc = 0.f;
#pragma unroll 4
    for (int j = 0; j < DD; j++) acc = fmaf(row[j], Wv[j * DD + t], acc);
    out[m * DD + t] = acc;
}

// ---------------- fused LN_s + cb + qe GEMM (fp32) ----------------
__global__ void __launch_bounds__(256) k_qeln(
    const float* __restrict__ slots, const float* __restrict__ weff,
    const float* __restrict__ wgv, const float* __restrict__ lsw,
    const float* __restrict__ lsb, float* __restrict__ qe, float* __restrict__ cb) {
    __shared__ __align__(16) float As[16][68];
    __shared__ __align__(16) float Ws[16][68];
    __shared__ float ws[DD], bs[DD], rowm[64], rowr[64];
    int tid = threadIdx.x, lane = tid & 31, warp = tid >> 5;
    int m0 = blockIdx.y * 64, n0 = blockIdx.x * 64;
    ws[tid] = lsw[tid]; bs[tid] = lsb[tid];
    float C1 = wgv[DD], C0 = wgv[DD + 1];
    float4 wg0 = *(const float4*)(wgv + lane * 8);
    float4 wg1 = *(const float4*)(wgv + lane * 8 + 4);
#pragma unroll
    for (int rr = 0; rr < 8; rr++) {
        int rl = warp * 8 + rr, row = m0 + rl;
        const float4* p = (const float4*)(slots + (size_t)row * DD);
        float4 v0 = p[lane * 2], v1 = p[lane * 2 + 1];
        float s  = v0.x + v0.y + v0.z + v0.w + v1.x + v1.y + v1.z + v1.w;
        float s2 = v0.x*v0.x + v0.y*v0.y + v0.z*v0.z + v0.w*v0.w
                 + v1.x*v1.x + v1.y*v1.y + v1.z*v1.z + v1.w*v1.w;
        float s3 = v0.x*wg0.x + v0.y*wg0.y + v0.z*wg0.z + v0.w*wg0.w
                 + v1.x*wg1.x + v1.y*wg1.y + v1.z*wg1.z + v1.w*wg1.w;
#pragma unroll
        for (int o = 16; o; o >>= 1) {
            s  += __shfl_xor_sync(0xffffffffu, s,  o);
            s2 += __shfl_xor_sync(0xffffffffu, s2, o);
            s3 += __shfl_xor_sync(0xffffffffu, s3, o);
        }
        if (lane == 0) {
            float m = s * (1.0f / DD);
            float var = s2 * (1.0f / DD) - m * m;
            float r = rsqrtf(var + LNEPS);
            rowm[rl] = m; rowr[rl] = r;
            if (blockIdx.x == 0) cb[row] = r * s3 - r * m * C1 + C0;
        }
    }
    __syncthreads();
    int ml = (tid >> 5) * 8, nl = (tid & 31) * 2;
    ull acc[4][2];
#pragma unroll
    for (int i = 0; i < 4; i++) { acc[i][0] = 0ull; acc[i][1] = 0ull; }
    for (int k0 = 0; k0 < DD; k0 += 16) {
#pragma unroll
        for (int l = 0; l < 4; l++) {
            int idx = tid + l * 256;
            int r = idx >> 4, c = idx & 15;
            float v = slots[(size_t)(m0 + r) * DD + k0 + c];
            As[c][r] = (v - rowm[r]) * rowr[r] * ws[k0 + c] + bs[k0 + c];
            Ws[c][r] = weff[(size_t)(n0 + r) * DD + k0 + c];
        }
        __syncthreads();
#pragma unroll
        for (int kk = 0; kk < 16; kk++) {
            ulonglong2 a01 = *(const ulonglong2*)&As[kk][ml];
            ulonglong2 a23 = *(const ulonglong2*)&As[kk][ml + 4];
            float2 bv = *(const float2*)&Ws[kk][nl];
            ull b0 = dup2(bv.x), b1 = dup2(bv.y);
            acc[0][0] = fma2(a01.x, b0, acc[0][0]); acc[0][1] = fma2(a01.x, b1, acc[0][1]);
            acc[1][0] = fma2(a01.y, b0, acc[1][0]); acc[1][1] = fma2(a01.y, b1, acc[1][1]);
            acc[2][0] = fma2(a23.x, b0, acc[2][0]); acc[2][1] = fma2(a23.x, b1, acc[2][1]);
            acc[3][0] = fma2(a23.y, b0, acc[3][0]); acc[3][1] = fma2(a23.y, b1, acc[3][1]);
        }
        __syncthreads();
    }
#pragma unroll
    for (int mi = 0; mi < 4; mi++) {
        float r0c0, r1c0, r0c1, r1c1;
        unpack2(acc[mi][0], r0c0, r1c0);
        unpack2(acc[mi][1], r0c1, r1c1);
        int m = m0 + ml + mi * 2;
        *(float2*)&qe[(size_t)m * DD + n0 + nl] = make_float2(r0c0, r0c1);
        *(float2*)&qe[(size_t)(m + 1) * DD + n0 + nl] = make_float2(r1c0, r1c1);
    }
}

// ---------------- fused attention: tensor-core, single buffer, 2 blocks/SM ----------------
// smem layout (bytes):
//   Xs  [0, 67584)          128 x 264 bf16 (stride 528B)
//   Qp  [67584, 76032)      16 x 264 bf16 (stride 528B), slots 11-15 zero
//   Ls  [76032, 85248)      128 x 18 f32 logits
//   As  [85248, 91392)      128 x 24 bf16 attn (stride 48B)
//   rsw [91392, 91648)      4 x 16 f32
//   cbs [91648, 91712)      16 f32
#define OFF_X   0
#define OFF_QP  67584
#define OFF_LS  76032
#define OFF_AS  85248
#define OFF_RSW 91392
#define OFF_CBS 91648
#define ATTN_SMEM 91712

__global__ void __launch_bounds__(256, 2) k_attn(
    const uint4* __restrict__ xln, const float* __restrict__ qe,
    const float* __restrict__ cb, float* __restrict__ uhpart,
    float* __restrict__ rspart) {
    extern __shared__ char sm[];
    uint32_t sb = s2u(sm);
    float* Ls  = (float*)(sm + OFF_LS);
    float* rsw = (float*)(sm + OFF_RSW);
    float* cbs = (float*)(sm + OFF_CBS);

    int bx = blockIdx.x, b = blockIdx.y;
    int tid = threadIdx.x, lane = tid & 31, warp = tid >> 5;

    // stage Qp (bf16, padded slots zero) + cbs
    for (int i = tid; i < 16 * 128; i += 256) {
        int slot = i >> 7, dp = i & 127;
        unsigned v = 0;
        if (slot < KS) {
            float2 f = *(const float2*)(qe + ((size_t)b * KS + slot) * DD + dp * 2);
            __nv_bfloat162 h = __float22bfloat162_rn(f);
            v = *(unsigned*)&h;
        }
        *(unsigned*)(sm + OFF_QP + slot * 528 + dp * 4) = v;
    }
    if (tid < 16) cbs[tid] = (tid < KS) ? cb[b * KS + tid] : 0.f;

    const uint4* Xg = xln + (size_t)b * NN * (DD / 8);

    float rsl[KS];
    float uacc[4][4];
#pragma unroll
    for (int i = 0; i < KS; i++) rsl[i] = 0.f;
#pragma unroll
    for (int i = 0; i < 4; i++)
#pragma unroll
        for (int j = 0; j < 4; j++) uacc[i][j] = 0.f;

    int g8  = (lane & 8)  ? 1 : 0;
    int g16 = (lane & 16) ? 1 : 0;
    uint32_t dA = sb + OFF_X + ((warp * 16) + (lane & 7) + g8 * 8) * 528 + g16 * 16;
    uint32_t dB = sb + OFF_QP + ((lane & 7) + g16 * 8) * 528 + g8 * 16;
    uint32_t aA = sb + OFF_AS + ((lane & 7) + g16 * 8) * 48 + g8 * 16;
    int d0w = warp * 32;
    uint32_t aB = sb + OFF_X + ((lane & 7) + g8 * 8) * 528 + d0w * 2 + g16 * 16;

    for (int t = 0; t < TPB; t++) {
        // stage X tile (cp.async)
        {
            int row0 = (bx * TPB + t) * TILE;
#pragma unroll
            for (int k = 0; k < 16; k++) {
                int idx = tid + k * 256;
                int r = idx >> 5, c = idx & 31;
                cpasync16(sb + OFF_X + r * 528 + c * 16,
                          (const void*)(Xg + (size_t)(row0 + r) * 32 + c));
            }
            cpcommit();
            cpwait<0>();
        }
        __syncthreads();

        // ---- dots via mma ----
        {
            float D0[4] = {0.f, 0.f, 0.f, 0.f}, D1[4] = {0.f, 0.f, 0.f, 0.f};
#pragma unroll
            for (int kc = 0; kc < 16; kc++) {
                unsigned a0, a1, a2, a3, b0, b1, b2, b3;
                ldsm4(a0, a1, a2, a3, dA + kc * 32);
                ldsm4(b0, b1, b2, b3, dB + kc * 32);
                mma16816(D0, a0, a1, a2, a3, b0, b1);
                mma16816(D1, a0, a1, a2, a3, b2, b3);
            }
            int lr = warp * 16 + (lane >> 2), lc = (lane & 3) * 2;
            *(float2*)(Ls + lr * 18 + lc)           = make_float2(D0[0], D0[1]);
            *(float2*)(Ls + (lr + 8) * 18 + lc)     = make_float2(D0[2], D0[3]);
            *(float2*)(Ls + lr * 18 + 8 + lc)       = make_float2(D1[0], D1[1]);
            *(float2*)(Ls + (lr + 8) * 18 + 8 + lc) = make_float2(D1[2], D1[3]);
        }
        __syncthreads();

        // ---- softmax: thread-per-row ----
        if (tid < TILE) {
            const float* lr = Ls + tid * 18;
            float l[KS];
#pragma unroll
            for (int i = 0; i < KS; i++) l[i] = (lr[i] + cbs[i]) * SCALEF;
            float mx = l[0];
#pragma unroll
            for (int i = 1; i < KS; i++) mx = fmaxf(mx, l[i]);
            float se = 0.f;
#pragma unroll
            for (int i = 0; i < KS; i++) { float e = __expf(l[i] - mx); l[i] = e; se += e; }
            float inv = __fdividef(1.0f, se);
            float a16[16];
#pragma unroll
            for (int i = 0; i < 16; i++) a16[i] = 0.f;
#pragma unroll
            for (int i = 0; i < KS; i++) {
                float a = fmaf(l[i], inv, EPSF);
                a16[i] = a; rsl[i] += a;
            }
            unsigned* dst = (unsigned*)(sm + OFF_AS + tid * 48);
#pragma unroll
            for (int p = 0; p < 8; p++) {
                __nv_bfloat162 h = __float22bfloat162_rn(make_float2(a16[2*p], a16[2*p+1]));
                dst[p] = *(unsigned*)&h;
            }
        }
        __syncthreads();

        // ---- accum via mma ----
        {
#pragma unroll
            for (int kr = 0; kr < 8; kr++) {
                unsigned p0, p1, p2, p3, x0, x1, x2, x3, y0, y1, y2, y3;
                ldsm4t(p0, p1, p2, p3, aA + kr * (16 * 48));
                ldsm4t(x0, x1, x2, x3, aB + kr * (16 * 528));
                ldsm4t(y0, y1, y2, y3, aB + kr * (16 * 528) + 32);
                mma16816(uacc[0], p0, p1, p2, p3, x0, x1);
                mma16816(uacc[1], p0, p1, p2, p3, x2, x3);
                mma16816(uacc[2], p0, p1, p2, p3, y0, y1);
                mma16816(uacc[3], p0, p1, p2, p3, y2, y3);
            }
        }
        __syncthreads();
    }

    // ---- write U fragments directly to global partials ----
    {
        float* up = uhpart + ((size_t)(b * NTP + bx)) * KS * DD;
        int slot = lane >> 2, dp = (lane & 3) * 2;
#pragma unroll
        for (int nt = 0; nt < 4; nt++) {
            int d = d0w + nt * 8 + dp;
            *(float2*)(up + slot * DD + d) = make_float2(uacc[nt][0], uacc[nt][1]);
            if (slot + 8 < KS)
                *(float2*)(up + (slot + 8) * DD + d) = make_float2(uacc[nt][2], uacc[nt][3]);
        }
    }
    // ---- row-sum reduce ----
    if (tid < TILE) {
#pragma unroll
        for (int i = 0; i < KS; i++) {
#pragma unroll
            for (int o = 16; o; o >>= 1) rsl[i] += __shfl_xor_sync(0xffffffffu, rsl[i], o);
        }
        if (lane == 0) {
#pragma unroll
            for (int i = 0; i < KS; i++) rsw[warp * 16 + i] = rsl[i];
        }
    }
    __syncthreads();
    if (tid < KS)
        rspart[(size_t)(b * NTP + bx) * KS + tid] =
            rsw[tid] + rsw[16 + tid] + rsw[32 + tid] + rsw[48 + tid];
}

// ---------------- fused GRU + LN_p: warp per row ----------------
__global__ void k_gruln(const float* __restrict__ gi, const float* __restrict__ gh,
                        float* __restrict__ slots, const float* __restrict__ wp,
                        const float* __restrict__ bp, float* __restrict__ p) {
    int m = blockIdx.x * 8 + (threadIdx.x >> 5);
    int lane = threadIdx.x & 31;
    int d0 = lane * 8;
    const float* gim = gi + (size_t)m * 3 * DD;
    const float* ghm = gh + (size_t)m * 3 * DD;
    float ir[8], iz[8], in_[8], hr[8], hz[8], hn[8], sp[8], v[8];
    *(float4*)ir   = *(const float4*)(gim + d0);       *(float4*)(ir+4)  = *(const float4*)(gim + d0 + 4);
    *(float4*)iz   = *(const float4*)(gim + DD + d0);  *(float4*)(iz+4)  = *(const float4*)(gim + DD + d0 + 4);
    *(float4*)in_  = *(const float4*)(gim + 2*DD + d0);*(float4*)(in_+4) = *(const float4*)(gim + 2*DD + d0 + 4);
    *(float4*)hr   = *(const float4*)(ghm + d0);       *(float4*)(hr+4)  = *(const float4*)(ghm + d0 + 4);
    *(float4*)hz   = *(const float4*)(ghm + DD + d0);  *(float4*)(hz+4)  = *(const float4*)(ghm + DD + d0 + 4);
    *(float4*)hn   = *(const float4*)(ghm + 2*DD + d0);*(float4*)(hn+4)  = *(const float4*)(ghm + 2*DD + d0 + 4);
    *(float4*)sp   = *(const float4*)(slots + (size_t)m*DD + d0);
    *(float4*)(sp+4) = *(const float4*)(slots + (size_t)m*DD + d0 + 4);
    float s = 0.f, s2 = 0.f;
#pragma unroll
    for (int j = 0; j < 8; j++) {
        float r = 1.0f / (1.0f + __expf(-(ir[j] + hr[j])));
        float z = 1.0f / (1.0f + __expf(-(iz[j] + hz[j])));
        float n = tanhf(in_[j] + r * hn[j]);
        float vv = (1.0f - z) * n + z * sp[j];
        v[j] = vv; s += vv; s2 += vv * vv;
    }
#pragma unroll
    for (int o = 16; o; o >>= 1) {
        s  += __shfl_xor_sync(0xffffffffu, s,  o);
        s2 += __shfl_xor_sync(0xffffffffu, s2, o);
    }
    float mm = s * (1.0f / DD);
    float var = s2 * (1.0f / DD) - mm * mm;
    float rr = rsqrtf(var + LNEPS);
    *(float4*)(slots + (size_t)m*DD + d0)     = *(float4*)v;
    *(float4*)(slots + (size_t)m*DD + d0 + 4) = *(float4*)(v+4);
    float w_[8], b_[8], pv[8];
    *(float4*)w_ = *(const float4*)(wp + d0); *(float4*)(w_+4) = *(const float4*)(wp + d0 + 4);
    *(float4*)b_ = *(const float4*)(bp + d0); *(float4*)(b_+4) = *(const float4*)(bp + d0 + 4);
#pragma unroll
    for (int j = 0; j < 8; j++) pv[j] = (v[j] - mm) * rr * w_[j] + b_[j];
    *(float4*)(p + (size_t)m*DD + d0)     = *(float4*)pv;
    *(float4*)(p + (size_t)m*DD + d0 + 4) = *(float4*)(pv+4);
}

// ---------------- tf32 tensor-core GEMM: C[m][n] = sum_k A[m][k]*W[n][k] ----------------
// 64x64 tile, 256 thr = 8 warps (2m x 4n), warp tile m32 x n16 via m16n8k8.
__device__ __forceinline__ void tgemm_body(
    const float* __restrict__ A, const float* __restrict__ W,
    const float* __restrict__ bias, float* __restrict__ C,
    int N, int K, int relu, int accf, int fin,
    const float* __restrict__ uhpart, const float* __restrict__ rspart,
    const float* __restrict__ wf, const float* __restrict__ bf,
    float (*As)[36], float (*Ws)[36], float* rinv) {
    int tid = threadIdx.x, lane = tid & 31, warp = tid >> 5;
    int m0 = blockIdx.y * 64, n0 = blockIdx.x * 64;
    int wm = (warp >> 2) * 32, wn = (warp & 3) * 16;
    if (fin) {
        if (tid < 64) {
            int m = m0 + tid, b = m / KS, i = m - b * KS;
            float r = 0.f;
#pragma unroll
            for (int t = 0; t < NTP; t++) r += rspart[(b * NTP + t) * KS + i];
            rinv[tid] = __fdividef(1.f, r);
        }
        __syncthreads();
    }
    float D[2][2][4];
#pragma unroll
    for (int x = 0; x < 2; x++)
#pragma unroll
        for (int y = 0; y < 2; y++)
#pragma unroll
            for (int z = 0; z < 4; z++) D[x][y][z] = 0.f;

    for (int k0 = 0; k0 < K; k0 += 32) {
#pragma unroll
        for (int j = 0; j < 2; j++) {
            int idx = tid + j * 256;
            int r = idx >> 3, c = (idx & 7) * 4;
            float4 av;
            if (fin) {
                int m = m0 + r, b = m / KS, i = m - b * KS;
                size_t base = ((size_t)(b * NTP) * KS + i) * DD + k0 + c;
                float4 s0 = *(const float4*)(uhpart + base);
#pragma unroll
                for (int t = 1; t < NTP; t++) {
                    float4 s1 = *(const float4*)(uhpart + base + (size_t)t * KS * DD);
                    s0.x += s1.x; s0.y += s1.y; s0.z += s1.z; s0.w += s1.w;
                }
                float irv = rinv[r];
                float4 w4 = *(const float4*)(wf + k0 + c);
                float4 b4 = *(const float4*)(bf + k0 + c);
                av.x = w4.x * s0.x * irv + b4.x;
                av.y = w4.y * s0.y * irv + b4.y;
                av.z = w4.z * s0.z * irv + b4.z;
                av.w = w4.w * s0.w * irv + b4.w;
            } else {
                av = *(const float4*)(A + (size_t)(m0 + r) * K + k0 + c);
            }
            cvt_tf32_4(av);
            *(float4*)&As[r][c] = av;
            float4 wv = *(const float4*)(W + (size_t)(n0 + r) * K + k0 + c);
            cvt_tf32_4(wv);
            *(float4*)&Ws[r][c] = wv;
        }
        __syncthreads();
#pragma unroll
        for (int ks = 0; ks < 4; ks++) {
            int kk = ks * 8 + (lane & 3);
            int ar = wm + (lane >> 2);
            int br = wn + (lane >> 2);
            unsigned a0 = __float_as_uint(As[ar][kk]);
            unsigned a1 = __float_as_uint(As[ar + 8][kk]);
            unsigned a2 = __float_as_uint(As[ar][kk + 4]);
            unsigned a3 = __float_as_uint(As[ar + 8][kk + 4]);
            unsigned a4 = __float_as_uint(As[ar + 16][kk]);
            unsigned a5 = __float_as_uint(As[ar + 24][kk]);
            unsigned a6 = __float_as_uint(As[ar + 16][kk + 4]);
            unsigned a7 = __float_as_uint(As[ar + 24][kk + 4]);
            unsigned b0 = __float_as_uint(Ws[br][kk]);
            unsigned b1 = __float_as_uint(Ws[br][kk + 4]);
            unsigned b2 = __float_as_uint(Ws[br + 8][kk]);
            unsigned b3 = __float_as_uint(Ws[br + 8][kk + 4]);
            mma_tf32(D[0][0], a0, a1, a2, a3, b0, b1);
            mma_tf32(D[0][1], a0, a1, a2, a3, b2, b3);
            mma_tf32(D[1][0], a4, a5, a6, a7, b0, b1);
            mma_tf32(D[1][1], a4, a5, a6, a7, b2, b3);
        }
        __syncthreads();
    }
#pragma unroll
    for (int mt = 0; mt < 2; mt++) {
#pragma unroll
        for (int nt = 0; nt < 2; nt++) {
            int row = m0 + wm + mt * 16 + (lane >> 2);
            int col = n0 + wn + nt * 8 + (lane & 3) * 2;
            float2 bb = bias ? *(const float2*)(bias + col) : make_float2(0.f, 0.f);
            float2 v0 = make_float2(D[mt][nt][0] + bb.x, D[mt][nt][1] + bb.y);
            float2 v1 = make_float2(D[mt][nt][2] + bb.x, D[mt][nt][3] + bb.y);
            if (relu) {
                v0.x = fmaxf(v0.x, 0.f); v0.y = fmaxf(v0.y, 0.f);
                v1.x = fmaxf(v1.x, 0.f); v1.y = fmaxf(v1.y, 0.f);
            }
            float2* p0 = (float2*)(C + (size_t)row * N + col);
            float2* p1 = (float2*)(C + (size_t)(row + 8) * N + col);
            if (accf) {
                float2 t0 = *p0, t1 = *p1;
                v0.x += t0.x; v0.y += t0.y; v1.x += t1.x; v1.y += t1.y;
            }
            *p0 = v0; *p1 = v1;
        }
    }
}

__global__ void __launch_bounds__(256) k_tgemm(
    const float* __restrict__ A, const float* __restrict__ W,
    const float* __restrict__ bias, float* __restrict__ C,
    int N, int K, int relu, int accf) {
    __shared__ __align__(16) float As[64][36];
    __shared__ __align__(16) float Ws[64][36];
    __shared__ float rinv[64];
    tgemm_body(A, W, bias, C, N, K, relu, accf, 0,
               nullptr, nullptr, nullptr, nullptr, As, Ws, rinv);
}

// z=0: gi = fin(uhpart) @ wihv^T + b_ih ; z=1: gh = slots @ W_hh^T + b_hh
__global__ void __launch_bounds__(256) k_tgemmd(
    const float* __restrict__ uhpart, const float* __restrict__ rspart,
    const float* __restrict__ wf, const float* __restrict__ bf,
    const float* __restrict__ wihv, const float* __restrict__ bih, float* __restrict__ gi,
    const float* __restrict__ slots, const float* __restrict__ Whh,
    const float* __restrict__ bhh, float* __restrict__ gh) {
    __shared__ __align__(16) float As[64][36];
    __shared__ __align__(16) float Ws[64][36];
    __shared__ float rinv[64];
    if (blockIdx.z == 0)
        tgemm_body(nullptr, wihv, bih, gi, 3 * DD, DD, 0, 0, 1,
                   uhpart, rspart, wf, bf, As, Ws, rinv);
    else
        tgemm_body(slots, Whh, bhh, gh, 3 * DD, DD, 0, 0, 0,
                   nullptr, nullptr, nullptr, nullptr, As, Ws, rinv);
}

extern "C" void kernel_launch(void* const* d_in, const int* in_sizes, int n_in,
                              void* d_out, int out_size) {
    const float* inputs     = (const float*)d_in[0];
    const float* slots_init = (const float*)d_in[1];
    const float* ln_f_w = (const float*)d_in[2];
    const float* ln_f_b = (const float*)d_in[3];
    const float* ln_s_w = (const float*)d_in[4];
    const float* ln_s_b = (const float*)d_in[5];
    const float* ln_p_w = (const float*)d_in[6];
    const float* ln_p_b = (const float*)d_in[7];
    const float* Wq  = (const float*)d_in[8];
    const float* Wk  = (const float*)d_in[9];
    const float* Wv  = (const float*)d_in[10];
    const float* W_ih = (const float*)d_in[11];
    const float* b_ih = (const float*)d_in[12];
    const float* W_hh = (const float*)d_in[13];
    const float* b_hh = (const float*)d_in[14];
    const float* W1 = (const float*)d_in[15];
    const float* b1 = (const float*)d_in[16];
    const float* W2 = (const float*)d_in[17];
    const float* b2 = (const float*)d_in[18];
    float* slots = (float*)d_out;

    unsigned short* p_xln;
    float *p_weff, *p_wgv, *p_wihv, *p_cb, *p_qe, *p_uhp, *p_rsp;
    float *p_gi, *p_gh, *p_p, *p_h1;
    cudaGetSymbolAddress((void**)&p_xln, g_xln);
    cudaGetSymbolAddress((void**)&p_weff, g_weff);
    cudaGetSymbolAddress((void**)&p_wgv, g_wgv);
    cudaGetSymbolAddress((void**)&p_wihv, g_wihv);
    cudaGetSymbolAddress((void**)&p_cb, g_cb);
    cudaGetSymbolAddress((void**)&p_qe, g_qe);
    cudaGetSymbolAddress((void**)&p_uhp, g_uhpart);
    cudaGetSymbolAddress((void**)&p_rsp, g_rspart);
    cudaGetSymbolAddress((void**)&p_gi, g_gi);
    cudaGetSymbolAddress((void**)&p_gh, g_gh);
    cudaGetSymbolAddress((void**)&p_p, g_p);
    cudaGetSymbolAddress((void**)&p_h1, g_h1);

    cudaFuncSetAttribute(k_attn, cudaFuncAttributeMaxDynamicSharedMemorySize, ATTN_SMEM);

    cudaMemcpyAsync(slots, slots_init, (size_t)BB * KS * DD * sizeof(float),
                    cudaMemcpyDeviceToDevice);
    k_xln<<<BB * NN / 8, 256>>>(inputs, p_xln);
    k_wprep<<<DD + 1, DD>>>(Wk, Wq, ln_f_w, ln_f_b, ln_s_w, ln_s_b, p_weff, p_wgv);
    k_wihv<<<3 * DD, DD>>>(W_ih, Wv, p_wihv);

    for (int it = 0; it < NITER; it++) {
        k_qeln<<<dim3(4, 11), 256>>>(slots, p_weff, p_wgv, ln_s_w, ln_s_b, p_qe, p_cb);
        k_attn<<<dim3(NTP, BB), 256, ATTN_SMEM>>>((const uint4*)p_xln, p_qe, p_cb,
                                                  p_uhp, p_rsp);
        k_tgemmd<<<dim3(12, 11, 2), 256>>>(p_uhp, p_rsp, ln_f_w, ln_f_b,
                                           p_wihv, b_ih, p_gi, slots, W_hh, b_hh, p_gh);
        k_gruln<<<88, 256>>>(p_gi, p_gh, slots, ln_p_w, ln_p_b, p_p);
        k_tgemm<<<dim3(8, 11), 256>>>(p_p, W1, b1, p_h1, HH, DD, 1, 0);
        k_tgemm<<<dim3(4, 11), 256>>>(p_h1, W2, b2, slots, DD, HH, 0, 1);
    }
}

// round 11
// speedup vs baseline: 2.5915x; 1.0036x over previous
#include <cuda_runtime.h>
#include <cuda_bf16.h>
#include <math.h>
#include <stdint.h>

#define BB 64
#define NN 4096
#define DD 256
#define KS 11
#define HH 512
#define NITER 5
#define EPSF 1e-8f
#define LNEPS 1e-5f
#define SCALEF 0.0625f
#define TILE 128
#define TPB 8
#define NTP (NN/TILE/TPB)   // 4 partials per batch

// ---------------- mma / ldmatrix / cp.async helpers ----------------
__device__ __forceinline__ uint32_t s2u(const void* p) {
    uint32_t a;
    asm("{.reg .u64 t; cvta.to.shared.u64 t, %1; cvt.u32.u64 %0, t;}" : "=r"(a) : "l"(p));
    return a;
}
__device__ __forceinline__ void ldsm4(unsigned& r0, unsigned& r1, unsigned& r2,
                                      unsigned& r3, uint32_t addr) {
    asm volatile("ldmatrix.sync.aligned.m8n8.x4.shared.b16 {%0,%1,%2,%3}, [%4];"
                 : "=r"(r0), "=r"(r1), "=r"(r2), "=r"(r3) : "r"(addr));
}
__device__ __forceinline__ void ldsm4t(unsigned& r0, unsigned& r1, unsigned& r2,
                                       unsigned& r3, uint32_t addr) {
    asm volatile("ldmatrix.sync.aligned.m8n8.x4.trans.shared.b16 {%0,%1,%2,%3}, [%4];"
                 : "=r"(r0), "=r"(r1), "=r"(r2), "=r"(r3) : "r"(addr));
}
__device__ __forceinline__ void mma16816(float* d, unsigned a0, unsigned a1, unsigned a2,
                                         unsigned a3, unsigned b0, unsigned b1) {
    asm volatile("mma.sync.aligned.m16n8k16.row.col.f32.bf16.bf16.f32 "
                 "{%0,%1,%2,%3}, {%4,%5,%6,%7}, {%8,%9}, {%0,%1,%2,%3};"
                 : "+f"(d[0]), "+f"(d[1]), "+f"(d[2]), "+f"(d[3])
                 : "r"(a0), "r"(a1), "r"(a2), "r"(a3), "r"(b0), "r"(b1));
}
__device__ __forceinline__ void mma_tf32(float* d, unsigned a0, unsigned a1, unsigned a2,
                                         unsigned a3, unsigned b0, unsigned b1) {
    asm volatile("mma.sync.aligned.m16n8k8.row.col.f32.tf32.tf32.f32 "
                 "{%0,%1,%2,%3}, {%4,%5,%6,%7}, {%8,%9}, {%0,%1,%2,%3};"
                 : "+f"(d[0]), "+f"(d[1]), "+f"(d[2]), "+f"(d[3])
                 : "r"(a0), "r"(a1), "r"(a2), "r"(a3), "r"(b0), "r"(b1));
}
__device__ __forceinline__ void cvt_tf32_4(float4& v) {
    unsigned x;
    asm("cvt.rna.tf32.f32 %0, %1;" : "=r"(x) : "f"(v.x)); v.x = __uint_as_float(x);
    asm("cvt.rna.tf32.f32 %0, %1;" : "=r"(x) : "f"(v.y)); v.y = __uint_as_float(x);
    asm("cvt.rna.tf32.f32 %0, %1;" : "=r"(x) : "f"(v.z)); v.z = __uint_as_float(x);
    asm("cvt.rna.tf32.f32 %0, %1;" : "=r"(x) : "f"(v.w)); v.w = __uint_as_float(x);
}
__device__ __forceinline__ void cpasync16(uint32_t saddr, const void* gaddr) {
    asm volatile("cp.async.cg.shared.global [%0], [%1], 16;" :: "r"(saddr), "l"(gaddr));
}
__device__ __forceinline__ void cpcommit() {
    asm volatile("cp.async.commit_group;");
}
template <int N>
__device__ __forceinline__ void cpwait() {
    asm volatile("cp.async.wait_group %0;" :: "n"(N));
}

// ---------------- scratch ----------------
__device__ __align__(16) unsigned short g_xln[BB*NN*DD];
__device__ __align__(16) unsigned g_weffh[DD*128];       // weff in bf16 pairs [d][t/2]
__device__ float g_wgv[DD + 2];
__device__ float g_wihv[3*DD*DD];
__device__ float g_cb[BB*KS];
__device__ __align__(16) unsigned short g_slnh[BB*KS*DD];
__device__ __align__(16) unsigned g_qeh[BB*KS*128];      // qe in bf16 pairs
__device__ float g_uhpart[BB*NTP*KS*DD];
__device__ float g_rspart[BB*NTP*KS];
__device__ float g_gi[BB*KS*3*DD];
__device__ float g_gh[BB*KS*3*DD];
__device__ float g_p[BB*KS*DD];
__device__ float g_h1[BB*KS*HH];

// ---------------- xln = (x-mean)*rstd in bf16 (once) ----------------
__global__ void k_xln(const float* __restrict__ X, unsigned short* __restrict__ out) {
    int row = blockIdx.x * 8 + (threadIdx.x >> 5);
    int lane = threadIdx.x & 31;
    const float4* p = (const float4*)(X + (size_t)row * DD);
    float4 v0 = p[lane * 2], v1 = p[lane * 2 + 1];
    float s  = v0.x + v0.y + v0.z + v0.w + v1.x + v1.y + v1.z + v1.w;
    float s2 = v0.x*v0.x + v0.y*v0.y + v0.z*v0.z + v0.w*v0.w
             + v1.x*v1.x + v1.y*v1.y + v1.z*v1.z + v1.w*v1.w;
#pragma unroll
    for (int o = 16; o; o >>= 1) {
        s  += __shfl_xor_sync(0xffffffffu, s,  o);
        s2 += __shfl_xor_sync(0xffffffffu, s2, o);
    }
    float m = s * (1.0f / DD);
    float var = s2 * (1.0f / DD) - m * m;
    float r = rsqrtf(var + LNEPS);
    __nv_bfloat162 h0 = __float22bfloat162_rn(make_float2((v0.x-m)*r, (v0.y-m)*r));
    __nv_bfloat162 h1 = __float22bfloat162_rn(make_float2((v0.z-m)*r, (v0.w-m)*r));
    __nv_bfloat162 h2 = __float22bfloat162_rn(make_float2((v1.x-m)*r, (v1.y-m)*r));
    __nv_bfloat162 h3 = __float22bfloat162_rn(make_float2((v1.z-m)*r, (v1.w-m)*r));
    uint4 o;
    o.x = *(unsigned int*)&h0; o.y = *(unsigned int*)&h1;
    o.z = *(unsigned int*)&h2; o.w = *(unsigned int*)&h3;
    ((uint4*)(out + (size_t)row * DD))[lane] = o;
}

// ---------------- wprep: weff (bf16) rows + gv/consts ----------------
__global__ void k_wprep(const float* __restrict__ Wk, const float* __restrict__ Wq,
                        const float* __restrict__ wf, const float* __restrict__ bf,
                        const float* __restrict__ ws, const float* __restrict__ bs,
                        unsigned* __restrict__ weffh, float* __restrict__ wgv) {
    __shared__ float col[DD];
    __shared__ float rowo[DD];
    __shared__ float red[8];
    int t = threadIdx.x;
    if (blockIdx.x < DD) {
        int d = blockIdx.x;
        col[t] = Wk[t * DD + d];
        __syncthreads();
        float acc = 0.f;
        for (int s = 0; s < DD; s++) acc = fmaf(col[s], Wq[s * DD + t], acc);
        rowo[t] = acc * wf[d];
        __syncthreads();
        if (t < 128) {
            __nv_bfloat162 h = __float22bfloat162_rn(make_float2(rowo[2*t], rowo[2*t+1]));
            weffh[d * 128 + t] = *(unsigned*)&h;
        }
    } else {
        float a = 0.f;
        for (int e = 0; e < DD; e++) a = fmaf(Wk[t * DD + e], bf[e], a);
        col[t] = a;
        __syncthreads();
        float gv = 0.f;
        for (int s = 0; s < DD; s++) gv = fmaf(Wq[s * DD + t], col[s], gv);
        float w = ws[t] * gv;
        wgv[t] = w;
        float c1 = w, c0 = bs[t] * gv;
        int lane = t & 31, warp = t >> 5;
#pragma unroll
        for (int o = 16; o; o >>= 1) {
            c1 += __shfl_xor_sync(0xffffffffu, c1, o);
            c0 += __shfl_xor_sync(0xffffffffu, c0, o);
        }
        __syncthreads();
        if (lane == 0) red[warp] = c1;
        __syncthreads();
        if (t == 0) {
            float s1 = 0.f;
            for (int i = 0; i < 8; i++) s1 += red[i];
            wgv[DD] = s1;
        }
        __syncthreads();
        if (lane == 0) red[warp] = c0;
        __syncthreads();
        if (t == 1) {
            float s0 = 0.f;
            for (int i = 0; i < 8; i++) s0 += red[i];
            wgv[DD + 1] = s0;
        }
    }
}

// ---------------- wihv[m][e] = sum_j W_ih[m,j] * Wv[j,e] (once) ----------------
__global__ void k_wihv(const float* __restrict__ Wih, const float* __restrict__ Wv,
                       float* __restrict__ out) {
    __shared__ float row[DD];
    int m = blockIdx.x, t = threadIdx.x;
    row[t] = Wih[m * DD + t];
    __syncthreads();
    float acc = 0.f;
#pragma unroll 4
    for (int j = 0; j < DD; j++) acc = fmaf(row[j], Wv[j * DD + t], acc);
    out[m * DD + t] = acc;
}

// ---------------- k_snb: sln = LN_s(slots) in bf16, cb (warp per row) ----------------
__global__ void k_snb(const float* __restrict__ slots, const float* __restrict__ wgv,
                      const float* __restrict__ lsw, const float* __restrict__ lsb,
                      unsigned short* __restrict__ slnh, float* __restrict__ cb) {
    int row = blockIdx.x * 8 + (threadIdx.x >> 5);
    int lane = threadIdx.x & 31;
    const float4* p = (const float4*)(slots + (size_t)row * DD);
    float4 v0 = p[lane * 2], v1 = p[lane * 2 + 1];
    float4 wg0 = *(const float4*)(wgv + lane * 8);
    float4 wg1 = *(const float4*)(wgv + lane * 8 + 4);
    float s  = v0.x + v0.y + v0.z + v0.w + v1.x + v1.y + v1.z + v1.w;
    float s2 = v0.x*v0.x + v0.y*v0.y + v0.z*v0.z + v0.w*v0.w
             + v1.x*v1.x + v1.y*v1.y + v1.z*v1.z + v1.w*v1.w;
    float s3 = v0.x*wg0.x + v0.y*wg0.y + v0.z*wg0.z + v0.w*wg0.w
             + v1.x*wg1.x + v1.y*wg1.y + v1.z*wg1.z + v1.w*wg1.w;
#pragma unroll
    for (int o = 16; o; o >>= 1) {
        s  += __shfl_xor_sync(0xffffffffu, s,  o);
        s2 += __shfl_xor_sync(0xffffffffu, s2, o);
        s3 += __shfl_xor_sync(0xffffffffu, s3, o);
    }
    float m = s * (1.0f / DD);
    float var = s2 * (1.0f / DD) - m * m;
    float r = rsqrtf(var + LNEPS);
    if (lane == 0) cb[row] = r * s3 - r * m * wgv[DD] + wgv[DD + 1];
    float4 w0 = *(const float4*)(lsw + lane * 8), w1 = *(const float4*)(lsw + lane * 8 + 4);
    float4 b0 = *(const float4*)(lsb + lane * 8), b1 = *(const float4*)(lsb + lane * 8 + 4);
    __nv_bfloat162 h0 = __float22bfloat162_rn(
        make_float2((v0.x-m)*r*w0.x + b0.x, (v0.y-m)*r*w0.y + b0.y));
    __nv_bfloat162 h1 = __float22bfloat162_rn(
        make_float2((v0.z-m)*r*w0.z + b0.z, (v0.w-m)*r*w0.w + b0.w));
    __nv_bfloat162 h2 = __float22bfloat162_rn(
        make_float2((v1.x-m)*r*w1.x + b1.x, (v1.y-m)*r*w1.y + b1.y));
    __nv_bfloat162 h3 = __float22bfloat162_rn(
        make_float2((v1.z-m)*r*w1.z + b1.z, (v1.w-m)*r*w1.w + b1.w));
    uint4 o;
    o.x = *(unsigned*)&h0; o.y = *(unsigned*)&h1;
    o.z = *(unsigned*)&h2; o.w = *(unsigned*)&h3;
    ((uint4*)(slnh + (size_t)row * DD))[lane] = o;
}

// ---------------- k_bgemm: qe(bf16) = sln(bf16) @ weff(bf16)^T, tensor cores ----------------
// 64x64 tile, 8 warps (4m x 2n), warp m16 x n32. A[m][k], B[n][k] both K-major bf16.
__global__ void __launch_bounds__(256) k_bgemm(
    const unsigned short* __restrict__ A, const unsigned short* __restrict__ Bw,
    unsigned* __restrict__ C) {
    __shared__ __align__(16) unsigned short As[64 * 72];
    __shared__ __align__(16) unsigned short Ws[64 * 72];
    uint32_t sa = s2u(As), sw = s2u(Ws);
    int tid = threadIdx.x, lane = tid & 31, warp = tid >> 5;
    int m0 = blockIdx.y * 64, n0 = blockIdx.x * 64;
    int wm = (warp >> 1) * 16, wn = (warp & 1) * 32;
    float D[4][4];
#pragma unroll
    for (int i = 0; i < 4; i++)
#pragma unroll
        for (int j = 0; j < 4; j++) D[i][j] = 0.f;
    int g8  = (lane & 8)  ? 1 : 0;
    int g16 = (lane & 16) ? 1 : 0;
    uint32_t aAddr  = sa + (wm + (lane & 7) + g8 * 8) * 144 + g16 * 16;
    uint32_t bAddr0 = sw + (wn + (lane & 7) + g16 * 8) * 144 + g8 * 16;
    uint32_t bAddr1 = bAddr0 + 16 * 144;

    for (int k0 = 0; k0 < DD; k0 += 64) {
#pragma unroll
        for (int j = 0; j < 2; j++) {
            int idx = tid + j * 256;
            int r = idx >> 3, c = idx & 7;
            *(uint4*)((char*)As + r * 144 + c * 16) =
                *(const uint4*)(A + (size_t)(m0 + r) * DD + k0 + c * 8);
            *(uint4*)((char*)Ws + r * 144 + c * 16) =
                *(const uint4*)(Bw + (size_t)(n0 + r) * DD + k0 + c * 8);
        }
        __syncthreads();
#pragma unroll
        for (int kc = 0; kc < 4; kc++) {
            unsigned a0, a1, a2, a3, b0, b1, b2, b3, c0, c1, c2, c3;
            ldsm4(a0, a1, a2, a3, aAddr + kc * 32);
            ldsm4(b0, b1, b2, b3, bAddr0 + kc * 32);
            ldsm4(c0, c1, c2, c3, bAddr1 + kc * 32);
            mma16816(D[0], a0, a1, a2, a3, b0, b1);
            mma16816(D[1], a0, a1, a2, a3, b2, b3);
            mma16816(D[2], a0, a1, a2, a3, c0, c1);
            mma16816(D[3], a0, a1, a2, a3, c2, c3);
        }
        __syncthreads();
    }
    int row = m0 + wm + (lane >> 2);
#pragma unroll
    for (int nt = 0; nt < 4; nt++) {
        int col = n0 + wn + nt * 8 + (lane & 3) * 2;
        __nv_bfloat162 h0 = __float22bfloat162_rn(make_float2(D[nt][0], D[nt][1]));
        __nv_bfloat162 h1 = __float22bfloat162_rn(make_float2(D[nt][2], D[nt][3]));
        C[(size_t)row * 128 + (col >> 1)]       = *(unsigned*)&h0;
        C[(size_t)(row + 8) * 128 + (col >> 1)] = *(unsigned*)&h1;
    }
}

// ---------------- fused attention: tensor-core, single buffer, 2 blocks/SM ----------------
#define OFF_X   0
#define OFF_QP  67584
#define OFF_LS  76032
#define OFF_AS  85248
#define OFF_RSW 91392
#define OFF_CBS 91648
#define ATTN_SMEM 91712

__global__ void __launch_bounds__(256, 2) k_attn(
    const uint4* __restrict__ xln, const unsigned* __restrict__ qeh,
    const float* __restrict__ cb, float* __restrict__ uhpart,
    float* __restrict__ rspart) {
    extern __shared__ char sm[];
    uint32_t sb = s2u(sm);
    float* Ls  = (float*)(sm + OFF_LS);
    float* rsw = (float*)(sm + OFF_RSW);
    float* cbs = (float*)(sm + OFF_CBS);

    int bx = blockIdx.x, b = blockIdx.y;
    int tid = threadIdx.x, lane = tid & 31, warp = tid >> 5;

    // stage Qp (bf16 copy, padded slots zero) + cbs
    for (int i = tid; i < 16 * 128; i += 256) {
        int slot = i >> 7, dp = i & 127;
        unsigned v = (slot < KS) ? qeh[((size_t)b * KS + slot) * 128 + dp] : 0u;
        *(unsigned*)(sm + OFF_QP + slot * 528 + dp * 4) = v;
    }
    if (tid < 16) cbs[tid] = (tid < KS) ? cb[b * KS + tid] : 0.f;

    const uint4* Xg = xln + (size_t)b * NN * (DD / 8);

    float rsl[KS];
    float uacc[4][4];
#pragma unroll
    for (int i = 0; i < KS; i++) rsl[i] = 0.f;
#pragma unroll
    for (int i = 0; i < 4; i++)
#pragma unroll
        for (int j = 0; j < 4; j++) uacc[i][j] = 0.f;

    int g8  = (lane & 8)  ? 1 : 0;
    int g16 = (lane & 16) ? 1 : 0;
    uint32_t dA = sb + OFF_X + ((warp * 16) + (lane & 7) + g8 * 8) * 528 + g16 * 16;
    uint32_t dB = sb + OFF_QP + ((lane & 7) + g16 * 8) * 528 + g8 * 16;
    uint32_t aA = sb + OFF_AS + ((lane & 7) + g16 * 8) * 48 + g8 * 16;
    int d0w = warp * 32;
    uint32_t aB = sb + OFF_X + ((lane & 7) + g8 * 8) * 528 + d0w * 2 + g16 * 16;

    for (int t = 0; t < TPB; t++) {
        {
            int row0 = (bx * TPB + t) * TILE;
#pragma unroll
            for (int k = 0; k < 16; k++) {
                int idx = tid + k * 256;
                int r = idx >> 5, c = idx & 31;
                cpasync16(sb + OFF_X + r * 528 + c * 16,
                          (const void*)(Xg + (size_t)(row0 + r) * 32 + c));
            }
            cpcommit();
            cpwait<0>();
        }
        __syncthreads();

        // ---- dots via mma ----
        {
            float D0[4] = {0.f, 0.f, 0.f, 0.f}, D1[4] = {0.f, 0.f, 0.f, 0.f};
#pragma unroll
            for (int kc = 0; kc < 16; kc++) {
                unsigned a0, a1, a2, a3, b0, b1, b2, b3;
                ldsm4(a0, a1, a2, a3, dA + kc * 32);
                ldsm4(b0, b1, b2, b3, dB + kc * 32);
                mma16816(D0, a0, a1, a2, a3, b0, b1);
                mma16816(D1, a0, a1, a2, a3, b2, b3);
            }
            int lr = warp * 16 + (lane >> 2), lc = (lane & 3) * 2;
            *(float2*)(Ls + lr * 18 + lc)           = make_float2(D0[0], D0[1]);
            *(float2*)(Ls + (lr + 8) * 18 + lc)     = make_float2(D0[2], D0[3]);
            *(float2*)(Ls + lr * 18 + 8 + lc)       = make_float2(D1[0], D1[1]);
            *(float2*)(Ls + (lr + 8) * 18 + 8 + lc) = make_float2(D1[2], D1[3]);
        }
        __syncthreads();

        // ---- softmax: thread-per-row ----
        if (tid < TILE) {
            const float* lr = Ls + tid * 18;
            float l[KS];
#pragma unroll
            for (int i = 0; i < KS; i++) l[i] = (lr[i] + cbs[i]) * SCALEF;
            float mx = l[0];
#pragma unroll
            for (int i = 1; i < KS; i++) mx = fmaxf(mx, l[i]);
            float se = 0.f;
#pragma unroll
            for (int i = 0; i < KS; i++) { float e = __expf(l[i] - mx); l[i] = e; se += e; }
            float inv = __fdividef(1.0f, se);
            float a16[16];
#pragma unroll
            for (int i = 0; i < 16; i++) a16[i] = 0.f;
#pragma unroll
            for (int i = 0; i < KS; i++) {
                float a = fmaf(l[i], inv, EPSF);
                a16[i] = a; rsl[i] += a;
            }
            unsigned* dst = (unsigned*)(sm + OFF_AS + tid * 48);
#pragma unroll
            for (int p = 0; p < 8; p++) {
                __nv_bfloat162 h = __float22bfloat162_rn(make_float2(a16[2*p], a16[2*p+1]));
                dst[p] = *(unsigned*)&h;
            }
        }
        __syncthreads();

        // ---- accum via mma ----
        {
#pragma unroll
            for (int kr = 0; kr < 8; kr++) {
                unsigned p0, p1, p2, p3, x0, x1, x2, x3, y0, y1, y2, y3;
                ldsm4t(p0, p1, p2, p3, aA + kr * (16 * 48));
                ldsm4t(x0, x1, x2, x3, aB + kr * (16 * 528));
                ldsm4t(y0, y1, y2, y3, aB + kr * (16 * 528) + 32);
                mma16816(uacc[0], p0, p1, p2, p3, x0, x1);
                mma16816(uacc[1], p0, p1, p2, p3, x2, x3);
                mma16816(uacc[2], p0, p1, p2, p3, y0, y1);
                mma16816(uacc[3], p0, p1, p2, p3, y2, y3);
            }
        }
        __syncthreads();
    }

    // ---- write U fragments directly to global partials ----
    {
        float* up = uhpart + ((size_t)(b * NTP + bx)) * KS * DD;
        int slot = lane >> 2, dp = (lane & 3) * 2;
#pragma unroll
        for (int nt = 0; nt < 4; nt++) {
            int d = d0w + nt * 8 + dp;
            *(float2*)(up + slot * DD + d) = make_float2(uacc[nt][0], uacc[nt][1]);
            if (slot + 8 < KS)
                *(float2*)(up + (slot + 8) * DD + d) = make_float2(uacc[nt][2], uacc[nt][3]);
        }
    }
    if (tid < TILE) {
#pragma unroll
        for (int i = 0; i < KS; i++) {
#pragma unroll
            for (int o = 16; o; o >>= 1) rsl[i] += __shfl_xor_sync(0xffffffffu, rsl[i], o);
        }
        if (lane == 0) {
#pragma unroll
            for (int i = 0; i < KS; i++) rsw[warp * 16 + i] = rsl[i];
        }
    }
    __syncthreads();
    if (tid < KS)
        rspart[(size_t)(b * NTP + bx) * KS + tid] =
            rsw[tid] + rsw[16 + tid] + rsw[32 + tid] + rsw[48 + tid];
}

// ---------------- fused GRU + LN_p: warp per row ----------------
__global__ void k_gruln(const float* __restrict__ gi, const float* __restrict__ gh,
                        float* __restrict__ slots, const float* __restrict__ wp,
                        const float* __restrict__ bp, float* __restrict__ p) {
    int m = blockIdx.x * 8 + (threadIdx.x >> 5);
    int lane = threadIdx.x & 31;
    int d0 = lane * 8;
    const float* gim = gi + (size_t)m * 3 * DD;
    const float* ghm = gh + (size_t)m * 3 * DD;
    float ir[8], iz[8], in_[8], hr[8], hz[8], hn[8], sp[8], v[8];
    *(float4*)ir   = *(const float4*)(gim + d0);       *(float4*)(ir+4)  = *(const float4*)(gim + d0 + 4);
    *(float4*)iz   = *(const float4*)(gim + DD + d0);  *(float4*)(iz+4)  = *(const float4*)(gim + DD + d0 + 4);
    *(float4*)in_  = *(const float4*)(gim + 2*DD + d0);*(float4*)(in_+4) = *(const float4*)(gim + 2*DD + d0 + 4);
    *(float4*)hr   = *(const float4*)(ghm + d0);       *(float4*)(hr+4)  = *(const float4*)(ghm + d0 + 4);
    *(float4*)hz   = *(const float4*)(ghm + DD + d0);  *(float4*)(hz+4)  = *(const float4*)(ghm + DD + d0 + 4);
    *(float4*)hn   = *(const float4*)(ghm + 2*DD + d0);*(float4*)(hn+4)  = *(const float4*)(ghm + 2*DD + d0 + 4);
    *(float4*)sp   = *(const float4*)(slots + (size_t)m*DD + d0);
    *(float4*)(sp+4) = *(const float4*)(slots + (size_t)m*DD + d0 + 4);
    float s = 0.f, s2 = 0.f;
#pragma unroll
    for (int j = 0; j < 8; j++) {
        float r = 1.0f / (1.0f + __expf(-(ir[j] + hr[j])));
        float z = 1.0f / (1.0f + __expf(-(iz[j] + hz[j])));
        float n = tanhf(in_[j] + r * hn[j]);
        float vv = (1.0f - z) * n + z * sp[j];
        v[j] = vv; s += vv; s2 += vv * vv;
    }
#pragma unroll
    for (int o = 16; o; o >>= 1) {
        s  += __shfl_xor_sync(0xffffffffu, s,  o);
        s2 += __shfl_xor_sync(0xffffffffu, s2, o);
    }
    float mm = s * (1.0f / DD);
    float var = s2 * (1.0f / DD) - mm * mm;
    float rr = rsqrtf(var + LNEPS);
    *(float4*)(slots + (size_t)m*DD + d0)     = *(float4*)v;
    *(float4*)(slots + (size_t)m*DD + d0 + 4) = *(float4*)(v+4);
    float w_[8], b_[8], pv[8];
    *(float4*)w_ = *(const float4*)(wp + d0); *(float4*)(w_+4) = *(const float4*)(wp + d0 + 4);
    *(float4*)b_ = *(const float4*)(bp + d0); *(float4*)(b_+4) = *(const float4*)(bp + d0 + 4);
#pragma unroll
    for (int j = 0; j < 8; j++) pv[j] = (v[j] - mm) * rr * w_[j] + b_[j];
    *(float4*)(p + (size_t)m*DD + d0)     = *(float4*)pv;
    *(float4*)(p + (size_t)m*DD + d0 + 4) = *(float4*)(pv+4);
}

// ---------------- 3xTF32 tensor GEMM: C[m][n] = sum_k A[m][k]*W[n][k] ----------------
__device__ __forceinline__ void tgemm_body(
    const float* __restrict__ A, const float* __restrict__ W,
    const float* __restrict__ bias, float* __restrict__ C,
    int N, int K, int relu, int accf, int fin,
    const float* __restrict__ uhpart, const float* __restrict__ rspart,
    const float* __restrict__ wf, const float* __restrict__ bf,
    float (*Ah)[36], float (*Al)[36], float (*Wh)[36], float (*Wl)[36], float* rinv) {
    int tid = threadIdx.x, lane = tid & 31, warp = tid >> 5;
    int m0 = blockIdx.y * 64, n0 = blockIdx.x * 64;
    int wm = (warp >> 2) * 32, wn = (warp & 3) * 16;
    if (fin) {
        if (tid < 64) {
            int m = m0 + tid, b = m / KS, i = m - b * KS;
            float r = 0.f;
#pragma unroll
            for (int t = 0; t < NTP; t++) r += rspart[(b * NTP + t) * KS + i];
            rinv[tid] = __fdividef(1.f, r);
        }
        __syncthreads();
    }
    float D[2][2][4];
#pragma unroll
    for (int x = 0; x < 2; x++)
#pragma unroll
        for (int y = 0; y < 2; y++)
#pragma unroll
            for (int z = 0; z < 4; z++) D[x][y][z] = 0.f;

    for (int k0 = 0; k0 < K; k0 += 32) {
#pragma unroll
        for (int j = 0; j < 2; j++) {
            int idx = tid + j * 256;
            int r = idx >> 3, c = (idx & 7) * 4;
            float4 av;
            if (fin) {
                int m = m0 + r, b = m / KS, i = m - b * KS;
                size_t base = ((size_t)(b * NTP) * KS + i) * DD + k0 + c;
                float4 s0 = *(const float4*)(uhpart + base);
#pragma unroll
                for (int t = 1; t < NTP; t++) {
                    float4 s1 = *(const float4*)(uhpart + base + (size_t)t * KS * DD);
                    s0.x += s1.x; s0.y += s1.y; s0.z += s1.z; s0.w += s1.w;
                }
                float irv = rinv[r];
                float4 w4 = *(const float4*)(wf + k0 + c);
                float4 b4 = *(const float4*)(bf + k0 + c);
                av.x = w4.x * s0.x * irv + b4.x;
                av.y = w4.y * s0.y * irv + b4.y;
                av.z = w4.z * s0.z * irv + b4.z;
                av.w = w4.w * s0.w * irv + b4.w;
            } else {
                av = *(const float4*)(A + (size_t)(m0 + r) * K + k0 + c);
            }
            float4 ah = av; cvt_tf32_4(ah);
            float4 al = make_float4(av.x - ah.x, av.y - ah.y, av.z - ah.z, av.w - ah.w);
            cvt_tf32_4(al);
            *(float4*)&Ah[r][c] = ah;
            *(float4*)&Al[r][c] = al;
            float4 wv = *(const float4*)(W + (size_t)(n0 + r) * K + k0 + c);
            float4 wh = wv; cvt_tf32_4(wh);
            float4 wl = make_float4(wv.x - wh.x, wv.y - wh.y, wv.z - wh.z, wv.w - wh.w);
            cvt_tf32_4(wl);
            *(float4*)&Wh[r][c] = wh;
            *(float4*)&Wl[r][c] = wl;
        }
        __syncthreads();
#pragma unroll
        for (int ks = 0; ks < 4; ks++) {
            int kk = ks * 8 + (lane & 3);
            int ar = wm + (lane >> 2);
            int br = wn + (lane >> 2);
            unsigned ah0 = __float_as_uint(Ah[ar][kk]);
            unsigned ah1 = __float_as_uint(Ah[ar + 8][kk]);
            unsigned ah2 = __float_as_uint(Ah[ar][kk + 4]);
            unsigned ah3 = __float_as_uint(Ah[ar + 8][kk + 4]);
            unsigned ah4 = __float_as_uint(Ah[ar + 16][kk]);
            unsigned ah5 = __float_as_uint(Ah[ar + 24][kk]);
            unsigned ah6 = __float_as_uint(Ah[ar + 16][kk + 4]);
            unsigned ah7 = __float_as_uint(Ah[ar + 24][kk + 4]);
            unsigned al0 = __float_as_uint(Al[ar][kk]);
            unsigned al1 = __float_as_uint(Al[ar + 8][kk]);
            unsigned al2 = __float_as_uint(Al[ar][kk + 4]);
            unsigned al3 = __float_as_uint(Al[ar + 8][kk + 4]);
            unsigned al4 = __float_as_uint(Al[ar + 16][kk]);
            unsigned al5 = __float_as_uint(Al[ar + 24][kk]);
            unsigned al6 = __float_as_uint(Al[ar + 16][kk + 4]);
            unsigned al7 = __float_as_uint(Al[ar + 24][kk + 4]);
            unsigned bh0 = __float_as_uint(Wh[br][kk]);
            unsigned bh1 = __float_as_uint(Wh[br][kk + 4]);
            unsigned bh2 = __float_as_uint(Wh[br + 8][kk]);
            unsigned bh3 = __float_as_uint(Wh[br + 8][kk + 4]);
            unsigned bl0 = __float_as_uint(Wl[br][kk]);
            unsigned bl1 = __float_as_uint(Wl[br][kk + 4]);
            unsigned bl2 = __float_as_uint(Wl[br + 8][kk]);
            unsigned bl3 = __float_as_uint(Wl[br + 8][kk + 4]);
            mma_tf32(D[0][0], ah0, ah1, ah2, ah3, bl0, bl1);
            mma_tf32(D[0][0], al0, al1, al2, al3, bh0, bh1);
            mma_tf32(D[0][0], ah0, ah1, ah2, ah3, bh0, bh1);
            mma_tf32(D[0][1], ah0, ah1, ah2, ah3, bl2, bl3);
            mma_tf32(D[0][1], al0, al1, al2, al3, bh2, bh3);
            mma_tf32(D[0][1], ah0, ah1, ah2, ah3, bh2, bh3);
            mma_tf32(D[1][0], ah4, ah5, ah6, ah7, bl0, bl1);
            mma_tf32(D[1][0], al4, al5, al6, al7, bh0, bh1);
            mma_tf32(D[1][0], ah4, ah5, ah6, ah7, bh0, bh1);
            mma_tf32(D[1][1], ah4, ah5, ah6, ah7, bl2, bl3);
            mma_tf32(D[1][1], al4, al5, al6, al7, bh2, bh3);
            mma_tf32(D[1][1], ah4, ah5, ah6, ah7, bh2, bh3);
        }
        __syncthreads();
    }
#pragma unroll
    for (int mt = 0; mt < 2; mt++) {
#pragma unroll
        for (int nt = 0; nt < 2; nt++) {
            int row = m0 + wm + mt * 16 + (lane >> 2);
            int col = n0 + wn + nt * 8 + (lane & 3) * 2;
            float2 bb = bias ? *(const float2*)(bias + col) : make_float2(0.f, 0.f);
            float2 v0 = make_float2(D[mt][nt][0] + bb.x, D[mt][nt][1] + bb.y);
            float2 v1 = make_float2(D[mt][nt][2] + bb.x, D[mt][nt][3] + bb.y);
            if (relu) {
                v0.x = fmaxf(v0.x, 0.f); v0.y = fmaxf(v0.y, 0.f);
                v1.x = fmaxf(v1.x, 0.f); v1.y = fmaxf(v1.y, 0.f);
            }
            float2* p0 = (float2*)(C + (size_t)row * N + col);
            float2* p1 = (float2*)(C + (size_t)(row + 8) * N + col);
            if (accf) {
                float2 t0 = *p0, t1 = *p1;
                v0.x += t0.x; v0.y += t0.y; v1.x += t1.x; v1.y += t1.y;
            }
            *p0 = v0; *p1 = v1;
        }
    }
}

__global__ void __launch_bounds__(256) k_tgemm(
    const float* __restrict__ A, const float* __restrict__ W,
    const float* __restrict__ bias, float* __restrict__ C,
    int N, int K, int relu, int accf) {
    __shared__ __align__(16) float Ah[64][36], Al[64][36], Wh[64][36], Wl[64][36];
    __shared__ float rinv[64];
    tgemm_body(A, W, bias, C, N, K, relu, accf, 0,
               nullptr, nullptr, nullptr, nullptr, Ah, Al, Wh, Wl, rinv);
}

__global__ void __launch_bounds__(256) k_tgemmd(
    const float* __restrict__ uhpart, const float* __restrict__ rspart,
    const float* __restrict__ wf, const float* __restrict__ bf,
    const float* __restrict__ wihv, const float* __restrict__ bih, float* __restrict__ gi,
    const float* __restrict__ slots, const float* __restrict__ Whh,
    const float* __restrict__ bhh, float* __restrict__ gh) {
    __shared__ __align__(16) float Ah[64][36], Al[64][36], Wh[64][36], Wl[64][36];
    __shared__ float rinv[64];
    if (blockIdx.z == 0)
        tgemm_body(nullptr, wihv, bih, gi, 3 * DD, DD, 0, 0, 1,
                   uhpart, rspart, wf, bf, Ah, Al, Wh, Wl, rinv);
    else
        tgemm_body(slots, Whh, bhh, gh, 3 * DD, DD, 0, 0, 0,
                   nullptr, nullptr, nullptr, nullptr, Ah, Al, Wh, Wl, rinv);
}

extern "C" void kernel_launch(void* const* d_in, const int* in_sizes, int n_in,
                              void* d_out, int out_size) {
    const float* inputs     = (const float*)d_in[0];
    const float* slots_init = (const float*)d_in[1];
    const float* ln_f_w = (const float*)d_in[2];
    const float* ln_f_b = (const float*)d_in[3];
    const float* ln_s_w = (const float*)d_in[4];
    const float* ln_s_b = (const float*)d_in[5];
    const float* ln_p_w = (const float*)d_in[6];
    const float* ln_p_b = (const float*)d_in[7];
    const float* Wq  = (const float*)d_in[8];
    const float* Wk  = (const float*)d_in[9];
    const float* Wv  = (const float*)d_in[10];
    const float* W_ih = (const float*)d_in[11];
    const float* b_ih = (const float*)d_in[12];
    const float* W_hh = (const float*)d_in[13];
    const float* b_hh = (const float*)d_in[14];
    const float* W1 = (const float*)d_in[15];
    const float* b1 = (const float*)d_in[16];
    const float* W2 = (const float*)d_in[17];
    const float* b2 = (const float*)d_in[18];
    float* slots = (float*)d_out;

    unsigned short *p_xln, *p_slnh;
    unsigned *p_weffh, *p_qeh;
    float *p_wgv, *p_wihv, *p_cb, *p_uhp, *p_rsp;
    float *p_gi, *p_gh, *p_p, *p_h1;
    cudaGetSymbolAddress((void**)&p_xln, g_xln);
    cudaGetSymbolAddress((void**)&p_weffh, g_weffh);
    cudaGetSymbolAddress((void**)&p_wgv, g_wgv);
    cudaGetSymbolAddress((void**)&p_wihv, g_wihv);
    cudaGetSymbolAddress((void**)&p_cb, g_cb);
    cudaGetSymbolAddress((void**)&p_slnh, g_slnh);
    cudaGetSymbolAddress((void**)&p_qeh, g_qeh);
    cudaGetSymbolAddress((void**)&p_uhp, g_uhpart);
    cudaGetSymbolAddress((void**)&p_rsp, g_rspart);
    cudaGetSymbolAddress((void**)&p_gi, g_gi);
    cudaGetSymbolAddress((void**)&p_gh, g_gh);
    cudaGetSymbolAddress((void**)&p_p, g_p);
    cudaGetSymbolAddress((void**)&p_h1, g_h1);

    cudaFuncSetAttribute(k_attn, cudaFuncAttributeMaxDynamicSharedMemorySize, ATTN_SMEM);

    cudaMemcpyAsync(slots, slots_init, (size_t)BB * KS * DD * sizeof(float),
                    cudaMemcpyDeviceToDevice);
    k_xln<<<BB * NN / 8, 256>>>(inputs, p_xln);
    k_wprep<<<DD + 1, DD>>>(Wk, Wq, ln_f_w, ln_f_b, ln_s_w, ln_s_b, p_weffh, p_wgv);
    k_wihv<<<3 * DD, DD>>>(W_ih, Wv, p_wihv);

    for (int it = 0; it < NITER; it++) {
        k_snb<<<88, 256>>>(slots, p_wgv, ln_s_w, ln_s_b, p_slnh, p_cb);
        k_bgemm<<<dim3(4, 11), 256>>>(p_slnh, (const unsigned short*)p_weffh, p_qeh);
        k_attn<<<dim3(NTP, BB), 256, ATTN_SMEM>>>((const uint4*)p_xln, p_qeh, p_cb,
                                                  p_uhp, p_rsp);
        k_tgemmd<<<dim3(12, 11, 2), 256>>>(p_uhp, p_rsp, ln_f_w, ln_f_b,
                                           p_wihv, b_ih, p_gi, slots, W_hh, b_hh, p_gh);
        k_gruln<<<88, 256>>>(p_gi, p_gh, slots, ln_p_w, ln_p_b, p_p);
        k_tgemm<<<dim3(8, 11), 256>>>(p_p, W1, b1, p_h1, HH, DD, 1, 0);
        k_tgemm<<<dim3(4, 11), 256>>>(p_h1, W2, b2, slots, DD, HH, 0, 1);
    }
}

// round 12
// speedup vs baseline: 3.1526x; 1.2165x over previous
#include <cuda_runtime.h>
#include <cuda_bf16.h>
#include <math.h>
#include <stdint.h>

#define BB 64
#define NN 4096
#define DD 256
#define KS 11
#define HH 512
#define NITER 5
#define EPSF 1e-8f
#define LNEPS 1e-5f
#define SCALEF 0.0625f
#define TILE 128
#define TPB 8
#define NTP (NN/TILE/TPB)   // 4 partials per batch

// ---------------- mma / ldmatrix / cp.async helpers ----------------
__device__ __forceinline__ uint32_t s2u(const void* p) {
    uint32_t a;
    asm("{.reg .u64 t; cvta.to.shared.u64 t, %1; cvt.u32.u64 %0, t;}" : "=r"(a) : "l"(p));
    return a;
}
__device__ __forceinline__ void ldsm4(unsigned& r0, unsigned& r1, unsigned& r2,
                                      unsigned& r3, uint32_t addr) {
    asm volatile("ldmatrix.sync.aligned.m8n8.x4.shared.b16 {%0,%1,%2,%3}, [%4];"
                 : "=r"(r0), "=r"(r1), "=r"(r2), "=r"(r3) : "r"(addr));
}
__device__ __forceinline__ void ldsm4t(unsigned& r0, unsigned& r1, unsigned& r2,
                                       unsigned& r3, uint32_t addr) {
    asm volatile("ldmatrix.sync.aligned.m8n8.x4.trans.shared.b16 {%0,%1,%2,%3}, [%4];"
                 : "=r"(r0), "=r"(r1), "=r"(r2), "=r"(r3) : "r"(addr));
}
__device__ __forceinline__ void mma16816(float* d, unsigned a0, unsigned a1, unsigned a2,
                                         unsigned a3, unsigned b0, unsigned b1) {
    asm volatile("mma.sync.aligned.m16n8k16.row.col.f32.bf16.bf16.f32 "
                 "{%0,%1,%2,%3}, {%4,%5,%6,%7}, {%8,%9}, {%0,%1,%2,%3};"
                 : "+f"(d[0]), "+f"(d[1]), "+f"(d[2]), "+f"(d[3])
                 : "r"(a0), "r"(a1), "r"(a2), "r"(a3), "r"(b0), "r"(b1));
}
__device__ __forceinline__ void cpasync16(uint32_t saddr, const void* gaddr) {
    asm volatile("cp.async.cg.shared.global [%0], [%1], 16;" :: "r"(saddr), "l"(gaddr));
}
__device__ __forceinline__ void cpcommit() {
    asm volatile("cp.async.commit_group;");
}
template <int N>
__device__ __forceinline__ void cpwait() {
    asm volatile("cp.async.wait_group %0;" :: "n"(N));
}
// split 8 consecutive floats into bf16 hi + bf16 residual lo (packed pairs)
__device__ __forceinline__ void split8(const float* v, uint4& hi, uint4& lo) {
    unsigned h[4], l[4];
#pragma unroll
    for (int p = 0; p < 4; p++) {
        float a = v[2 * p], b = v[2 * p + 1];
        __nv_bfloat162 hh = __float22bfloat162_rn(make_float2(a, b));
        float2 hf = __bfloat1622float2(hh);
        __nv_bfloat162 ll = __float22bfloat162_rn(make_float2(a - hf.x, b - hf.y));
        h[p] = *(unsigned*)&hh; l[p] = *(unsigned*)&ll;
    }
    hi = make_uint4(h[0], h[1], h[2], h[3]);
    lo = make_uint4(l[0], l[1], l[2], l[3]);
}

// ---------------- scratch ----------------
__device__ __align__(16) unsigned short g_xln[BB*NN*DD];
__device__ __align__(16) unsigned g_weffh[DD*128];       // weff bf16 pairs [d][t/2]
__device__ float g_wgv[DD + 2];
__device__ float g_wihv[3*DD*DD];
__device__ float g_cb[BB*KS];
__device__ __align__(16) unsigned g_qeh[BB*KS*128];      // qe bf16 pairs
__device__ float g_uhpart[BB*NTP*KS*DD];
__device__ float g_rspart[BB*NTP*KS];
__device__ float g_gi[BB*KS*3*DD];
__device__ float g_gh[BB*KS*3*DD];
__device__ float g_p[BB*KS*DD];
__device__ float g_h1[BB*KS*HH];

// ---------------- xln = (x-mean)*rstd in bf16 (once) ----------------
__global__ void k_xln(const float* __restrict__ X, unsigned short* __restrict__ out) {
    int row = blockIdx.x * 8 + (threadIdx.x >> 5);
    int lane = threadIdx.x & 31;
    const float4* p = (const float4*)(X + (size_t)row * DD);
    float4 v0 = p[lane * 2], v1 = p[lane * 2 + 1];
    float s  = v0.x + v0.y + v0.z + v0.w + v1.x + v1.y + v1.z + v1.w;
    float s2 = v0.x*v0.x + v0.y*v0.y + v0.z*v0.z + v0.w*v0.w
             + v1.x*v1.x + v1.y*v1.y + v1.z*v1.z + v1.w*v1.w;
#pragma unroll
    for (int o = 16; o; o >>= 1) {
        s  += __shfl_xor_sync(0xffffffffu, s,  o);
        s2 += __shfl_xor_sync(0xffffffffu, s2, o);
    }
    float m = s * (1.0f / DD);
    float var = s2 * (1.0f / DD) - m * m;
    float r = rsqrtf(var + LNEPS);
    __nv_bfloat162 h0 = __float22bfloat162_rn(make_float2((v0.x-m)*r, (v0.y-m)*r));
    __nv_bfloat162 h1 = __float22bfloat162_rn(make_float2((v0.z-m)*r, (v0.w-m)*r));
    __nv_bfloat162 h2 = __float22bfloat162_rn(make_float2((v1.x-m)*r, (v1.y-m)*r));
    __nv_bfloat162 h3 = __float22bfloat162_rn(make_float2((v1.z-m)*r, (v1.w-m)*r));
    uint4 o;
    o.x = *(unsigned int*)&h0; o.y = *(unsigned int*)&h1;
    o.z = *(unsigned int*)&h2; o.w = *(unsigned int*)&h3;
    ((uint4*)(out + (size_t)row * DD))[lane] = o;
}

// ---------------- wprep: weff (bf16) rows + gv/consts ----------------
__global__ void k_wprep(const float* __restrict__ Wk, const float* __restrict__ Wq,
                        const float* __restrict__ wf, const float* __restrict__ bf,
                        const float* __restrict__ ws, const float* __restrict__ bs,
                        unsigned* __restrict__ weffh, float* __restrict__ wgv) {
    __shared__ float col[DD];
    __shared__ float rowo[DD];
    __shared__ float red[8];
    int t = threadIdx.x;
    if (blockIdx.x < DD) {
        int d = blockIdx.x;
        col[t] = Wk[t * DD + d];
        __syncthreads();
        float acc = 0.f;
        for (int s = 0; s < DD; s++) acc = fmaf(col[s], Wq[s * DD + t], acc);
        rowo[t] = acc * wf[d];
        __syncthreads();
        if (t < 128) {
            __nv_bfloat162 h = __float22bfloat162_rn(make_float2(rowo[2*t], rowo[2*t+1]));
            weffh[d * 128 + t] = *(unsigned*)&h;
        }
    } else {
        float a = 0.f;
        for (int e = 0; e < DD; e++) a = fmaf(Wk[t * DD + e], bf[e], a);
        col[t] = a;
        __syncthreads();
        float gv = 0.f;
        for (int s = 0; s < DD; s++) gv = fmaf(Wq[s * DD + t], col[s], gv);
        float w = ws[t] * gv;
        wgv[t] = w;
        float c1 = w, c0 = bs[t] * gv;
        int lane = t & 31, warp = t >> 5;
#pragma unroll
        for (int o = 16; o; o >>= 1) {
            c1 += __shfl_xor_sync(0xffffffffu, c1, o);
            c0 += __shfl_xor_sync(0xffffffffu, c0, o);
        }
        __syncthreads();
        if (lane == 0) red[warp] = c1;
        __syncthreads();
        if (t == 0) {
            float s1 = 0.f;
            for (int i = 0; i < 8; i++) s1 += red[i];
            wgv[DD] = s1;
        }
        __syncthreads();
        if (lane == 0) red[warp] = c0;
        __syncthreads();
        if (t == 1) {
            float s0 = 0.f;
            for (int i = 0; i < 8; i++) s0 += red[i];
            wgv[DD + 1] = s0;
        }
    }
}

// ---------------- wihv[m][e] = sum_j W_ih[m,j] * Wv[j,e] (once) ----------------
__global__ void k_wihv(const float* __restrict__ Wih, const float* __restrict__ Wv,
                       float* __restrict__ out) {
    __shared__ float row[DD];
    int m = blockIdx.x, t = threadIdx.x;
    row[t] = Wih[m * DD + t];
    __syncthreads();
    float acc = 0.f;
#pragma unroll 4
    for (int j = 0; j < DD; j++) acc = fmaf(row[j], Wv[j * DD + t], acc);
    out[m * DD + t] = acc;
}

// ---------------- k_qeb: fused LN_s + cb + qe GEMM (bf16 tensor cores) ----------------
// qe[m][n] = sum_e LNs(slots)[m][e] * weff[n][e]; output bf16 pairs.
__global__ void __launch_bounds__(256) k_qeb(
    const float* __restrict__ slots, const unsigned* __restrict__ weffh,
    const float* __restrict__ wgv, const float* __restrict__ lsw,
    const float* __restrict__ lsb, unsigned* __restrict__ qeh, float* __restrict__ cb) {
    __shared__ __align__(16) unsigned short As[64 * 72];
    __shared__ __align__(16) unsigned short Ws[64 * 72];
    __shared__ float ws[DD], bs[DD], rowm[64], rowr[64];
    uint32_t sa = s2u(As), sw = s2u(Ws);
    int tid = threadIdx.x, lane = tid & 31, warp = tid >> 5;
    int m0 = blockIdx.y * 64, n0 = blockIdx.x * 64;
    ws[tid] = lsw[tid]; bs[tid] = lsb[tid];
    float C1 = wgv[DD], C0 = wgv[DD + 1];
    float4 wg0 = *(const float4*)(wgv + lane * 8);
    float4 wg1 = *(const float4*)(wgv + lane * 8 + 4);
#pragma unroll
    for (int rr = 0; rr < 8; rr++) {
        int rl = warp * 8 + rr, row = m0 + rl;
        const float4* p = (const float4*)(slots + (size_t)row * DD);
        float4 v0 = p[lane * 2], v1 = p[lane * 2 + 1];
        float s  = v0.x + v0.y + v0.z + v0.w + v1.x + v1.y + v1.z + v1.w;
        float s2 = v0.x*v0.x + v0.y*v0.y + v0.z*v0.z + v0.w*v0.w
                 + v1.x*v1.x + v1.y*v1.y + v1.z*v1.z + v1.w*v1.w;
        float s3 = v0.x*wg0.x + v0.y*wg0.y + v0.z*wg0.z + v0.w*wg0.w
                 + v1.x*wg1.x + v1.y*wg1.y + v1.z*wg1.z + v1.w*wg1.w;
#pragma unroll
        for (int o = 16; o; o >>= 1) {
            s  += __shfl_xor_sync(0xffffffffu, s,  o);
            s2 += __shfl_xor_sync(0xffffffffu, s2, o);
            s3 += __shfl_xor_sync(0xffffffffu, s3, o);
        }
        if (lane == 0) {
            float m = s * (1.0f / DD);
            float var = s2 * (1.0f / DD) - m * m;
            float r = rsqrtf(var + LNEPS);
            rowm[rl] = m; rowr[rl] = r;
            if (blockIdx.x == 0) cb[row] = r * s3 - r * m * C1 + C0;
        }
    }
    __syncthreads();

    int wm = (warp >> 1) * 16, wn = (warp & 1) * 32;
    float D[4][4];
#pragma unroll
    for (int i = 0; i < 4; i++)
#pragma unroll
        for (int j = 0; j < 4; j++) D[i][j] = 0.f;
    int g8  = (lane & 8)  ? 1 : 0;
    int g16 = (lane & 16) ? 1 : 0;
    uint32_t aAddr  = sa + (wm + (lane & 7) + g8 * 8) * 144 + g16 * 16;
    uint32_t bAddr0 = sw + (wn + (lane & 7) + g16 * 8) * 144 + g8 * 16;
    uint32_t bAddr1 = bAddr0 + 16 * 144;

    for (int k0 = 0; k0 < DD; k0 += 64) {
#pragma unroll
        for (int j = 0; j < 2; j++) {
            int idx = tid + j * 256;
            int r = idx >> 3, c = idx & 7;
            // A: LN(slots) -> bf16
            const float* ap = slots + (size_t)(m0 + r) * DD + k0 + c * 8;
            float m = rowm[r], rs = rowr[r];
            unsigned hv[4];
#pragma unroll
            for (int p = 0; p < 4; p++) {
                float a = (ap[2*p]   - m) * rs * ws[k0 + c*8 + 2*p]   + bs[k0 + c*8 + 2*p];
                float b = (ap[2*p+1] - m) * rs * ws[k0 + c*8 + 2*p+1] + bs[k0 + c*8 + 2*p+1];
                __nv_bfloat162 h = __float22bfloat162_rn(make_float2(a, b));
                hv[p] = *(unsigned*)&h;
            }
            *(uint4*)((char*)As + r * 144 + c * 16) = make_uint4(hv[0], hv[1], hv[2], hv[3]);
            // W: copy bf16
            *(uint4*)((char*)Ws + r * 144 + c * 16) =
                *(const uint4*)(weffh + (size_t)(n0 + r) * 128 + k0 / 2 + c * 4);
        }
        __syncthreads();
#pragma unroll
        for (int kc = 0; kc < 4; kc++) {
            unsigned a0, a1, a2, a3, b0, b1, b2, b3, c0, c1, c2, c3;
            ldsm4(a0, a1, a2, a3, aAddr + kc * 32);
            ldsm4(b0, b1, b2, b3, bAddr0 + kc * 32);
            ldsm4(c0, c1, c2, c3, bAddr1 + kc * 32);
            mma16816(D[0], a0, a1, a2, a3, b0, b1);
            mma16816(D[1], a0, a1, a2, a3, b2, b3);
            mma16816(D[2], a0, a1, a2, a3, c0, c1);
            mma16816(D[3], a0, a1, a2, a3, c2, c3);
        }
        __syncthreads();
    }
    int row = m0 + wm + (lane >> 2);
#pragma unroll
    for (int nt = 0; nt < 4; nt++) {
        int col = n0 + wn + nt * 8 + (lane & 3) * 2;
        __nv_bfloat162 h0 = __float22bfloat162_rn(make_float2(D[nt][0], D[nt][1]));
        __nv_bfloat162 h1 = __float22bfloat162_rn(make_float2(D[nt][2], D[nt][3]));
        qeh[(size_t)row * 128 + (col >> 1)]       = *(unsigned*)&h0;
        qeh[(size_t)(row + 8) * 128 + (col >> 1)] = *(unsigned*)&h1;
    }
}

// ---------------- fused attention: tensor-core, single buffer, 2 blocks/SM ----------------
#define OFF_X   0
#define OFF_QP  67584
#define OFF_LS  76032
#define OFF_AS  85248
#define OFF_RSW 91392
#define OFF_CBS 91648
#define ATTN_SMEM 91712

__global__ void __launch_bounds__(256, 2) k_attn(
    const uint4* __restrict__ xln, const unsigned* __restrict__ qeh,
    const float* __restrict__ cb, float* __restrict__ uhpart,
    float* __restrict__ rspart) {
    extern __shared__ char sm[];
    uint32_t sb = s2u(sm);
    float* Ls  = (float*)(sm + OFF_LS);
    float* rsw = (float*)(sm + OFF_RSW);
    float* cbs = (float*)(sm + OFF_CBS);

    int bx = blockIdx.x, b = blockIdx.y;
    int tid = threadIdx.x, lane = tid & 31, warp = tid >> 5;

    for (int i = tid; i < 16 * 128; i += 256) {
        int slot = i >> 7, dp = i & 127;
        unsigned v = (slot < KS) ? qeh[((size_t)b * KS + slot) * 128 + dp] : 0u;
        *(unsigned*)(sm + OFF_QP + slot * 528 + dp * 4) = v;
    }
    if (tid < 16) cbs[tid] = (tid < KS) ? cb[b * KS + tid] : 0.f;

    const uint4* Xg = xln + (size_t)b * NN * (DD / 8);

    float rsl[KS];
    float uacc[4][4];
#pragma unroll
    for (int i = 0; i < KS; i++) rsl[i] = 0.f;
#pragma unroll
    for (int i = 0; i < 4; i++)
#pragma unroll
        for (int j = 0; j < 4; j++) uacc[i][j] = 0.f;

    int g8  = (lane & 8)  ? 1 : 0;
    int g16 = (lane & 16) ? 1 : 0;
    uint32_t dA = sb + OFF_X + ((warp * 16) + (lane & 7) + g8 * 8) * 528 + g16 * 16;
    uint32_t dB = sb + OFF_QP + ((lane & 7) + g16 * 8) * 528 + g8 * 16;
    uint32_t aA = sb + OFF_AS + ((lane & 7) + g16 * 8) * 48 + g8 * 16;
    int d0w = warp * 32;
    uint32_t aB = sb + OFF_X + ((lane & 7) + g8 * 8) * 528 + d0w * 2 + g16 * 16;

    for (int t = 0; t < TPB; t++) {
        {
            int row0 = (bx * TPB + t) * TILE;
#pragma unroll
            for (int k = 0; k < 16; k++) {
                int idx = tid + k * 256;
                int r = idx >> 5, c = idx & 31;
                cpasync16(sb + OFF_X + r * 528 + c * 16,
                          (const void*)(Xg + (size_t)(row0 + r) * 32 + c));
            }
            cpcommit();
            cpwait<0>();
        }
        __syncthreads();

        // ---- dots via mma ----
        {
            float D0[4] = {0.f, 0.f, 0.f, 0.f}, D1[4] = {0.f, 0.f, 0.f, 0.f};
#pragma unroll
            for (int kc = 0; kc < 16; kc++) {
                unsigned a0, a1, a2, a3, b0, b1, b2, b3;
                ldsm4(a0, a1, a2, a3, dA + kc * 32);
                ldsm4(b0, b1, b2, b3, dB + kc * 32);
                mma16816(D0, a0, a1, a2, a3, b0, b1);
                mma16816(D1, a0, a1, a2, a3, b2, b3);
            }
            int lr = warp * 16 + (lane >> 2), lc = (lane & 3) * 2;
            *(float2*)(Ls + lr * 18 + lc)           = make_float2(D0[0], D0[1]);
            *(float2*)(Ls + (lr + 8) * 18 + lc)     = make_float2(D0[2], D0[3]);
            *(float2*)(Ls + lr * 18 + 8 + lc)       = make_float2(D1[0], D1[1]);
            *(float2*)(Ls + (lr + 8) * 18 + 8 + lc) = make_float2(D1[2], D1[3]);
        }
        __syncthreads();

        // ---- softmax: thread-per-row ----
        if (tid < TILE) {
            const float* lr = Ls + tid * 18;
            float l[KS];
#pragma unroll
            for (int i = 0; i < KS; i++) l[i] = (lr[i] + cbs[i]) * SCALEF;
            float mx = l[0];
#pragma unroll
            for (int i = 1; i < KS; i++) mx = fmaxf(mx, l[i]);
            float se = 0.f;
#pragma unroll
            for (int i = 0; i < KS; i++) { float e = __expf(l[i] - mx); l[i] = e; se += e; }
            float inv = __fdividef(1.0f, se);
            float a16[16];
#pragma unroll
            for (int i = 0; i < 16; i++) a16[i] = 0.f;
#pragma unroll
            for (int i = 0; i < KS; i++) {
                float a = fmaf(l[i], inv, EPSF);
                a16[i] = a; rsl[i] += a;
            }
            unsigned* dst = (unsigned*)(sm + OFF_AS + tid * 48);
#pragma unroll
            for (int p = 0; p < 8; p++) {
                __nv_bfloat162 h = __float22bfloat162_rn(make_float2(a16[2*p], a16[2*p+1]));
                dst[p] = *(unsigned*)&h;
            }
        }
        __syncthreads();

        // ---- accum via mma ----
        {
#pragma unroll
            for (int kr = 0; kr < 8; kr++) {
                unsigned p0, p1, p2, p3, x0, x1, x2, x3, y0, y1, y2, y3;
                ldsm4t(p0, p1, p2, p3, aA + kr * (16 * 48));
                ldsm4t(x0, x1, x2, x3, aB + kr * (16 * 528));
                ldsm4t(y0, y1, y2, y3, aB + kr * (16 * 528) + 32);
                mma16816(uacc[0], p0, p1, p2, p3, x0, x1);
                mma16816(uacc[1], p0, p1, p2, p3, x2, x3);
                mma16816(uacc[2], p0, p1, p2, p3, y0, y1);
                mma16816(uacc[3], p0, p1, p2, p3, y2, y3);
            }
        }
        __syncthreads();
    }

    {
        float* up = uhpart + ((size_t)(b * NTP + bx)) * KS * DD;
        int slot = lane >> 2, dp = (lane & 3) * 2;
#pragma unroll
        for (int nt = 0; nt < 4; nt++) {
            int d = d0w + nt * 8 + dp;
            *(float2*)(up + slot * DD + d) = make_float2(uacc[nt][0], uacc[nt][1]);
            if (slot + 8 < KS)
                *(float2*)(up + (slot + 8) * DD + d) = make_float2(uacc[nt][2], uacc[nt][3]);
        }
    }
    if (tid < TILE) {
#pragma unroll
        for (int i = 0; i < KS; i++) {
#pragma unroll
            for (int o = 16; o; o >>= 1) rsl[i] += __shfl_xor_sync(0xffffffffu, rsl[i], o);
        }
        if (lane == 0) {
#pragma unroll
            for (int i = 0; i < KS; i++) rsw[warp * 16 + i] = rsl[i];
        }
    }
    __syncthreads();
    if (tid < KS)
        rspart[(size_t)(b * NTP + bx) * KS + tid] =
            rsw[tid] + rsw[16 + tid] + rsw[32 + tid] + rsw[48 + tid];
}

// ---------------- fused GRU + LN_p: warp per row ----------------
__global__ void k_gruln(const float* __restrict__ gi, const float* __restrict__ gh,
                        float* __restrict__ slots, const float* __restrict__ wp,
                        const float* __restrict__ bp, float* __restrict__ p) {
    int m = blockIdx.x * 8 + (threadIdx.x >> 5);
    int lane = threadIdx.x & 31;
    int d0 = lane * 8;
    const float* gim = gi + (size_t)m * 3 * DD;
    const float* ghm = gh + (size_t)m * 3 * DD;
    float ir[8], iz[8], in_[8], hr[8], hz[8], hn[8], sp[8], v[8];
    *(float4*)ir   = *(const float4*)(gim + d0);       *(float4*)(ir+4)  = *(const float4*)(gim + d0 + 4);
    *(float4*)iz   = *(const float4*)(gim + DD + d0);  *(float4*)(iz+4)  = *(const float4*)(gim + DD + d0 + 4);
    *(float4*)in_  = *(const float4*)(gim + 2*DD + d0);*(float4*)(in_+4) = *(const float4*)(gim + 2*DD + d0 + 4);
    *(float4*)hr   = *(const float4*)(ghm + d0);       *(float4*)(hr+4)  = *(const float4*)(ghm + d0 + 4);
    *(float4*)hz   = *(const float4*)(ghm + DD + d0);  *(float4*)(hz+4)  = *(const float4*)(ghm + DD + d0 + 4);
    *(float4*)hn   = *(const float4*)(ghm + 2*DD + d0);*(float4*)(hn+4)  = *(const float4*)(ghm + 2*DD + d0 + 4);
    *(float4*)sp   = *(const float4*)(slots + (size_t)m*DD + d0);
    *(float4*)(sp+4) = *(const float4*)(slots + (size_t)m*DD + d0 + 4);
    float s = 0.f, s2 = 0.f;
#pragma unroll
    for (int j = 0; j < 8; j++) {
        float r = 1.0f / (1.0f + __expf(-(ir[j] + hr[j])));
        float z = 1.0f / (1.0f + __expf(-(iz[j] + hz[j])));
        float n = tanhf(in_[j] + r * hn[j]);
        float vv = (1.0f - z) * n + z * sp[j];
        v[j] = vv; s += vv; s2 += vv * vv;
    }
#pragma unroll
    for (int o = 16; o; o >>= 1) {
        s  += __shfl_xor_sync(0xffffffffu, s,  o);
        s2 += __shfl_xor_sync(0xffffffffu, s2, o);
    }
    float mm = s * (1.0f / DD);
    float var = s2 * (1.0f / DD) - mm * mm;
    float rr = rsqrtf(var + LNEPS);
    *(float4*)(slots + (size_t)m*DD + d0)     = *(float4*)v;
    *(float4*)(slots + (size_t)m*DD + d0 + 4) = *(float4*)(v+4);
    float w_[8], b_[8], pv[8];
    *(float4*)w_ = *(const float4*)(wp + d0); *(float4*)(w_+4) = *(const float4*)(wp + d0 + 4);
    *(float4*)b_ = *(const float4*)(bp + d0); *(float4*)(b_+4) = *(const float4*)(bp + d0 + 4);
#pragma unroll
    for (int j = 0; j < 8; j++) pv[j] = (v[j] - mm) * rr * w_[j] + b_[j];
    *(float4*)(p + (size_t)m*DD + d0)     = *(float4*)pv;
    *(float4*)(p + (size_t)m*DD + d0 + 4) = *(float4*)(pv+4);
}

// ---------------- split-bf16 tensor GEMM: C[m][n] = sum_k A[m][k]*W[n][k] ----------------
// 64x64 tile, K-tile 64, 8 warps (4m x 2n), warp m16 x n32.
// D = Ah*Wh + Ah*Wl + Al*Wh   (Al*Wl dropped, O(2^-18))
__device__ __forceinline__ void tgemm_body(
    const float* __restrict__ A, const float* __restrict__ W,
    const float* __restrict__ bias, float* __restrict__ C,
    int N, int K, int relu, int accf, int fin,
    const float* __restrict__ uhpart, const float* __restrict__ rspart,
    const float* __restrict__ wf, const float* __restrict__ bf,
    unsigned short* AhS, unsigned short* AlS,
    unsigned short* WhS, unsigned short* WlS, float* rinv) {
    uint32_t saH = s2u(AhS), saL = s2u(AlS), swH = s2u(WhS), swL = s2u(WlS);
    int tid = threadIdx.x, lane = tid & 31, warp = tid >> 5;
    int m0 = blockIdx.y * 64, n0 = blockIdx.x * 64;
    int wm = (warp >> 1) * 16, wn = (warp & 1) * 32;
    if (fin) {
        if (tid < 64) {
            int m = m0 + tid, b = m / KS, i = m - b * KS;
            float r = 0.f;
#pragma unroll
            for (int t = 0; t < NTP; t++) r += rspart[(b * NTP + t) * KS + i];
            rinv[tid] = __fdividef(1.f, r);
        }
        __syncthreads();
    }
    float D[4][4];
#pragma unroll
    for (int i = 0; i < 4; i++)
#pragma unroll
        for (int j = 0; j < 4; j++) D[i][j] = 0.f;

    int g8  = (lane & 8)  ? 1 : 0;
    int g16 = (lane & 16) ? 1 : 0;
    uint32_t aOff = (wm + (lane & 7) + g8 * 8) * 144 + g16 * 16;
    uint32_t bOff0 = (wn + (lane & 7) + g16 * 8) * 144 + g8 * 16;
    uint32_t bOff1 = bOff0 + 16 * 144;

    for (int k0 = 0; k0 < K; k0 += 64) {
#pragma unroll
        for (int j = 0; j < 2; j++) {
            int idx = tid + j * 256;
            int r = idx >> 3, c = idx & 7;
            float av[8];
            if (fin) {
                int m = m0 + r, b = m / KS, i = m - b * KS;
                size_t base = ((size_t)(b * NTP) * KS + i) * DD + k0 + c * 8;
                float4 s0 = *(const float4*)(uhpart + base);
                float4 s1 = *(const float4*)(uhpart + base + 4);
#pragma unroll
                for (int t = 1; t < NTP; t++) {
                    float4 t0 = *(const float4*)(uhpart + base + (size_t)t * KS * DD);
                    float4 t1 = *(const float4*)(uhpart + base + (size_t)t * KS * DD + 4);
                    s0.x += t0.x; s0.y += t0.y; s0.z += t0.z; s0.w += t0.w;
                    s1.x += t1.x; s1.y += t1.y; s1.z += t1.z; s1.w += t1.w;
                }
                float irv = rinv[r];
                float4 w0 = *(const float4*)(wf + k0 + c * 8);
                float4 w1 = *(const float4*)(wf + k0 + c * 8 + 4);
                float4 b0 = *(const float4*)(bf + k0 + c * 8);
                float4 b1 = *(const float4*)(bf + k0 + c * 8 + 4);
                av[0] = w0.x * s0.x * irv + b0.x; av[1] = w0.y * s0.y * irv + b0.y;
                av[2] = w0.z * s0.z * irv + b0.z; av[3] = w0.w * s0.w * irv + b0.w;
                av[4] = w1.x * s1.x * irv + b1.x; av[5] = w1.y * s1.y * irv + b1.y;
                av[6] = w1.z * s1.z * irv + b1.z; av[7] = w1.w * s1.w * irv + b1.w;
            } else {
                *(float4*)av       = *(const float4*)(A + (size_t)(m0 + r) * K + k0 + c * 8);
                *(float4*)(av + 4) = *(const float4*)(A + (size_t)(m0 + r) * K + k0 + c * 8 + 4);
            }
            uint4 hi, lo;
            split8(av, hi, lo);
            *(uint4*)((char*)AhS + r * 144 + c * 16) = hi;
            *(uint4*)((char*)AlS + r * 144 + c * 16) = lo;
            float wv[8];
            *(float4*)wv       = *(const float4*)(W + (size_t)(n0 + r) * K + k0 + c * 8);
            *(float4*)(wv + 4) = *(const float4*)(W + (size_t)(n0 + r) * K + k0 + c * 8 + 4);
            split8(wv, hi, lo);
            *(uint4*)((char*)WhS + r * 144 + c * 16) = hi;
            *(uint4*)((char*)WlS + r * 144 + c * 16) = lo;
        }
        __syncthreads();
#pragma unroll
        for (int kc = 0; kc < 4; kc++) {
            unsigned ah0, ah1, ah2, ah3, al0, al1, al2, al3;
            ldsm4(ah0, ah1, ah2, ah3, saH + aOff + kc * 32);
            ldsm4(al0, al1, al2, al3, saL + aOff + kc * 32);
            unsigned bh0, bh1, bh2, bh3, bl0, bl1, bl2, bl3;
            ldsm4(bh0, bh1, bh2, bh3, swH + bOff0 + kc * 32);
            ldsm4(bl0, bl1, bl2, bl3, swL + bOff0 + kc * 32);
            mma16816(D[0], ah0, ah1, ah2, ah3, bh0, bh1);
            mma16816(D[0], ah0, ah1, ah2, ah3, bl0, bl1);
            mma16816(D[0], al0, al1, al2, al3, bh0, bh1);
            mma16816(D[1], ah0, ah1, ah2, ah3, bh2, bh3);
            mma16816(D[1], ah0, ah1, ah2, ah3, bl2, bl3);
            mma16816(D[1], al0, al1, al2, al3, bh2, bh3);
            unsigned ch0, ch1, ch2, ch3, cl0, cl1, cl2, cl3;
            ldsm4(ch0, ch1, ch2, ch3, swH + bOff1 + kc * 32);
            ldsm4(cl0, cl1, cl2, cl3, swL + bOff1 + kc * 32);
            mma16816(D[2], ah0, ah1, ah2, ah3, ch0, ch1);
            mma16816(D[2], ah0, ah1, ah2, ah3, cl0, cl1);
            mma16816(D[2], al0, al1, al2, al3, ch0, ch1);
            mma16816(D[3], ah0, ah1, ah2, ah3, ch2, ch3);
            mma16816(D[3], ah0, ah1, ah2, ah3, cl2, cl3);
            mma16816(D[3], al0, al1, al2, al3, ch2, ch3);
        }
        __syncthreads();
    }
    int row = m0 + wm + (lane >> 2);
#pragma unroll
    for (int nt = 0; nt < 4; nt++) {
        int col = n0 + wn + nt * 8 + (lane & 3) * 2;
        float2 bb = bias ? *(const float2*)(bias + col) : make_float2(0.f, 0.f);
        float2 v0 = make_float2(D[nt][0] + bb.x, D[nt][1] + bb.y);
        float2 v1 = make_float2(D[nt][2] + bb.x, D[nt][3] + bb.y);
        if (relu) {
            v0.x = fmaxf(v0.x, 0.f); v0.y = fmaxf(v0.y, 0.f);
            v1.x = fmaxf(v1.x, 0.f); v1.y = fmaxf(v1.y, 0.f);
        }
        float2* p0 = (float2*)(C + (size_t)row * N + col);
        float2* p1 = (float2*)(C + (size_t)(row + 8) * N + col);
        if (accf) {
            float2 t0 = *p0, t1 = *p1;
            v0.x += t0.x; v0.y += t0.y; v1.x += t1.x; v1.y += t1.y;
        }
        *p0 = v0; *p1 = v1;
    }
}

__global__ void __launch_bounds__(256) k_tgemm(
    const float* __restrict__ A, const float* __restrict__ W,
    const float* __restrict__ bias, float* __restrict__ C,
    int N, int K, int relu, int accf) {
    __shared__ __align__(16) unsigned short Ah[64*72], Al[64*72], Wh[64*72], Wl[64*72];
    __shared__ float rinv[64];
    tgemm_body(A, W, bias, C, N, K, relu, accf, 0,
               nullptr, nullptr, nullptr, nullptr, Ah, Al, Wh, Wl, rinv);
}

__global__ void __launch_bounds__(256) k_tgemmd(
    const float* __restrict__ uhpart, const float* __restrict__ rspart,
    const float* __restrict__ wf, const float* __restrict__ bf,
    const float* __restrict__ wihv, const float* __restrict__ bih, float* __restrict__ gi,
    const float* __restrict__ slots, const float* __restrict__ Whh,
    const float* __restrict__ bhh, float* __restrict__ gh) {
    __shared__ __align__(16) unsigned short Ah[64*72], Al[64*72], Wh[64*72], Wl[64*72];
    __shared__ float rinv[64];
    if (blockIdx.z == 0)
        tgemm_body(nullptr, wihv, bih, gi, 3 * DD, DD, 0, 0, 1,
                   uhpart, rspart, wf, bf, Ah, Al, Wh, Wl, rinv);
    else
        tgemm_body(slots, Whh, bhh, gh, 3 * DD, DD, 0, 0, 0,
                   nullptr, nullptr, nullptr, nullptr, Ah, Al, Wh, Wl, rinv);
}

extern "C" void kernel_launch(void* const* d_in, const int* in_sizes, int n_in,
                              void* d_out, int out_size) {
    const float* inputs     = (const float*)d_in[0];
    const float* slots_init = (const float*)d_in[1];
    const float* ln_f_w = (const float*)d_in[2];
    const float* ln_f_b = (const float*)d_in[3];
    const float* ln_s_w = (const float*)d_in[4];
    const float* ln_s_b = (const float*)d_in[5];
    const float* ln_p_w = (const float*)d_in[6];
    const float* ln_p_b = (const float*)d_in[7];
    const float* Wq  = (const float*)d_in[8];
    const float* Wk  = (const float*)d_in[9];
    const float* Wv  = (const float*)d_in[10];
    const float* W_ih = (const float*)d_in[11];
    const float* b_ih = (const float*)d_in[12];
    const float* W_hh = (const float*)d_in[13];
    const float* b_hh = (const float*)d_in[14];
    const float* W1 = (const float*)d_in[15];
    const float* b1 = (const float*)d_in[16];
    const float* W2 = (const float*)d_in[17];
    const float* b2 = (const float*)d_in[18];
    float* slots = (float*)d_out;

    unsigned short* p_xln;
    unsigned *p_weffh, *p_qeh;
    float *p_wgv, *p_wihv, *p_cb, *p_uhp, *p_rsp;
    float *p_gi, *p_gh, *p_p, *p_h1;
    cudaGetSymbolAddress((void**)&p_xln, g_xln);
    cudaGetSymbolAddress((void**)&p_weffh, g_weffh);
    cudaGetSymbolAddress((void**)&p_wgv, g_wgv);
    cudaGetSymbolAddress((void**)&p_wihv, g_wihv);
    cudaGetSymbolAddress((void**)&p_cb, g_cb);
    cudaGetSymbolAddress((void**)&p_qeh, g_qeh);
    cudaGetSymbolAddress((void**)&p_uhp, g_uhpart);
    cudaGetSymbolAddress((void**)&p_rsp, g_rspart);
    cudaGetSymbolAddress((void**)&p_gi, g_gi);
    cudaGetSymbolAddress((void**)&p_gh, g_gh);
    cudaGetSymbolAddress((void**)&p_p, g_p);
    cudaGetSymbolAddress((void**)&p_h1, g_h1);

    cudaFuncSetAttribute(k_attn, cudaFuncAttributeMaxDynamicSharedMemorySize, ATTN_SMEM);

    cudaMemcpyAsync(slots, slots_init, (size_t)BB * KS * DD * sizeof(float),
                    cudaMemcpyDeviceToDevice);
    k_xln<<<BB * NN / 8, 256>>>(inputs, p_xln);
    k_wprep<<<DD + 1, DD>>>(Wk, Wq, ln_f_w, ln_f_b, ln_s_w, ln_s_b, p_weffh, p_wgv);
    k_wihv<<<3 * DD, DD>>>(W_ih, Wv, p_wihv);

    for (int it = 0; it < NITER; it++) {
        k_qeb<<<dim3(4, 11), 256>>>(slots, p_weffh, p_wgv, ln_s_w, ln_s_b, p_qeh, p_cb);
        k_attn<<<dim3(NTP, BB), 256, ATTN_SMEM>>>((const uint4*)p_xln, p_qeh, p_cb,
                                                  p_uhp, p_rsp);
        k_tgemmd<<<dim3(12, 11, 2), 256>>>(p_uhp, p_rsp, ln_f_w, ln_f_b,
                                           p_wihv, b_ih, p_gi, slots, W_hh, b_hh, p_gh);
        k_gruln<<<88, 256>>>(p_gi, p_gh, slots, ln_p_w, ln_p_b, p_p);
        k_tgemm<<<dim3(8, 11), 256>>>(p_p, W1, b1, p_h1, HH, DD, 1, 0);
        k_tgemm<<<dim3(4, 11), 256>>>(p_h1, W2, b2, slots, DD, HH, 0, 1);
    }
}